// round 8
// baseline (speedup 1.0000x reference)
#include <cuda_runtime.h>
#include <cstddef>

// ---------------- problem constants ----------------
#define BB   2
#define CINX 64
#define CH   128
#define HH   64
#define WW   1024
#define HWX  (HH*WW)          // 65536
#define H2X  32
#define W2X  512
#define NP2  (H2X*W2X)        // 16384
#define RESB_ELEMS (BB*CH*NP2)   // 4194304

typedef unsigned long long U64;

// f32x2 packed FMA (Blackwell): c = a*b + c elementwise on 2 packed fp32
#define FMA2(c, a, b) asm("fma.rn.f32x2 %0, %1, %2, %0;" : "+l"(c) : "l"(a), "l"(b))
#define PACK2(d, x)   asm("mov.b64 %0, {%1, %1};" : "=l"(d) : "r"(__float_as_uint(x)))
#define UNPK2(lo, hi, d) asm("mov.b64 {%0, %1}, %2;" : "=r"(lo), "=r"(hi) : "l"(d))

// resa (legacy 8x8 tile) smem geometry
#define ROWS 132
#define STAGE_F (16*ROWS*2)

// new K8 GEMM stage: in 8x132 + w 8x132
#define PW_STAGE (8*132*2)     // 2112 floats

// ---------------- scratch (static device memory; no allocation) ----------------
__device__ float g_resA1[BB*CH*HWX];
__device__ float g_resA2[BB*CH*HWX];
__device__ float g_resA3[BB*CH*HWX];
__device__ float g_buf1 [BB*CH*HWX];
__device__ float g_buf2 [BB*CH*HWX];
__device__ float g_hT   [BB*HWX*CH];          // transposed h: [B][H][W][C]
__device__ float g_wn   [BB*NP2*25*16];       // [B*NP2][25][16]
__device__ float g_y    [(size_t)BB*NP2*2048];// pixel-major: [B*NP2][2048]

__device__ __forceinline__ float lrelu01(float z) { return z > 0.f ? z : 0.01f*z; }

// =====================================================================
// K8 GEMM inner: 8-K chunk, 16 oc x 4 px per thread, f32x2.
// ty = tid>>5 (warp-uniform -> w LDS broadcast), tx = tid&31.
// in_s: [8][132] pixel-minor; w_s: [8][132] oc-minor.
// =====================================================================
__device__ __forceinline__ void gemm_k8_16x4(const float* __restrict__ in_s,
                                             const float* __restrict__ w_s,
                                             int ty, int tx, U64 acc[8][4])
{
    #pragma unroll
    for (int kk = 0; kk < 8; kk++) {
        const float* wrow = w_s + kk*132 + ty*16;
        ulonglong2 w0 = *reinterpret_cast<const ulonglong2*>(wrow);
        ulonglong2 w1 = *reinterpret_cast<const ulonglong2*>(wrow + 4);
        ulonglong2 w2 = *reinterpret_cast<const ulonglong2*>(wrow + 8);
        ulonglong2 w3 = *reinterpret_cast<const ulonglong2*>(wrow + 12);
        U64 wp[8] = {w0.x, w0.y, w1.x, w1.y, w2.x, w2.y, w3.x, w3.y};
        float4 xa = *reinterpret_cast<const float4*>(in_s + kk*132 + tx*4);
        float xs[4] = {xa.x, xa.y, xa.z, xa.w};
        U64 xp[4];
        #pragma unroll
        for (int p = 0; p < 4; p++) PACK2(xp[p], xs[p]);
        #pragma unroll
        for (int j = 0; j < 8; j++)
            #pragma unroll
            for (int p = 0; p < 4; p++)
                FMA2(acc[j][p], wp[j], xp[p]);
    }
}

// =====================================================================
// Direct conv: block = 128 oc x 128 px (one row), thread = 16 oc x 4 px.
// CC input channels per chunk, double-buffered, bn(lrelu(conv+b)).
// =====================================================================
template<int CIN, int KS, int DIL, int PAD, int CC>
__global__ __launch_bounds__(256, 2)
void conv_f2_k(const float* __restrict__ in, const float* __restrict__ wg,
               const float* __restrict__ bias, const float* __restrict__ bns,
               const float* __restrict__ bnb, float* __restrict__ out)
{
    constexpr int KK = KS*KS, IWP = 136;
    constexpr int INTOT = CC*KS*IWP;
    constexpr int NIN   = (INTOT + 255)/256;
    constexpr int NCH   = CIN/CC;

    __shared__ __align__(16) float in_s[2][INTOT];
    __shared__ __align__(16) float w_s[2][CC*KK*132];

    const int w0 = blockIdx.x * 128;
    const int hrow = blockIdx.y;
    const int b  = blockIdx.z;
    const int tid = threadIdx.x;
    const int ty = tid >> 5, tx = tid & 31;

    U64 acc[8][4];
    #pragma unroll
    for (int j = 0; j < 8; j++)
        #pragma unroll
        for (int p = 0; p < 4; p++) acc[j][p] = 0ULL;

    float  rin[NIN];
    float  rww9[KS == 3 ? 9 : 1];
    float4 rww4[KS == 2 ? 2 : 1];

    auto load_chunk = [&](int cb) {
        #pragma unroll
        for (int j = 0; j < NIN; j++) {
            int idx = tid + j*256;
            float v = 0.f;
            if (idx < INTOT) {
                int ci  = idx / (KS*IWP);
                int rem = idx - ci*(KS*IWP);
                int r = rem / IWP, col = rem - r*IWP;
                int gy = hrow - PAD + r*DIL;
                int gx = w0 - PAD + col;
                if ((unsigned)gy < (unsigned)HH && (unsigned)gx < (unsigned)WW)
                    v = in[((b*CIN + cb + ci)*HH + gy)*WW + gx];
            }
            rin[j] = v;
        }
        if (KS == 3) {
            // CC==2: 128 oc x 18 elems, 9 scalars per thread
            int oc = tid & 127, part = tid >> 7;
            #pragma unroll
            for (int j = 0; j < 9; j++) {
                int r = part*9 + j;
                int ci = r / KK, k = r - ci*KK;
                rww9[j] = wg[oc*CIN*KK + (cb + ci)*KK + k];
            }
        } else {
            // KS==2, CC==4: 16 contiguous elems per oc, 2 float4 per thread
            int oc = tid >> 1, q2 = tid & 1;
            #pragma unroll
            for (int i = 0; i < 2; i++)
                rww4[i] = *reinterpret_cast<const float4*>(
                    &wg[(oc*CIN + cb)*KK + (q2*2 + i)*4]);
        }
    };
    auto store_stage = [&](int st) {
        #pragma unroll
        for (int j = 0; j < NIN; j++) {
            int idx = tid + j*256;
            if (idx < INTOT) in_s[st][idx] = rin[j];
        }
        if (KS == 3) {
            int oc = tid & 127, part = tid >> 7;
            #pragma unroll
            for (int j = 0; j < 9; j++)
                w_s[st][(part*9 + j)*132 + oc] = rww9[j];
        } else {
            int oc = tid >> 1, q2 = tid & 1;
            #pragma unroll
            for (int i = 0; i < 2; i++) {
                float vv[4] = {rww4[i].x, rww4[i].y, rww4[i].z, rww4[i].w};
                #pragma unroll
                for (int jj = 0; jj < 4; jj++)
                    w_s[st][((q2*2 + i)*4 + jj)*132 + oc] = vv[jj];
            }
        }
    };

    load_chunk(0);
    store_stage(0);
    if (NCH > 1) load_chunk(CC);
    __syncthreads();

    for (int c = 0; c < NCH; c++) {
        if (c + 1 < NCH) store_stage((c + 1) & 1);
        if (c + 2 < NCH) load_chunk((c + 2)*CC);
        const int st = c & 1;
        #pragma unroll
        for (int ci = 0; ci < CC; ci++) {
            #pragma unroll
            for (int kh = 0; kh < KS; kh++) {
                const float* xrow = &in_s[st][(ci*KS + kh)*IWP + tx*4];
                float xr[8];
                *reinterpret_cast<float4*>(&xr[0]) = *reinterpret_cast<const float4*>(xrow);
                *reinterpret_cast<float4*>(&xr[4]) = *reinterpret_cast<const float4*>(xrow + 4);
                #pragma unroll
                for (int kw = 0; kw < KS; kw++) {
                    const float* wrow = &w_s[st][(ci*KK + kh*KS + kw)*132 + ty*16];
                    ulonglong2 wq0 = *reinterpret_cast<const ulonglong2*>(wrow);
                    ulonglong2 wq1 = *reinterpret_cast<const ulonglong2*>(wrow + 4);
                    ulonglong2 wq2 = *reinterpret_cast<const ulonglong2*>(wrow + 8);
                    ulonglong2 wq3 = *reinterpret_cast<const ulonglong2*>(wrow + 12);
                    U64 wp[8] = {wq0.x, wq0.y, wq1.x, wq1.y, wq2.x, wq2.y, wq3.x, wq3.y};
                    U64 xp[4];
                    #pragma unroll
                    for (int p = 0; p < 4; p++) PACK2(xp[p], xr[p + kw*DIL]);
                    #pragma unroll
                    for (int j = 0; j < 8; j++)
                        #pragma unroll
                        for (int p = 0; p < 4; p++)
                            FMA2(acc[j][p], wp[j], xp[p]);
                }
            }
        }
        __syncthreads();
    }
    #pragma unroll
    for (int j = 0; j < 8; j++) {
        float lo[4], hi[4];
        #pragma unroll
        for (int p = 0; p < 4; p++) {
            unsigned a, c; UNPK2(a, c, acc[j][p]);
            lo[p] = __uint_as_float(a); hi[p] = __uint_as_float(c);
        }
        #pragma unroll
        for (int hh2 = 0; hh2 < 2; hh2++) {
            int oc = ty*16 + 2*j + hh2;
            const float* src = hh2 ? hi : lo;
            float bi = bias[oc], s = bns[oc], bb2 = bnb[oc];
            float zt[4];
            #pragma unroll
            for (int p = 0; p < 4; p++) zt[p] = s*lrelu01(src[p] + bi) + bb2;
            *reinterpret_cast<float4*>(&out[((b*128 + oc)*HH + hrow)*WW + w0 + tx*4]) =
                make_float4(zt[0], zt[1], zt[2], zt[3]);
        }
    }
}

// =====================================================================
// Pointwise 128->128, K8 chunks, 128 oc x 128 px block, 16x4 tile.
// TR=1 writes transposed [pix][C].
// =====================================================================
template<int TR>
__global__ __launch_bounds__(256, 2)
void gemm128_f2_k(const float* __restrict__ in, const float* __restrict__ wg,
                  const float* __restrict__ bias, const float* __restrict__ bns,
                  const float* __restrict__ bnb, float* __restrict__ out)
{
    __shared__ __align__(16) float sraw[2*PW_STAGE];
    const int gp = blockIdx.x * 128;
    const int b = gp / HWX, pp = gp - b*HWX;
    const int tid = threadIdx.x, ty = tid >> 5, tx = tid & 31;
    const int sc_ch = tid >> 5, sc_px = (tid & 31)*4;
    const int sw_oc = tid >> 1, sw_h = tid & 1;
    U64 acc[8][4];
    #pragma unroll
    for (int j = 0; j < 8; j++)
        #pragma unroll
        for (int p = 0; p < 4; p++) acc[j][p] = 0ULL;

    float4 rin, rw;
    auto load_chunk = [&](int kc) {
        rin = *reinterpret_cast<const float4*>(&in[((b*128 + kc*8 + sc_ch)*HWX) + pp + sc_px]);
        rw  = *reinterpret_cast<const float4*>(&wg[sw_oc*128 + kc*8 + sw_h*4]);
    };
    auto store_stage = [&](int st) {
        float* base = sraw + st*PW_STAGE;
        *reinterpret_cast<float4*>(&base[sc_ch*132 + sc_px]) = rin;
        float* w_s = base + 8*132;
        w_s[(sw_h*4+0)*132 + sw_oc] = rw.x; w_s[(sw_h*4+1)*132 + sw_oc] = rw.y;
        w_s[(sw_h*4+2)*132 + sw_oc] = rw.z; w_s[(sw_h*4+3)*132 + sw_oc] = rw.w;
    };

    load_chunk(0); store_stage(0);
    load_chunk(1);
    __syncthreads();
    for (int kc = 0; kc < 16; kc++) {
        if (kc + 1 < 16) store_stage((kc + 1) & 1);
        if (kc + 2 < 16) load_chunk(kc + 2);
        const float* base = sraw + (kc & 1)*PW_STAGE;
        gemm_k8_16x4(base, base + 8*132, ty, tx, acc);
        __syncthreads();
    }

    if (TR == 0) {
        #pragma unroll
        for (int j = 0; j < 8; j++) {
            float lo[4], hi[4];
            #pragma unroll
            for (int p = 0; p < 4; p++) {
                unsigned a, c; UNPK2(a, c, acc[j][p]);
                lo[p] = __uint_as_float(a); hi[p] = __uint_as_float(c);
            }
            #pragma unroll
            for (int hh2 = 0; hh2 < 2; hh2++) {
                int oc = ty*16 + 2*j + hh2;
                const float* src = hh2 ? hi : lo;
                float bi = bias[oc], s = bns[oc], bb2 = bnb[oc];
                float zt[4];
                #pragma unroll
                for (int p = 0; p < 4; p++) {
                    float z = s*(src[p] + bi) + bb2;
                    zt[p] = z > 0.f ? z : 0.f;
                }
                *reinterpret_cast<float4*>(&out[((b*128 + oc)*HWX) + pp + tx*4]) =
                    make_float4(zt[0], zt[1], zt[2], zt[3]);
            }
        }
    } else {
        // 4 groups of 32 oc, transpose via smem stage [32][132] (reuses sraw)
        float* stage = sraw;
        for (int g = 0; g < 4; g++) {
            __syncthreads();
            if ((ty >> 1) == g) {
                #pragma unroll
                for (int j = 0; j < 8; j++) {
                    unsigned a, c;
                    float lo[4], hi[4];
                    #pragma unroll
                    for (int p = 0; p < 4; p++) {
                        UNPK2(a, c, acc[j][p]);
                        lo[p] = __uint_as_float(a); hi[p] = __uint_as_float(c);
                    }
                    int ocl = (ty & 1)*16 + 2*j;
                    int oc  = g*32 + ocl;
                    float bi0 = bias[oc],   s0 = bns[oc],   b0 = bnb[oc];
                    float bi1 = bias[oc+1], s1 = bns[oc+1], b1 = bnb[oc+1];
                    #pragma unroll
                    for (int p = 0; p < 4; p++) {
                        float z0 = s0*(lo[p] + bi0) + b0;
                        float z1 = s1*(hi[p] + bi1) + b1;
                        stage[ocl*132 + tx*4 + p]     = z0 > 0.f ? z0 : 0.f;
                        stage[(ocl+1)*132 + tx*4 + p] = z1 > 0.f ? z1 : 0.f;
                    }
                }
            }
            __syncthreads();
            #pragma unroll
            for (int it = 0; it < 4; it++) {
                int idx = tid + it*256;
                int c4 = idx & 7, pix = idx >> 3;
                float4 v;
                v.x = stage[(c4*4+0)*132 + pix];
                v.y = stage[(c4*4+1)*132 + pix];
                v.z = stage[(c4*4+2)*132 + pix];
                v.w = stage[(c4*4+3)*132 + pix];
                *reinterpret_cast<float4*>(&out[(size_t)(b*HWX + pp + pix)*128 + g*32 + c4*4]) = v;
            }
        }
    }
}

// =====================================================================
// resA: bn3(lrelu(c5 @ concat + c5_b)) + lrelu(c1 @ x + c1_b)
// (kept from R6: 16-K chunks, 8oc x 8px tile, two accumulators)
// =====================================================================
__device__ __forceinline__ void gemm_chunk_f2(const float* __restrict__ in_s,
                                              const float* __restrict__ w_s,
                                              int ty, int tx, U64 acc[4][8])
{
    #pragma unroll
    for (int kk = 0; kk < 16; kk++) {
        ulonglong2 wa = *reinterpret_cast<const ulonglong2*>(w_s + kk*ROWS + ty*8);
        ulonglong2 wb = *reinterpret_cast<const ulonglong2*>(w_s + kk*ROWS + ty*8 + 4);
        U64 wp[4] = {wa.x, wa.y, wb.x, wb.y};
        float4 xa = *reinterpret_cast<const float4*>(in_s + kk*ROWS + tx*4);
        float4 xb = *reinterpret_cast<const float4*>(in_s + kk*ROWS + 64 + tx*4);
        float xs[8] = {xa.x, xa.y, xa.z, xa.w, xb.x, xb.y, xb.z, xb.w};
        U64 xp[8];
        #pragma unroll
        for (int p = 0; p < 8; p++) PACK2(xp[p], xs[p]);
        #pragma unroll
        for (int j = 0; j < 4; j++)
            #pragma unroll
            for (int p = 0; p < 8; p++)
                FMA2(acc[j][p], wp[j], xp[p]);
    }
}

__global__ __launch_bounds__(256)
void resa_f2_k(const float* __restrict__ r1, const float* __restrict__ r2,
               const float* __restrict__ r3, const float* __restrict__ x,
               const float* __restrict__ c5w, const float* __restrict__ c5b,
               const float* __restrict__ c1w, const float* __restrict__ c1b,
               const float* __restrict__ bns, const float* __restrict__ bnb,
               float* __restrict__ out)
{
    __shared__ __align__(16) float sraw[2*STAGE_F];
    const int gp = blockIdx.x * 128;
    const int b = gp / HWX, pp = gp - b*HWX;
    const int tid = threadIdx.x, ty = tid >> 4, tx = tid & 15;
    const int oc1 = tid >> 2, q1 = tid & 3;
    U64 acc[4][8], acc2[4][8];
    #pragma unroll
    for (int j = 0; j < 4; j++)
        #pragma unroll
        for (int p = 0; p < 8; p++) { acc[j][p] = 0ULL; acc2[j][p] = 0ULL; }

    float4 ra, rb, rwa, rwb;
    auto load_c = [&](int c) {
        if (c < 24) {
            const float* src = c < 8 ? r1 : (c < 16 ? r2 : r3);
            int chb = (c & 7)*16;
            const float* sp = &src[((b*128 + chb + ty)*HWX) + pp + tx*8];
            ra = *reinterpret_cast<const float4*>(sp);
            rb = *reinterpret_cast<const float4*>(sp + 4);
            rwa = *reinterpret_cast<const float4*>(&c5w[oc1*384 + c*16 + q1*4]);
            rwb = *reinterpret_cast<const float4*>(&c5w[(oc1 + 64)*384 + c*16 + q1*4]);
        } else {
            int kc = c - 24;
            const float* sp = &x[((b*64 + kc*16 + ty)*HWX) + pp + tx*8];
            ra = *reinterpret_cast<const float4*>(sp);
            rb = *reinterpret_cast<const float4*>(sp + 4);
            rwa = *reinterpret_cast<const float4*>(&c1w[oc1*64 + kc*16 + q1*4]);
            rwb = *reinterpret_cast<const float4*>(&c1w[(oc1 + 64)*64 + kc*16 + q1*4]);
        }
    };
    auto store_stage = [&](int st) {
        float* in_s = sraw + st*STAGE_F;
        float* w_s  = in_s + 16*ROWS;
        *reinterpret_cast<float4*>(&in_s[ty*ROWS + tx*8])     = ra;
        *reinterpret_cast<float4*>(&in_s[ty*ROWS + tx*8 + 4]) = rb;
        w_s[(q1*4+0)*ROWS + oc1] = rwa.x; w_s[(q1*4+1)*ROWS + oc1] = rwa.y;
        w_s[(q1*4+2)*ROWS + oc1] = rwa.z; w_s[(q1*4+3)*ROWS + oc1] = rwa.w;
        w_s[(q1*4+0)*ROWS + oc1+64] = rwb.x; w_s[(q1*4+1)*ROWS + oc1+64] = rwb.y;
        w_s[(q1*4+2)*ROWS + oc1+64] = rwb.z; w_s[(q1*4+3)*ROWS + oc1+64] = rwb.w;
    };

    load_c(0); store_stage(0);
    load_c(1);
    __syncthreads();
    for (int c = 0; c < 28; c++) {
        if (c + 1 < 28) store_stage((c + 1) & 1);
        if (c + 2 < 28) load_c(c + 2);
        const float* base = sraw + (c & 1)*STAGE_F;
        if (c < 24) gemm_chunk_f2(base, base + 16*ROWS, ty, tx, acc);
        else        gemm_chunk_f2(base, base + 16*ROWS, ty, tx, acc2);
        __syncthreads();
    }

    #pragma unroll
    for (int j = 0; j < 4; j++) {
        float lo[8], hi[8], lo2[8], hi2[8];
        #pragma unroll
        for (int p = 0; p < 8; p++) {
            unsigned a, c; UNPK2(a, c, acc[j][p]);
            lo[p] = __uint_as_float(a); hi[p] = __uint_as_float(c);
            UNPK2(a, c, acc2[j][p]);
            lo2[p] = __uint_as_float(a); hi2[p] = __uint_as_float(c);
        }
        #pragma unroll
        for (int hh2 = 0; hh2 < 2; hh2++) {
            int oc = ty*8 + 2*j + hh2;
            const float* m  = hh2 ? hi  : lo;
            const float* m2 = hh2 ? hi2 : lo2;
            float b5 = c5b[oc], b1 = c1b[oc], s = bns[oc], bb2 = bnb[oc];
            float zt[8];
            #pragma unroll
            for (int p = 0; p < 8; p++)
                zt[p] = s*lrelu01(m[p] + b5) + bb2 + lrelu01(m2[p] + b1);
            float* op = &out[((b*128 + oc)*HWX) + pp];
            *reinterpret_cast<float4*>(op + tx*4)      = make_float4(zt[0], zt[1], zt[2], zt[3]);
            *reinterpret_cast<float4*>(op + 64 + tx*4) = make_float4(zt[4], zt[5], zt[6], zt[7]);
        }
    }
}

// =====================================================================
// WeightNet: gxyz -> 8 -> 8 -> 16, per (b, k, pixel)
// =====================================================================
__global__ __launch_bounds__(256)
void weightnet_k(const float* __restrict__ xyz,
                 const float* __restrict__ w1w, const float* __restrict__ w1b,
                 const float* __restrict__ w2w, const float* __restrict__ w2b,
                 const float* __restrict__ w3w, const float* __restrict__ w3b,
                 const float* __restrict__ s1, const float* __restrict__ b1,
                 const float* __restrict__ s2, const float* __restrict__ b2,
                 const float* __restrict__ s3, const float* __restrict__ b3,
                 float* __restrict__ out)
{
    int g = blockIdx.x*256 + threadIdx.x;   // B*25*NP2 = 819200
    int pix = g & (NP2 - 1);
    int rest = g >> 14;
    int k = rest % 25, b = rest / 25;
    int h2 = pix >> 9, w2 = pix & 511;
    int hi = 2*h2 - 2 + k/5, wi = 2*w2 - 2 + (k % 5);
    bool inb = ((unsigned)hi < (unsigned)HH) && ((unsigned)wi < (unsigned)WW);
    float gv[3];
    #pragma unroll
    for (int c = 0; c < 3; c++) {
        float ctr = xyz[(b*3 + c)*HWX + (2*h2)*WW + 2*w2];
        float nb  = inb ? xyz[(b*3 + c)*HWX + hi*WW + wi] : 0.f;
        gv[c] = nb - ctr;
    }
    float a1[8];
    #pragma unroll
    for (int j = 0; j < 8; j++) {
        float z = w1b[j];
        #pragma unroll
        for (int c = 0; c < 3; c++) z += w1w[j*3 + c]*gv[c];
        z = s1[j]*z + b1[j];
        a1[j] = z > 0.f ? z : 0.f;
    }
    float a2[8];
    #pragma unroll
    for (int j = 0; j < 8; j++) {
        float z = w2b[j];
        #pragma unroll
        for (int i = 0; i < 8; i++) z += w2w[j*8 + i]*a1[i];
        z = s2[j]*z + b2[j];
        a2[j] = z > 0.f ? z : 0.f;
    }
    float o[16];
    #pragma unroll
    for (int n = 0; n < 16; n++) {
        float z = w3b[n];
        #pragma unroll
        for (int i = 0; i < 8; i++) z += w3w[n*8 + i]*a2[i];
        z = s3[n]*z + b3[n];
        o[n] = z > 0.f ? z : 0.f;
    }
    size_t base = (((size_t)(b*NP2 + pix))*25 + k)*16;
    #pragma unroll
    for (int q = 0; q < 4; q++)
        *reinterpret_cast<float4*>(&out[base + q*4]) =
            make_float4(o[q*4], o[q*4+1], o[q*4+2], o[q*4+3]);
}

// =====================================================================
// Einsum: y[pix][c*16+n] = sum_k unf(hT)[c][k] * wn[pix][k][n], 2 pixels/block
// =====================================================================
__global__ __launch_bounds__(128)
void einsum_k(const float* __restrict__ hT, const float* __restrict__ wn,
              float* __restrict__ y)
{
    __shared__ __align__(16) float u_s[2][25][128];
    __shared__ float wn_s[2][400];
    const int gpix = blockIdx.x*2;
    const int b = gpix / NP2;
    const int tid = threadIdx.x;

    for (int i = tid; i < 800; i += 128) {
        int pl = i / 400, r = i - pl*400;
        wn_s[pl][r] = wn[(size_t)(gpix + pl)*400 + r];
    }
    for (int idx = 0; idx < 50; idx++) {
        int pl = idx / 25, k = idx - pl*25;
        int pp = (gpix + pl) - b*NP2;
        int h2 = pp >> 9, w2 = pp & 511;
        int hi = 2*h2 - 2 + k/5, wi = 2*w2 - 2 + (k % 5);
        float v = 0.f;
        if ((unsigned)hi < (unsigned)HH && (unsigned)wi < (unsigned)WW)
            v = hT[((size_t)(b*HH + hi)*WW + wi)*128 + tid];
        u_s[pl][k][tid] = v;
    }
    __syncthreads();

    const int s = tid & 63, pl = tid >> 6;
    const int cg = s & 15, ng = s >> 4;
    float acc[8][4];
    #pragma unroll
    for (int i = 0; i < 8; i++)
        #pragma unroll
        for (int n = 0; n < 4; n++) acc[i][n] = 0.f;

    #pragma unroll
    for (int k = 0; k < 25; k++) {
        float4 ua = *reinterpret_cast<const float4*>(&u_s[pl][k][cg*4]);
        float4 ub = *reinterpret_cast<const float4*>(&u_s[pl][k][64 + cg*4]);
        float u[8] = {ua.x, ua.y, ua.z, ua.w, ub.x, ub.y, ub.z, ub.w};
        float4 wv = *reinterpret_cast<const float4*>(&wn_s[pl][k*16 + ng*4]);
        float wvv[4] = {wv.x, wv.y, wv.z, wv.w};
        #pragma unroll
        for (int i = 0; i < 8; i++)
            #pragma unroll
            for (int n = 0; n < 4; n++) acc[i][n] += u[i]*wvv[n];
    }
    size_t base = (size_t)(gpix + pl)*2048;
    #pragma unroll
    for (int i = 0; i < 8; i++) {
        int c = (i < 4) ? (cg*4 + i) : (64 + cg*4 + i - 4);
        *reinterpret_cast<float4*>(&y[base + c*16 + ng*4]) =
            make_float4(acc[i][0], acc[i][1], acc[i][2], acc[i][3]);
    }
}

// =====================================================================
// Final GEMM: K=2048, y pixel-major in, resB NCHW out, relu(bn(.)), K8/16x4
// =====================================================================
__global__ __launch_bounds__(256, 2)
void final_f2_k(const float* __restrict__ y, const float* __restrict__ lw,
                const float* __restrict__ lb, const float* __restrict__ bns,
                const float* __restrict__ bnb, float* __restrict__ out)
{
    __shared__ __align__(16) float sraw[2*PW_STAGE];
    const int gp = blockIdx.x * 128;          // over B*NP2
    const int b = gp / NP2, pp = gp - b*NP2;
    const int tid = threadIdx.x, ty = tid >> 5, tx = tid & 31;
    const int sy_px = tid >> 1, sy_h = tid & 1;
    const int sw_oc = tid >> 1, sw_h = tid & 1;
    U64 acc[8][4];
    #pragma unroll
    for (int j = 0; j < 8; j++)
        #pragma unroll
        for (int p = 0; p < 4; p++) acc[j][p] = 0ULL;

    float4 rin, rw;
    auto load_chunk = [&](int kc) {
        rin = *reinterpret_cast<const float4*>(&y[(size_t)(gp + sy_px)*2048 + kc*8 + sy_h*4]);
        rw  = *reinterpret_cast<const float4*>(&lw[sw_oc*2048 + kc*8 + sw_h*4]);
    };
    auto store_stage = [&](int st) {
        float* in_s = sraw + st*PW_STAGE;
        float* w_s  = in_s + 8*132;
        in_s[(sy_h*4+0)*132 + sy_px] = rin.x; in_s[(sy_h*4+1)*132 + sy_px] = rin.y;
        in_s[(sy_h*4+2)*132 + sy_px] = rin.z; in_s[(sy_h*4+3)*132 + sy_px] = rin.w;
        w_s[(sw_h*4+0)*132 + sw_oc] = rw.x; w_s[(sw_h*4+1)*132 + sw_oc] = rw.y;
        w_s[(sw_h*4+2)*132 + sw_oc] = rw.z; w_s[(sw_h*4+3)*132 + sw_oc] = rw.w;
    };

    load_chunk(0); store_stage(0);
    load_chunk(1);
    __syncthreads();
    for (int kc = 0; kc < 256; kc++) {
        if (kc + 1 < 256) store_stage((kc + 1) & 1);
        if (kc + 2 < 256) load_chunk(kc + 2);
        const float* base = sraw + (kc & 1)*PW_STAGE;
        gemm_k8_16x4(base, base + 8*132, ty, tx, acc);
        __syncthreads();
    }
    #pragma unroll
    for (int j = 0; j < 8; j++) {
        float lo[4], hi[4];
        #pragma unroll
        for (int p = 0; p < 4; p++) {
            unsigned a, c; UNPK2(a, c, acc[j][p]);
            lo[p] = __uint_as_float(a); hi[p] = __uint_as_float(c);
        }
        #pragma unroll
        for (int hh2 = 0; hh2 < 2; hh2++) {
            int oc = ty*16 + 2*j + hh2;
            const float* src = hh2 ? hi : lo;
            float bi = lb[oc], s = bns[oc], bb2 = bnb[oc];
            float zt[4];
            #pragma unroll
            for (int p = 0; p < 4; p++) {
                float z = s*(src[p] + bi) + bb2;
                zt[p] = z > 0.f ? z : 0.f;
            }
            *reinterpret_cast<float4*>(&out[((b*128 + oc)*NP2) + pp + tx*4]) =
                make_float4(zt[0], zt[1], zt[2], zt[3]);
        }
    }
}

// =====================================================================
// host launcher
// =====================================================================
extern "C" void kernel_launch(void* const* d_in, const int* in_sizes, int n_in,
                              void* d_out, int out_size)
{
    const float* x      = (const float*)d_in[0];
    const float* xyz    = (const float*)d_in[1];
    const float* c1_w   = (const float*)d_in[2];
    const float* c1_b   = (const float*)d_in[3];
    const float* c2_w   = (const float*)d_in[4];
    const float* c2_b   = (const float*)d_in[5];
    const float* c3_w   = (const float*)d_in[6];
    const float* c3_b   = (const float*)d_in[7];
    const float* c4_w   = (const float*)d_in[8];
    const float* c4_b   = (const float*)d_in[9];
    const float* c5_w   = (const float*)d_in[10];
    const float* c5_b   = (const float*)d_in[11];
    const float* rbn_s  = (const float*)d_in[12];
    const float* rbn_b  = (const float*)d_in[13];
    const float* p_w    = (const float*)d_in[14];
    const float* p_b    = (const float*)d_in[15];
    const float* pbn_s  = (const float*)d_in[16];
    const float* pbn_b  = (const float*)d_in[17];
    const float* lin_w  = (const float*)d_in[18];
    const float* lin_b  = (const float*)d_in[19];
    const float* w1_w   = (const float*)d_in[20];
    const float* w1_b   = (const float*)d_in[21];
    const float* w2_w   = (const float*)d_in[22];
    const float* w2_b   = (const float*)d_in[23];
    const float* w3_w   = (const float*)d_in[24];
    const float* w3_b   = (const float*)d_in[25];
    const float* wbn1_s = (const float*)d_in[26];
    const float* wbn1_b = (const float*)d_in[27];
    const float* wbn2_s = (const float*)d_in[28];
    const float* wbn2_b = (const float*)d_in[29];
    const float* wbn3_s = (const float*)d_in[30];
    const float* wbn3_b = (const float*)d_in[31];

    float* outp = (float*)d_out;
    float* resB = outp;                 // [B,128,H2,W2]
    float* resA = outp + RESB_ELEMS;    // [B,128,H,W]

    float *A1, *A2, *A3, *B1, *B2, *HT, *WN, *Y;
    cudaGetSymbolAddress((void**)&A1, g_resA1);
    cudaGetSymbolAddress((void**)&A2, g_resA2);
    cudaGetSymbolAddress((void**)&A3, g_resA3);
    cudaGetSymbolAddress((void**)&B1, g_buf1);
    cudaGetSymbolAddress((void**)&B2, g_buf2);
    cudaGetSymbolAddress((void**)&HT, g_hT);
    cudaGetSymbolAddress((void**)&WN, g_wn);
    cudaGetSymbolAddress((void**)&Y,  g_y);

    dim3 cgrid(WW/128, HH, BB);   // (8, 64, 2)
    // ResBlock trunk
    conv_f2_k<64, 3, 1, 1, 2><<<cgrid, 256>>>(x,  c2_w, c2_b, rbn_s,       rbn_b,       A1);
    conv_f2_k<128,3, 2, 2, 2><<<cgrid, 256>>>(A1, c3_w, c3_b, rbn_s + 128, rbn_b + 128, A2);
    conv_f2_k<128,2, 2, 1, 4><<<cgrid, 256>>>(A2, c4_w, c4_b, rbn_s + 256, rbn_b + 256, A3);
    resa_f2_k<<<BB*HWX/128, 256>>>(A1, A2, A3, x, c5_w, c5_b, c1_w, c1_b,
                                   rbn_s + 384, rbn_b + 384, resA);
    // Pointwise MLP (3rd layer writes transposed for the unfold gather)
    gemm128_f2_k<0><<<BB*HWX/128, 256>>>(resA, p_w,          p_b,       pbn_s,       pbn_b,       B1);
    gemm128_f2_k<0><<<BB*HWX/128, 256>>>(B1,   p_w + 16384,  p_b + 128, pbn_s + 128, pbn_b + 128, B2);
    gemm128_f2_k<1><<<BB*HWX/128, 256>>>(B2,   p_w + 32768,  p_b + 256, pbn_s + 256, pbn_b + 256, HT);
    // WeightNet on geometry
    weightnet_k<<<(BB*25*NP2)/256, 256>>>(xyz, w1_w, w1_b, w2_w, w2_b, w3_w, w3_b,
                                          wbn1_s, wbn1_b, wbn2_s, wbn2_b, wbn3_s, wbn3_b, WN);
    // unfold x wn einsum -> y (pixel-major)
    einsum_k<<<BB*NP2/2, 128>>>(HT, WN, Y);
    // final 128x2048 pointwise GEMM -> resB
    final_f2_k<<<BB*NP2/128, 256>>>(Y, lin_w, lin_b, pbn_s + 384, pbn_b + 384, resB);
}

// round 9
// speedup vs baseline: 1.1931x; 1.1931x over previous
#include <cuda_runtime.h>
#include <cstddef>

// ---------------- problem constants ----------------
#define BB   2
#define CINX 64
#define CH   128
#define HH   64
#define WW   1024
#define HWX  (HH*WW)          // 65536
#define H2X  32
#define W2X  512
#define NP2  (H2X*W2X)        // 16384
#define RESB_ELEMS (BB*CH*NP2)   // 4194304

typedef unsigned long long U64;

// f32x2 packed FMA (Blackwell): c = a*b + c elementwise on 2 packed fp32
#define FMA2(c, a, b) asm("fma.rn.f32x2 %0, %1, %2, %0;" : "+l"(c) : "l"(a), "l"(b))
#define PACK2(d, x)   asm("mov.b64 %0, {%1, %1};" : "=l"(d) : "r"(__float_as_uint(x)))
#define UNPK2(lo, hi, d) asm("mov.b64 {%0, %1}, %2;" : "=r"(lo), "=r"(hi) : "l"(d))

// GEMM smem tile geometry: 16 K x 128 px (stride 132), 16 K x 128 oc (stride 132)
#define ROWS 132
#define STAGE_F (16*ROWS*2)    // floats per stage (in + w)

// ---------------- scratch (static device memory; no allocation) ----------------
__device__ float g_resA1[BB*CH*HWX];
__device__ float g_resA2[BB*CH*HWX];
__device__ float g_resA3[BB*CH*HWX];
__device__ float g_buf1 [BB*CH*HWX];
__device__ float g_buf2 [BB*CH*HWX];
__device__ float g_hT   [BB*HWX*CH];          // transposed h: [B][H][W][C]
__device__ float g_wn   [BB*NP2*25*16];       // [B*NP2][25][16]
__device__ float g_y    [(size_t)BB*NP2*2048];// pixel-major: [B*NP2][2048]

__device__ __forceinline__ float lrelu01(float z) { return z > 0.f ? z : 0.01f*z; }

// =====================================================================
// GEMM inner: 16-K chunk, 8 oc x 8 px per thread (pixel-split 4+4), f32x2
// in_s: [16][ROWS] pixel-minor (cols 0..127 used); w_s: [16][ROWS] oc-minor
// =====================================================================
__device__ __forceinline__ void gemm_chunk_f2(const float* __restrict__ in_s,
                                              const float* __restrict__ w_s,
                                              int ty, int tx, U64 acc[4][8])
{
    #pragma unroll
    for (int kk = 0; kk < 16; kk++) {
        ulonglong2 wa = *reinterpret_cast<const ulonglong2*>(w_s + kk*ROWS + ty*8);
        ulonglong2 wb = *reinterpret_cast<const ulonglong2*>(w_s + kk*ROWS + ty*8 + 4);
        U64 wp[4] = {wa.x, wa.y, wb.x, wb.y};
        float4 xa = *reinterpret_cast<const float4*>(in_s + kk*ROWS + tx*4);
        float4 xb = *reinterpret_cast<const float4*>(in_s + kk*ROWS + 64 + tx*4);
        float xs[8] = {xa.x, xa.y, xa.z, xa.w, xb.x, xb.y, xb.z, xb.w};
        U64 xp[8];
        #pragma unroll
        for (int p = 0; p < 8; p++) PACK2(xp[p], xs[p]);
        #pragma unroll
        for (int j = 0; j < 4; j++)
            #pragma unroll
            for (int p = 0; p < 8; p++)
                FMA2(acc[j][p], wp[j], xp[p]);
    }
}

// =====================================================================
// Direct conv, double-buffered: block = 64 oc x 256 px (one row), CC=4 chans/chunk
// bn(lrelu(conv+b)), f32x2, pixel-split (halves at 0 / 128). 2 CTAs/SM.
// =====================================================================
template<int CIN, int KS, int DIL, int PAD>
__global__ __launch_bounds__(256, 2)
void conv_f2_k(const float* __restrict__ in, const float* __restrict__ wg,
               const float* __restrict__ bias, const float* __restrict__ bns,
               const float* __restrict__ bnb, float* __restrict__ out)
{
    constexpr int CC = 4, WT = 256, KK = KS*KS, IWP = 260;
    constexpr int INTOT = CC*KS*IWP;
    constexpr int NIN   = (INTOT + 255)/256;
    constexpr int WROW  = 68;
    constexpr int WTOT  = CC*KK*WROW;
    constexpr int WELEM = 64*CC*KK;
    constexpr int NW    = (WELEM + 1023)/1024;
    constexpr int WPO   = CC*KK;
    constexpr int NCH   = CIN/CC;

    __shared__ __align__(16) float in_s[2][INTOT];
    __shared__ __align__(16) float w_s[2][WTOT];

    const int bx  = blockIdx.x;
    const int w0  = (bx >> 1) * WT;
    const int oc0 = (bx & 1) * 64;
    const int h   = blockIdx.y;
    const int b   = blockIdx.z;
    const int tid = threadIdx.x;
    const int ty = tid >> 5, tx = tid & 31;

    U64 acc[4][8];
    #pragma unroll
    for (int j = 0; j < 4; j++)
        #pragma unroll
        for (int p = 0; p < 8; p++) acc[j][p] = 0ULL;

    float  rin[NIN];
    float4 rw[NW];

    auto load_chunk = [&](int cb) {
        #pragma unroll
        for (int j = 0; j < NIN; j++) {
            int idx = tid + j*256;
            float v = 0.f;
            if (idx < INTOT) {
                int ci  = idx / (KS*IWP);
                int rem = idx - ci*(KS*IWP);
                int r = rem / IWP, col = rem - r*IWP;
                int gy = h - PAD + r*DIL;
                int gx = w0 - PAD + col;
                if ((unsigned)gy < (unsigned)HH && (unsigned)gx < (unsigned)WW)
                    v = in[((b*CIN + cb + ci)*HH + gy)*WW + gx];
            }
            rin[j] = v;
        }
        #pragma unroll
        for (int j = 0; j < NW; j++) {
            int idx = tid*4 + j*1024;
            if (idx < WELEM) {
                int ocl = idx / WPO;
                int r   = idx - ocl*WPO;
                rw[j] = *reinterpret_cast<const float4*>(&wg[((oc0 + ocl)*CIN + cb)*KK + r]);
            }
        }
    };
    auto store_stage = [&](int st) {
        #pragma unroll
        for (int j = 0; j < NIN; j++) {
            int idx = tid + j*256;
            if (idx < INTOT) in_s[st][idx] = rin[j];
        }
        #pragma unroll
        for (int j = 0; j < NW; j++) {
            int idx = tid*4 + j*1024;
            if (idx < WELEM) {
                int ocl = idx / WPO;
                int r   = idx - ocl*WPO;
                float vv[4] = {rw[j].x, rw[j].y, rw[j].z, rw[j].w};
                #pragma unroll
                for (int jj = 0; jj < 4; jj++)
                    w_s[st][(r + jj)*WROW + ocl] = vv[jj];
            }
        }
    };

    load_chunk(0);
    store_stage(0);
    if (NCH > 1) load_chunk(CC);
    __syncthreads();

    for (int c = 0; c < NCH; c++) {
        if (c + 1 < NCH) store_stage((c + 1) & 1);
        if (c + 2 < NCH) load_chunk((c + 2)*CC);
        const int st = c & 1;
        #pragma unroll
        for (int ci = 0; ci < CC; ci++) {
            #pragma unroll
            for (int kh = 0; kh < KS; kh++) {
                const float* xrow = &in_s[st][(ci*KS + kh)*IWP];
                float xr1[8], xr2[8];
                *reinterpret_cast<float4*>(&xr1[0]) = *reinterpret_cast<const float4*>(xrow + tx*4);
                *reinterpret_cast<float4*>(&xr1[4]) = *reinterpret_cast<const float4*>(xrow + tx*4 + 4);
                *reinterpret_cast<float4*>(&xr2[0]) = *reinterpret_cast<const float4*>(xrow + 128 + tx*4);
                *reinterpret_cast<float4*>(&xr2[4]) = *reinterpret_cast<const float4*>(xrow + 128 + tx*4 + 4);
                #pragma unroll
                for (int kw = 0; kw < KS; kw++) {
                    const float* wrow = &w_s[st][(ci*KK + kh*KS + kw)*WROW + ty*8];
                    ulonglong2 wa = *reinterpret_cast<const ulonglong2*>(wrow);
                    ulonglong2 wb = *reinterpret_cast<const ulonglong2*>(wrow + 4);
                    U64 wp[4] = {wa.x, wa.y, wb.x, wb.y};
                    U64 xp[8];
                    #pragma unroll
                    for (int p = 0; p < 4; p++) PACK2(xp[p], xr1[p + kw*DIL]);
                    #pragma unroll
                    for (int p = 4; p < 8; p++) PACK2(xp[p], xr2[p - 4 + kw*DIL]);
                    #pragma unroll
                    for (int j = 0; j < 4; j++)
                        #pragma unroll
                        for (int p = 0; p < 8; p++)
                            FMA2(acc[j][p], wp[j], xp[p]);
                }
            }
        }
        __syncthreads();
    }
    #pragma unroll
    for (int j = 0; j < 4; j++) {
        float lo[8], hi[8];
        #pragma unroll
        for (int p = 0; p < 8; p++) {
            unsigned a, c; UNPK2(a, c, acc[j][p]);
            lo[p] = __uint_as_float(a); hi[p] = __uint_as_float(c);
        }
        #pragma unroll
        for (int hh2 = 0; hh2 < 2; hh2++) {
            int oc = oc0 + ty*8 + 2*j + hh2;
            const float* src = hh2 ? hi : lo;
            float bi = bias[oc], s = bns[oc], bb2 = bnb[oc];
            float zt[8];
            #pragma unroll
            for (int p = 0; p < 8; p++) zt[p] = s*lrelu01(src[p] + bi) + bb2;
            float* op = &out[((b*128 + oc)*HH + h)*WW + w0];
            *reinterpret_cast<float4*>(op + tx*4)       = make_float4(zt[0], zt[1], zt[2], zt[3]);
            *reinterpret_cast<float4*>(op + 128 + tx*4) = make_float4(zt[4], zt[5], zt[6], zt[7]);
        }
    }
}

// =====================================================================
// Pointwise 128->128, double-buffered, NCHW in, relu(bn(Wx+b)).
// TR=1 writes transposed [pix][C]. 128 px per block.
// =====================================================================
template<int TR>
__global__ __launch_bounds__(256, 2)
void gemm128_f2_k(const float* __restrict__ in, const float* __restrict__ wg,
                  const float* __restrict__ bias, const float* __restrict__ bns,
                  const float* __restrict__ bnb, float* __restrict__ out)
{
    __shared__ __align__(16) float sraw[2*STAGE_F];
    const int gp = blockIdx.x * 128;
    const int b = gp / HWX, pp = gp - b*HWX;
    const int tid = threadIdx.x, ty = tid >> 4, tx = tid & 15;
    const int oc1 = tid >> 2, q1 = tid & 3;
    U64 acc[4][8];
    #pragma unroll
    for (int j = 0; j < 4; j++)
        #pragma unroll
        for (int p = 0; p < 8; p++) acc[j][p] = 0ULL;

    float4 ra, rb, rwa, rwb;
    auto load_chunk = [&](int kc) {
        const float* sp = &in[((b*128 + kc*16 + ty)*HWX) + pp + tx*8];
        ra = *reinterpret_cast<const float4*>(sp);
        rb = *reinterpret_cast<const float4*>(sp + 4);
        rwa = *reinterpret_cast<const float4*>(&wg[oc1*128 + kc*16 + q1*4]);
        rwb = *reinterpret_cast<const float4*>(&wg[(oc1 + 64)*128 + kc*16 + q1*4]);
    };
    auto store_stage = [&](int st) {
        float* in_s = sraw + st*STAGE_F;
        float* w_s  = in_s + 16*ROWS;
        *reinterpret_cast<float4*>(&in_s[ty*ROWS + tx*8])     = ra;
        *reinterpret_cast<float4*>(&in_s[ty*ROWS + tx*8 + 4]) = rb;
        w_s[(q1*4+0)*ROWS + oc1] = rwa.x; w_s[(q1*4+1)*ROWS + oc1] = rwa.y;
        w_s[(q1*4+2)*ROWS + oc1] = rwa.z; w_s[(q1*4+3)*ROWS + oc1] = rwa.w;
        w_s[(q1*4+0)*ROWS + oc1+64] = rwb.x; w_s[(q1*4+1)*ROWS + oc1+64] = rwb.y;
        w_s[(q1*4+2)*ROWS + oc1+64] = rwb.z; w_s[(q1*4+3)*ROWS + oc1+64] = rwb.w;
    };

    load_chunk(0); store_stage(0);
    load_chunk(1);
    __syncthreads();
    for (int kc = 0; kc < 8; kc++) {
        if (kc + 1 < 8) store_stage((kc + 1) & 1);
        if (kc + 2 < 8) load_chunk(kc + 2);
        const float* base = sraw + (kc & 1)*STAGE_F;
        gemm_chunk_f2(base, base + 16*ROWS, ty, tx, acc);
        __syncthreads();
    }

    if (TR == 0) {
        #pragma unroll
        for (int j = 0; j < 4; j++) {
            float lo[8], hi[8];
            #pragma unroll
            for (int p = 0; p < 8; p++) {
                unsigned a, c; UNPK2(a, c, acc[j][p]);
                lo[p] = __uint_as_float(a); hi[p] = __uint_as_float(c);
            }
            #pragma unroll
            for (int hh2 = 0; hh2 < 2; hh2++) {
                int oc = ty*8 + 2*j + hh2;
                const float* src = hh2 ? hi : lo;
                float bi = bias[oc], s = bns[oc], bb2 = bnb[oc];
                float zt[8];
                #pragma unroll
                for (int p = 0; p < 8; p++) {
                    float z = s*(src[p] + bi) + bb2;
                    zt[p] = z > 0.f ? z : 0.f;
                }
                float* op = &out[((b*128 + oc)*HWX) + pp];
                *reinterpret_cast<float4*>(op + tx*4)      = make_float4(zt[0], zt[1], zt[2], zt[3]);
                *reinterpret_cast<float4*>(op + 64 + tx*4) = make_float4(zt[4], zt[5], zt[6], zt[7]);
            }
        }
    } else {
        // 4-pass transpose via smem staging (reuses sraw; needs 32*129 floats)
        float* stage = sraw;
        for (int g = 0; g < 4; g++) {
            __syncthreads();
            if ((ty >> 2) == g) {
                #pragma unroll
                for (int j = 0; j < 4; j++) {
                    unsigned a, c;
                    float lo[8], hi[8];
                    #pragma unroll
                    for (int p = 0; p < 8; p++) {
                        UNPK2(a, c, acc[j][p]);
                        lo[p] = __uint_as_float(a); hi[p] = __uint_as_float(c);
                    }
                    int oc = ty*8 + 2*j;
                    int ocl = oc - g*32;
                    float bi0 = bias[oc],   s0 = bns[oc],   b0 = bnb[oc];
                    float bi1 = bias[oc+1], s1 = bns[oc+1], b1 = bnb[oc+1];
                    #pragma unroll
                    for (int p = 0; p < 8; p++) {
                        int col = (p < 4) ? (tx*4 + p) : (64 + tx*4 + p - 4);
                        float z0 = s0*(lo[p] + bi0) + b0;
                        float z1 = s1*(hi[p] + bi1) + b1;
                        stage[ocl*129 + col]     = z0 > 0.f ? z0 : 0.f;
                        stage[(ocl+1)*129 + col] = z1 > 0.f ? z1 : 0.f;
                    }
                }
            }
            __syncthreads();
            for (int t2 = tid; t2 < 1024; t2 += 256) {
                int pix = t2 >> 3, c4 = t2 & 7;
                float4 v;
                v.x = stage[(c4*4+0)*129 + pix];
                v.y = stage[(c4*4+1)*129 + pix];
                v.z = stage[(c4*4+2)*129 + pix];
                v.w = stage[(c4*4+3)*129 + pix];
                *reinterpret_cast<float4*>(&out[(size_t)(b*HWX + pp + pix)*128 + g*32 + c4*4]) = v;
            }
        }
    }
}

// =====================================================================
// resA main: out = bn3(lrelu(c5 @ concat + c5_b)), K=384, single accumulator
// =====================================================================
__global__ __launch_bounds__(256, 2)
void resa_main_k(const float* __restrict__ r1, const float* __restrict__ r2,
                 const float* __restrict__ r3,
                 const float* __restrict__ c5w, const float* __restrict__ c5b,
                 const float* __restrict__ bns, const float* __restrict__ bnb,
                 float* __restrict__ out)
{
    __shared__ __align__(16) float sraw[2*STAGE_F];
    const int gp = blockIdx.x * 128;
    const int b = gp / HWX, pp = gp - b*HWX;
    const int tid = threadIdx.x, ty = tid >> 4, tx = tid & 15;
    const int oc1 = tid >> 2, q1 = tid & 3;
    U64 acc[4][8];
    #pragma unroll
    for (int j = 0; j < 4; j++)
        #pragma unroll
        for (int p = 0; p < 8; p++) acc[j][p] = 0ULL;

    float4 ra, rb, rwa, rwb;
    auto load_c = [&](int c) {
        const float* src = c < 8 ? r1 : (c < 16 ? r2 : r3);
        int chb = (c & 7)*16;
        const float* sp = &src[((b*128 + chb + ty)*HWX) + pp + tx*8];
        ra = *reinterpret_cast<const float4*>(sp);
        rb = *reinterpret_cast<const float4*>(sp + 4);
        rwa = *reinterpret_cast<const float4*>(&c5w[oc1*384 + c*16 + q1*4]);
        rwb = *reinterpret_cast<const float4*>(&c5w[(oc1 + 64)*384 + c*16 + q1*4]);
    };
    auto store_stage = [&](int st) {
        float* in_s = sraw + st*STAGE_F;
        float* w_s  = in_s + 16*ROWS;
        *reinterpret_cast<float4*>(&in_s[ty*ROWS + tx*8])     = ra;
        *reinterpret_cast<float4*>(&in_s[ty*ROWS + tx*8 + 4]) = rb;
        w_s[(q1*4+0)*ROWS + oc1] = rwa.x; w_s[(q1*4+1)*ROWS + oc1] = rwa.y;
        w_s[(q1*4+2)*ROWS + oc1] = rwa.z; w_s[(q1*4+3)*ROWS + oc1] = rwa.w;
        w_s[(q1*4+0)*ROWS + oc1+64] = rwb.x; w_s[(q1*4+1)*ROWS + oc1+64] = rwb.y;
        w_s[(q1*4+2)*ROWS + oc1+64] = rwb.z; w_s[(q1*4+3)*ROWS + oc1+64] = rwb.w;
    };

    load_c(0); store_stage(0);
    load_c(1);
    __syncthreads();
    for (int c = 0; c < 24; c++) {
        if (c + 1 < 24) store_stage((c + 1) & 1);
        if (c + 2 < 24) load_c(c + 2);
        const float* base = sraw + (c & 1)*STAGE_F;
        gemm_chunk_f2(base, base + 16*ROWS, ty, tx, acc);
        __syncthreads();
    }

    #pragma unroll
    for (int j = 0; j < 4; j++) {
        float lo[8], hi[8];
        #pragma unroll
        for (int p = 0; p < 8; p++) {
            unsigned a, c; UNPK2(a, c, acc[j][p]);
            lo[p] = __uint_as_float(a); hi[p] = __uint_as_float(c);
        }
        #pragma unroll
        for (int hh2 = 0; hh2 < 2; hh2++) {
            int oc = ty*8 + 2*j + hh2;
            const float* m = hh2 ? hi : lo;
            float b5 = c5b[oc], s = bns[oc], bb2 = bnb[oc];
            float zt[8];
            #pragma unroll
            for (int p = 0; p < 8; p++)
                zt[p] = s*lrelu01(m[p] + b5) + bb2;
            float* op = &out[((b*128 + oc)*HWX) + pp];
            *reinterpret_cast<float4*>(op + tx*4)      = make_float4(zt[0], zt[1], zt[2], zt[3]);
            *reinterpret_cast<float4*>(op + 64 + tx*4) = make_float4(zt[4], zt[5], zt[6], zt[7]);
        }
    }
}

// =====================================================================
// resA shortcut add: out += lrelu(c1 @ x + c1_b), K=64, single accumulator
// =====================================================================
__global__ __launch_bounds__(256, 2)
void resa_add_k(const float* __restrict__ x,
                const float* __restrict__ c1w, const float* __restrict__ c1b,
                float* __restrict__ out)
{
    __shared__ __align__(16) float sraw[2*STAGE_F];
    const int gp = blockIdx.x * 128;
    const int b = gp / HWX, pp = gp - b*HWX;
    const int tid = threadIdx.x, ty = tid >> 4, tx = tid & 15;
    const int oc1 = tid >> 2, q1 = tid & 3;
    U64 acc[4][8];
    #pragma unroll
    for (int j = 0; j < 4; j++)
        #pragma unroll
        for (int p = 0; p < 8; p++) acc[j][p] = 0ULL;

    float4 ra, rb, rwa, rwb;
    auto load_c = [&](int kc) {
        const float* sp = &x[((b*64 + kc*16 + ty)*HWX) + pp + tx*8];
        ra = *reinterpret_cast<const float4*>(sp);
        rb = *reinterpret_cast<const float4*>(sp + 4);
        rwa = *reinterpret_cast<const float4*>(&c1w[oc1*64 + kc*16 + q1*4]);
        rwb = *reinterpret_cast<const float4*>(&c1w[(oc1 + 64)*64 + kc*16 + q1*4]);
    };
    auto store_stage = [&](int st) {
        float* in_s = sraw + st*STAGE_F;
        float* w_s  = in_s + 16*ROWS;
        *reinterpret_cast<float4*>(&in_s[ty*ROWS + tx*8])     = ra;
        *reinterpret_cast<float4*>(&in_s[ty*ROWS + tx*8 + 4]) = rb;
        w_s[(q1*4+0)*ROWS + oc1] = rwa.x; w_s[(q1*4+1)*ROWS + oc1] = rwa.y;
        w_s[(q1*4+2)*ROWS + oc1] = rwa.z; w_s[(q1*4+3)*ROWS + oc1] = rwa.w;
        w_s[(q1*4+0)*ROWS + oc1+64] = rwb.x; w_s[(q1*4+1)*ROWS + oc1+64] = rwb.y;
        w_s[(q1*4+2)*ROWS + oc1+64] = rwb.z; w_s[(q1*4+3)*ROWS + oc1+64] = rwb.w;
    };

    load_c(0); store_stage(0);
    load_c(1);
    __syncthreads();
    for (int kc = 0; kc < 4; kc++) {
        if (kc + 1 < 4) store_stage((kc + 1) & 1);
        if (kc + 2 < 4) load_c(kc + 2);
        const float* base = sraw + (kc & 1)*STAGE_F;
        gemm_chunk_f2(base, base + 16*ROWS, ty, tx, acc);
        __syncthreads();
    }

    #pragma unroll
    for (int j = 0; j < 4; j++) {
        float lo[8], hi[8];
        #pragma unroll
        for (int p = 0; p < 8; p++) {
            unsigned a, c; UNPK2(a, c, acc[j][p]);
            lo[p] = __uint_as_float(a); hi[p] = __uint_as_float(c);
        }
        #pragma unroll
        for (int hh2 = 0; hh2 < 2; hh2++) {
            int oc = ty*8 + 2*j + hh2;
            const float* m = hh2 ? hi : lo;
            float b1 = c1b[oc];
            float* op = &out[((b*128 + oc)*HWX) + pp];
            float4 o0 = *reinterpret_cast<const float4*>(op + tx*4);
            float4 o1 = *reinterpret_cast<const float4*>(op + 64 + tx*4);
            o0.x += lrelu01(m[0] + b1); o0.y += lrelu01(m[1] + b1);
            o0.z += lrelu01(m[2] + b1); o0.w += lrelu01(m[3] + b1);
            o1.x += lrelu01(m[4] + b1); o1.y += lrelu01(m[5] + b1);
            o1.z += lrelu01(m[6] + b1); o1.w += lrelu01(m[7] + b1);
            *reinterpret_cast<float4*>(op + tx*4)      = o0;
            *reinterpret_cast<float4*>(op + 64 + tx*4) = o1;
        }
    }
}

// =====================================================================
// WeightNet: gxyz -> 8 -> 8 -> 16, per (b, k, pixel)
// =====================================================================
__global__ __launch_bounds__(256)
void weightnet_k(const float* __restrict__ xyz,
                 const float* __restrict__ w1w, const float* __restrict__ w1b,
                 const float* __restrict__ w2w, const float* __restrict__ w2b,
                 const float* __restrict__ w3w, const float* __restrict__ w3b,
                 const float* __restrict__ s1, const float* __restrict__ b1,
                 const float* __restrict__ s2, const float* __restrict__ b2,
                 const float* __restrict__ s3, const float* __restrict__ b3,
                 float* __restrict__ out)
{
    int g = blockIdx.x*256 + threadIdx.x;   // B*25*NP2 = 819200
    int pix = g & (NP2 - 1);
    int rest = g >> 14;
    int k = rest % 25, b = rest / 25;
    int h2 = pix >> 9, w2 = pix & 511;
    int hi = 2*h2 - 2 + k/5, wi = 2*w2 - 2 + (k % 5);
    bool inb = ((unsigned)hi < (unsigned)HH) && ((unsigned)wi < (unsigned)WW);
    float gv[3];
    #pragma unroll
    for (int c = 0; c < 3; c++) {
        float ctr = xyz[(b*3 + c)*HWX + (2*h2)*WW + 2*w2];
        float nb  = inb ? xyz[(b*3 + c)*HWX + hi*WW + wi] : 0.f;
        gv[c] = nb - ctr;
    }
    float a1[8];
    #pragma unroll
    for (int j = 0; j < 8; j++) {
        float z = w1b[j];
        #pragma unroll
        for (int c = 0; c < 3; c++) z += w1w[j*3 + c]*gv[c];
        z = s1[j]*z + b1[j];
        a1[j] = z > 0.f ? z : 0.f;
    }
    float a2[8];
    #pragma unroll
    for (int j = 0; j < 8; j++) {
        float z = w2b[j];
        #pragma unroll
        for (int i = 0; i < 8; i++) z += w2w[j*8 + i]*a1[i];
        z = s2[j]*z + b2[j];
        a2[j] = z > 0.f ? z : 0.f;
    }
    float o[16];
    #pragma unroll
    for (int n = 0; n < 16; n++) {
        float z = w3b[n];
        #pragma unroll
        for (int i = 0; i < 8; i++) z += w3w[n*8 + i]*a2[i];
        z = s3[n]*z + b3[n];
        o[n] = z > 0.f ? z : 0.f;
    }
    size_t base = (((size_t)(b*NP2 + pix))*25 + k)*16;
    #pragma unroll
    for (int q = 0; q < 4; q++)
        *reinterpret_cast<float4*>(&out[base + q*4]) =
            make_float4(o[q*4], o[q*4+1], o[q*4+2], o[q*4+3]);
}

// =====================================================================
// Einsum: y[pix][c*16+n] = sum_k unf(hT)[c][k] * wn[pix][k][n], 2 pixels/block
// =====================================================================
__global__ __launch_bounds__(128)
void einsum_k(const float* __restrict__ hT, const float* __restrict__ wn,
              float* __restrict__ y)
{
    __shared__ __align__(16) float u_s[2][25][128];
    __shared__ float wn_s[2][400];
    const int gpix = blockIdx.x*2;
    const int b = gpix / NP2;
    const int tid = threadIdx.x;

    for (int i = tid; i < 800; i += 128) {
        int pl = i / 400, r = i - pl*400;
        wn_s[pl][r] = wn[(size_t)(gpix + pl)*400 + r];
    }
    for (int idx = 0; idx < 50; idx++) {
        int pl = idx / 25, k = idx - pl*25;
        int pp = (gpix + pl) - b*NP2;
        int h2 = pp >> 9, w2 = pp & 511;
        int hi = 2*h2 - 2 + k/5, wi = 2*w2 - 2 + (k % 5);
        float v = 0.f;
        if ((unsigned)hi < (unsigned)HH && (unsigned)wi < (unsigned)WW)
            v = hT[((size_t)(b*HH + hi)*WW + wi)*128 + tid];
        u_s[pl][k][tid] = v;
    }
    __syncthreads();

    const int s = tid & 63, pl = tid >> 6;
    const int cg = s & 15, ng = s >> 4;
    float acc[8][4];
    #pragma unroll
    for (int i = 0; i < 8; i++)
        #pragma unroll
        for (int n = 0; n < 4; n++) acc[i][n] = 0.f;

    #pragma unroll
    for (int k = 0; k < 25; k++) {
        float4 ua = *reinterpret_cast<const float4*>(&u_s[pl][k][cg*4]);
        float4 ub = *reinterpret_cast<const float4*>(&u_s[pl][k][64 + cg*4]);
        float u[8] = {ua.x, ua.y, ua.z, ua.w, ub.x, ub.y, ub.z, ub.w};
        float4 wv = *reinterpret_cast<const float4*>(&wn_s[pl][k*16 + ng*4]);
        float wvv[4] = {wv.x, wv.y, wv.z, wv.w};
        #pragma unroll
        for (int i = 0; i < 8; i++)
            #pragma unroll
            for (int n = 0; n < 4; n++) acc[i][n] += u[i]*wvv[n];
    }
    size_t base = (size_t)(gpix + pl)*2048;
    #pragma unroll
    for (int i = 0; i < 8; i++) {
        int c = (i < 4) ? (cg*4 + i) : (64 + cg*4 + i - 4);
        *reinterpret_cast<float4*>(&y[base + c*16 + ng*4]) =
            make_float4(acc[i][0], acc[i][1], acc[i][2], acc[i][3]);
    }
}

// =====================================================================
// Final GEMM: K=2048, y pixel-major in, resB NCHW out, relu(bn(.)), double-buffered
// =====================================================================
__global__ __launch_bounds__(256, 2)
void final_f2_k(const float* __restrict__ y, const float* __restrict__ lw,
                const float* __restrict__ lb, const float* __restrict__ bns,
                const float* __restrict__ bnb, float* __restrict__ out)
{
    __shared__ __align__(16) float sraw[2*STAGE_F];
    const int gp = blockIdx.x * 128;          // over B*NP2
    const int b = gp / NP2, pp = gp - b*NP2;
    const int tid = threadIdx.x, ty = tid >> 4, tx = tid & 15;
    const int oc1 = tid >> 2, q1 = tid & 3;
    U64 acc[4][8];
    #pragma unroll
    for (int j = 0; j < 4; j++)
        #pragma unroll
        for (int p = 0; p < 8; p++) acc[j][p] = 0ULL;

    float4 ra, rb, rwa, rwb;
    auto load_chunk = [&](int kc) {
        ra  = *reinterpret_cast<const float4*>(&y[(size_t)(gp + oc1)*2048 + kc*16 + q1*4]);
        rb  = *reinterpret_cast<const float4*>(&y[(size_t)(gp + oc1 + 64)*2048 + kc*16 + q1*4]);
        rwa = *reinterpret_cast<const float4*>(&lw[oc1*2048 + kc*16 + q1*4]);
        rwb = *reinterpret_cast<const float4*>(&lw[(oc1 + 64)*2048 + kc*16 + q1*4]);
    };
    auto store_stage = [&](int st) {
        float* in_s = sraw + st*STAGE_F;
        float* w_s  = in_s + 16*ROWS;
        in_s[(q1*4+0)*ROWS + oc1] = ra.x; in_s[(q1*4+1)*ROWS + oc1] = ra.y;
        in_s[(q1*4+2)*ROWS + oc1] = ra.z; in_s[(q1*4+3)*ROWS + oc1] = ra.w;
        in_s[(q1*4+0)*ROWS + oc1+64] = rb.x; in_s[(q1*4+1)*ROWS + oc1+64] = rb.y;
        in_s[(q1*4+2)*ROWS + oc1+64] = rb.z; in_s[(q1*4+3)*ROWS + oc1+64] = rb.w;
        w_s[(q1*4+0)*ROWS + oc1] = rwa.x; w_s[(q1*4+1)*ROWS + oc1] = rwa.y;
        w_s[(q1*4+2)*ROWS + oc1] = rwa.z; w_s[(q1*4+3)*ROWS + oc1] = rwa.w;
        w_s[(q1*4+0)*ROWS + oc1+64] = rwb.x; w_s[(q1*4+1)*ROWS + oc1+64] = rwb.y;
        w_s[(q1*4+2)*ROWS + oc1+64] = rwb.z; w_s[(q1*4+3)*ROWS + oc1+64] = rwb.w;
    };

    load_chunk(0); store_stage(0);
    load_chunk(1);
    __syncthreads();
    for (int kc = 0; kc < 128; kc++) {
        if (kc + 1 < 128) store_stage((kc + 1) & 1);
        if (kc + 2 < 128) load_chunk(kc + 2);
        const float* base = sraw + (kc & 1)*STAGE_F;
        gemm_chunk_f2(base, base + 16*ROWS, ty, tx, acc);
        __syncthreads();
    }
    #pragma unroll
    for (int j = 0; j < 4; j++) {
        float lo[8], hi[8];
        #pragma unroll
        for (int p = 0; p < 8; p++) {
            unsigned a, c; UNPK2(a, c, acc[j][p]);
            lo[p] = __uint_as_float(a); hi[p] = __uint_as_float(c);
        }
        #pragma unroll
        for (int hh2 = 0; hh2 < 2; hh2++) {
            int oc = ty*8 + 2*j + hh2;
            const float* src = hh2 ? hi : lo;
            float bi = lb[oc], s = bns[oc], bb2 = bnb[oc];
            float zt[8];
            #pragma unroll
            for (int p = 0; p < 8; p++) {
                float z = s*(src[p] + bi) + bb2;
                zt[p] = z > 0.f ? z : 0.f;
            }
            float* op = &out[((b*128 + oc)*NP2) + pp];
            *reinterpret_cast<float4*>(op + tx*4)      = make_float4(zt[0], zt[1], zt[2], zt[3]);
            *reinterpret_cast<float4*>(op + 64 + tx*4) = make_float4(zt[4], zt[5], zt[6], zt[7]);
        }
    }
}

// =====================================================================
// host launcher
// =====================================================================
extern "C" void kernel_launch(void* const* d_in, const int* in_sizes, int n_in,
                              void* d_out, int out_size)
{
    const float* x      = (const float*)d_in[0];
    const float* xyz    = (const float*)d_in[1];
    const float* c1_w   = (const float*)d_in[2];
    const float* c1_b   = (const float*)d_in[3];
    const float* c2_w   = (const float*)d_in[4];
    const float* c2_b   = (const float*)d_in[5];
    const float* c3_w   = (const float*)d_in[6];
    const float* c3_b   = (const float*)d_in[7];
    const float* c4_w   = (const float*)d_in[8];
    const float* c4_b   = (const float*)d_in[9];
    const float* c5_w   = (const float*)d_in[10];
    const float* c5_b   = (const float*)d_in[11];
    const float* rbn_s  = (const float*)d_in[12];
    const float* rbn_b  = (const float*)d_in[13];
    const float* p_w    = (const float*)d_in[14];
    const float* p_b    = (const float*)d_in[15];
    const float* pbn_s  = (const float*)d_in[16];
    const float* pbn_b  = (const float*)d_in[17];
    const float* lin_w  = (const float*)d_in[18];
    const float* lin_b  = (const float*)d_in[19];
    const float* w1_w   = (const float*)d_in[20];
    const float* w1_b   = (const float*)d_in[21];
    const float* w2_w   = (const float*)d_in[22];
    const float* w2_b   = (const float*)d_in[23];
    const float* w3_w   = (const float*)d_in[24];
    const float* w3_b   = (const float*)d_in[25];
    const float* wbn1_s = (const float*)d_in[26];
    const float* wbn1_b = (const float*)d_in[27];
    const float* wbn2_s = (const float*)d_in[28];
    const float* wbn2_b = (const float*)d_in[29];
    const float* wbn3_s = (const float*)d_in[30];
    const float* wbn3_b = (const float*)d_in[31];

    float* outp = (float*)d_out;
    float* resB = outp;                 // [B,128,H2,W2]
    float* resA = outp + RESB_ELEMS;    // [B,128,H,W]

    float *A1, *A2, *A3, *B1, *B2, *HT, *WN, *Y;
    cudaGetSymbolAddress((void**)&A1, g_resA1);
    cudaGetSymbolAddress((void**)&A2, g_resA2);
    cudaGetSymbolAddress((void**)&A3, g_resA3);
    cudaGetSymbolAddress((void**)&B1, g_buf1);
    cudaGetSymbolAddress((void**)&B2, g_buf2);
    cudaGetSymbolAddress((void**)&HT, g_hT);
    cudaGetSymbolAddress((void**)&WN, g_wn);
    cudaGetSymbolAddress((void**)&Y,  g_y);

    dim3 cgrid(8, 64, 2);   // (4 px-tiles x 2 oc-halves, rows, batch)
    // ResBlock trunk
    conv_f2_k<64, 3, 1, 1><<<cgrid, 256>>>(x,  c2_w, c2_b, rbn_s,       rbn_b,       A1);
    conv_f2_k<128,3, 2, 2><<<cgrid, 256>>>(A1, c3_w, c3_b, rbn_s + 128, rbn_b + 128, A2);
    conv_f2_k<128,2, 2, 1><<<cgrid, 256>>>(A2, c4_w, c4_b, rbn_s + 256, rbn_b + 256, A3);
    resa_main_k<<<BB*HWX/128, 256>>>(A1, A2, A3, c5_w, c5_b,
                                     rbn_s + 384, rbn_b + 384, resA);
    resa_add_k<<<BB*HWX/128, 256>>>(x, c1_w, c1_b, resA);
    // Pointwise MLP (3rd layer writes transposed for the unfold gather)
    gemm128_f2_k<0><<<BB*HWX/128, 256>>>(resA, p_w,          p_b,       pbn_s,       pbn_b,       B1);
    gemm128_f2_k<0><<<BB*HWX/128, 256>>>(B1,   p_w + 16384,  p_b + 128, pbn_s + 128, pbn_b + 128, B2);
    gemm128_f2_k<1><<<BB*HWX/128, 256>>>(B2,   p_w + 32768,  p_b + 256, pbn_s + 256, pbn_b + 256, HT);
    // WeightNet on geometry
    weightnet_k<<<(BB*25*NP2)/256, 256>>>(xyz, w1_w, w1_b, w2_w, w2_b, w3_w, w3_b,
                                          wbn1_s, wbn1_b, wbn2_s, wbn2_b, wbn3_s, wbn3_b, WN);
    // unfold x wn einsum -> y (pixel-major)
    einsum_k<<<BB*NP2/2, 128>>>(HT, WN, Y);
    // final 128x2048 pointwise GEMM -> resB
    final_f2_k<<<BB*NP2/128, 256>>>(Y, lin_w, lin_b, pbn_s + 384, pbn_b + 384, resB);
}

// round 10
// speedup vs baseline: 1.2771x; 1.0704x over previous
#include <cuda_runtime.h>
#include <cstddef>

// ---------------- problem constants ----------------
#define BB   2
#define CINX 64
#define CH   128
#define HH   64
#define WW   1024
#define HWX  (HH*WW)          // 65536
#define H2X  32
#define W2X  512
#define NP2  (H2X*W2X)        // 16384
#define RESB_ELEMS (BB*CH*NP2)   // 4194304

typedef unsigned long long U64;

// f32x2 packed FMA (Blackwell): c = a*b + c elementwise on 2 packed fp32
#define FMA2(c, a, b) asm("fma.rn.f32x2 %0, %1, %2, %0;" : "+l"(c) : "l"(a), "l"(b))
#define PACK2(d, x)   asm("mov.b64 %0, {%1, %1};" : "=l"(d) : "r"(__float_as_uint(x)))
#define UNPK2(lo, hi, d) asm("mov.b64 {%0, %1}, %2;" : "=r"(lo), "=r"(hi) : "l"(d))

// GEMM smem tile geometry: 16 K x 128 px (stride 132), 16 K x 128 oc (stride 132)
#define ROWS 132
#define STAGE_F (16*ROWS*2)    // floats per stage (in + w)

// ---------------- scratch (static device memory; no allocation) ----------------
__device__ float g_resA1[BB*CH*HWX];
__device__ float g_resA2[BB*CH*HWX];
__device__ float g_resA3[BB*CH*HWX];
__device__ float g_buf1 [BB*CH*HWX];
__device__ float g_buf2 [BB*CH*HWX];
__device__ float g_hT   [BB*HWX*CH];          // transposed h: [B][H][W][C]
__device__ float g_wn   [BB*NP2*25*16];       // [B*NP2][25][16]
__device__ float g_y    [(size_t)BB*NP2*2048];// pixel-major: [B*NP2][2048]

__device__ __forceinline__ float lrelu01(float z) { return z > 0.f ? z : 0.01f*z; }

// =====================================================================
// GEMM inner: 16-K chunk, 8 oc x 8 px per thread (pixel-split 4+4), f32x2
// in_s: [16][ROWS] pixel-minor (cols 0..127 used); w_s: [16][ROWS] oc-minor
// =====================================================================
__device__ __forceinline__ void gemm_chunk_f2(const float* __restrict__ in_s,
                                              const float* __restrict__ w_s,
                                              int ty, int tx, U64 acc[4][8])
{
    #pragma unroll
    for (int kk = 0; kk < 16; kk++) {
        ulonglong2 wa = *reinterpret_cast<const ulonglong2*>(w_s + kk*ROWS + ty*8);
        ulonglong2 wb = *reinterpret_cast<const ulonglong2*>(w_s + kk*ROWS + ty*8 + 4);
        U64 wp[4] = {wa.x, wa.y, wb.x, wb.y};
        float4 xa = *reinterpret_cast<const float4*>(in_s + kk*ROWS + tx*4);
        float4 xb = *reinterpret_cast<const float4*>(in_s + kk*ROWS + 64 + tx*4);
        float xs[8] = {xa.x, xa.y, xa.z, xa.w, xb.x, xb.y, xb.z, xb.w};
        U64 xp[8];
        #pragma unroll
        for (int p = 0; p < 8; p++) PACK2(xp[p], xs[p]);
        #pragma unroll
        for (int j = 0; j < 4; j++)
            #pragma unroll
            for (int p = 0; p < 8; p++)
                FMA2(acc[j][p], wp[j], xp[p]);
    }
}

// =====================================================================
// Direct conv, double-buffered: block = 64 oc x 256 px (one row).
// CC channels/chunk chosen so regs fit 2 CTAs/SM without spills.
// Weight staging: float4 path when WPO%4==0, coalesced scalar path otherwise.
// =====================================================================
template<int CIN, int KS, int DIL, int PAD, int CC>
__global__ __launch_bounds__(256, 2)
void conv_f2_k(const float* __restrict__ in, const float* __restrict__ wg,
               const float* __restrict__ bias, const float* __restrict__ bns,
               const float* __restrict__ bnb, float* __restrict__ out)
{
    constexpr int WT = 256, KK = KS*KS, IWP = 260;
    constexpr int INTOT = CC*KS*IWP;
    constexpr int NIN   = (INTOT + 255)/256;
    constexpr int WROW  = 68;
    constexpr int WTOT  = CC*KK*WROW;
    constexpr int WPO   = CC*KK;
    constexpr int WELEM = 64*WPO;
    constexpr int NCH   = CIN/CC;
    constexpr bool W4   = (WPO % 4) == 0;
    constexpr int NW    = W4 ? (WELEM + 1023)/1024 : 1;
    constexpr int NWS   = W4 ? 1 : (WELEM + 255)/256;

    __shared__ __align__(16) float in_s[2][INTOT];
    __shared__ __align__(16) float w_s[2][WTOT];

    const int bx  = blockIdx.x;
    const int w0  = (bx >> 1) * WT;
    const int oc0 = (bx & 1) * 64;
    const int h   = blockIdx.y;
    const int b   = blockIdx.z;
    const int tid = threadIdx.x;
    const int ty = tid >> 5, tx = tid & 31;

    U64 acc[4][8];
    #pragma unroll
    for (int j = 0; j < 4; j++)
        #pragma unroll
        for (int p = 0; p < 8; p++) acc[j][p] = 0ULL;

    float  rin[NIN];
    float4 rw4[NW];
    float  rws[NWS];

    auto load_chunk = [&](int cb) {
        #pragma unroll
        for (int j = 0; j < NIN; j++) {
            int idx = tid + j*256;
            float v = 0.f;
            if (idx < INTOT) {
                int ci  = idx / (KS*IWP);
                int rem = idx - ci*(KS*IWP);
                int r = rem / IWP, col = rem - r*IWP;
                int gy = h - PAD + r*DIL;
                int gx = w0 - PAD + col;
                if ((unsigned)gy < (unsigned)HH && (unsigned)gx < (unsigned)WW)
                    v = in[((b*CIN + cb + ci)*HH + gy)*WW + gx];
            }
            rin[j] = v;
        }
        if constexpr (W4) {
            #pragma unroll
            for (int j = 0; j < NW; j++) {
                int idx = tid*4 + j*1024;
                if (idx < WELEM) {
                    int ocl = idx / WPO;
                    int r   = idx - ocl*WPO;
                    rw4[j] = *reinterpret_cast<const float4*>(&wg[((oc0 + ocl)*CIN + cb)*KK + r]);
                }
            }
        } else {
            #pragma unroll
            for (int j = 0; j < NWS; j++) {
                int idx = tid + j*256;
                if (idx < WELEM) {
                    int ocl = idx / WPO;
                    int r   = idx - ocl*WPO;
                    rws[j] = wg[((oc0 + ocl)*CIN + cb)*KK + r];
                }
            }
        }
    };
    auto store_stage = [&](int st) {
        #pragma unroll
        for (int j = 0; j < NIN; j++) {
            int idx = tid + j*256;
            if (idx < INTOT) in_s[st][idx] = rin[j];
        }
        if constexpr (W4) {
            #pragma unroll
            for (int j = 0; j < NW; j++) {
                int idx = tid*4 + j*1024;
                if (idx < WELEM) {
                    int ocl = idx / WPO;
                    int r   = idx - ocl*WPO;
                    float vv[4] = {rw4[j].x, rw4[j].y, rw4[j].z, rw4[j].w};
                    #pragma unroll
                    for (int jj = 0; jj < 4; jj++)
                        w_s[st][(r + jj)*WROW + ocl] = vv[jj];
                }
            }
        } else {
            #pragma unroll
            for (int j = 0; j < NWS; j++) {
                int idx = tid + j*256;
                if (idx < WELEM) {
                    int ocl = idx / WPO;
                    int r   = idx - ocl*WPO;
                    w_s[st][r*WROW + ocl] = rws[j];
                }
            }
        }
    };

    load_chunk(0);
    store_stage(0);
    if (NCH > 1) load_chunk(CC);
    __syncthreads();

    for (int c = 0; c < NCH; c++) {
        if (c + 1 < NCH) store_stage((c + 1) & 1);
        if (c + 2 < NCH) load_chunk((c + 2)*CC);
        const int st = c & 1;
        #pragma unroll
        for (int ci = 0; ci < CC; ci++) {
            #pragma unroll
            for (int kh = 0; kh < KS; kh++) {
                const float* xrow = &in_s[st][(ci*KS + kh)*IWP];
                float xr1[8], xr2[8];
                *reinterpret_cast<float4*>(&xr1[0]) = *reinterpret_cast<const float4*>(xrow + tx*4);
                *reinterpret_cast<float4*>(&xr1[4]) = *reinterpret_cast<const float4*>(xrow + tx*4 + 4);
                *reinterpret_cast<float4*>(&xr2[0]) = *reinterpret_cast<const float4*>(xrow + 128 + tx*4);
                *reinterpret_cast<float4*>(&xr2[4]) = *reinterpret_cast<const float4*>(xrow + 128 + tx*4 + 4);
                #pragma unroll
                for (int kw = 0; kw < KS; kw++) {
                    const float* wrow = &w_s[st][(ci*KK + kh*KS + kw)*WROW + ty*8];
                    ulonglong2 wa = *reinterpret_cast<const ulonglong2*>(wrow);
                    ulonglong2 wb = *reinterpret_cast<const ulonglong2*>(wrow + 4);
                    U64 wp[4] = {wa.x, wa.y, wb.x, wb.y};
                    U64 xp[8];
                    #pragma unroll
                    for (int p = 0; p < 4; p++) PACK2(xp[p], xr1[p + kw*DIL]);
                    #pragma unroll
                    for (int p = 4; p < 8; p++) PACK2(xp[p], xr2[p - 4 + kw*DIL]);
                    #pragma unroll
                    for (int j = 0; j < 4; j++)
                        #pragma unroll
                        for (int p = 0; p < 8; p++)
                            FMA2(acc[j][p], wp[j], xp[p]);
                }
            }
        }
        __syncthreads();
    }
    #pragma unroll
    for (int j = 0; j < 4; j++) {
        float lo[8], hi[8];
        #pragma unroll
        for (int p = 0; p < 8; p++) {
            unsigned a, c; UNPK2(a, c, acc[j][p]);
            lo[p] = __uint_as_float(a); hi[p] = __uint_as_float(c);
        }
        #pragma unroll
        for (int hh2 = 0; hh2 < 2; hh2++) {
            int oc = oc0 + ty*8 + 2*j + hh2;
            const float* src = hh2 ? hi : lo;
            float bi = bias[oc], s = bns[oc], bb2 = bnb[oc];
            float zt[8];
            #pragma unroll
            for (int p = 0; p < 8; p++) zt[p] = s*lrelu01(src[p] + bi) + bb2;
            float* op = &out[((b*128 + oc)*HH + h)*WW + w0];
            *reinterpret_cast<float4*>(op + tx*4)       = make_float4(zt[0], zt[1], zt[2], zt[3]);
            *reinterpret_cast<float4*>(op + 128 + tx*4) = make_float4(zt[4], zt[5], zt[6], zt[7]);
        }
    }
}

// =====================================================================
// Pointwise 128->128, double-buffered, NCHW in, relu(bn(Wx+b)).
// TR=1 writes transposed [pix][C]. 128 px per block.
// =====================================================================
template<int TR>
__global__ __launch_bounds__(256, 2)
void gemm128_f2_k(const float* __restrict__ in, const float* __restrict__ wg,
                  const float* __restrict__ bias, const float* __restrict__ bns,
                  const float* __restrict__ bnb, float* __restrict__ out)
{
    __shared__ __align__(16) float sraw[2*STAGE_F];
    const int gp = blockIdx.x * 128;
    const int b = gp / HWX, pp = gp - b*HWX;
    const int tid = threadIdx.x, ty = tid >> 4, tx = tid & 15;
    const int oc1 = tid >> 2, q1 = tid & 3;
    U64 acc[4][8];
    #pragma unroll
    for (int j = 0; j < 4; j++)
        #pragma unroll
        for (int p = 0; p < 8; p++) acc[j][p] = 0ULL;

    float4 ra, rb, rwa, rwb;
    auto load_chunk = [&](int kc) {
        const float* sp = &in[((b*128 + kc*16 + ty)*HWX) + pp + tx*8];
        ra = *reinterpret_cast<const float4*>(sp);
        rb = *reinterpret_cast<const float4*>(sp + 4);
        rwa = *reinterpret_cast<const float4*>(&wg[oc1*128 + kc*16 + q1*4]);
        rwb = *reinterpret_cast<const float4*>(&wg[(oc1 + 64)*128 + kc*16 + q1*4]);
    };
    auto store_stage = [&](int st) {
        float* in_s = sraw + st*STAGE_F;
        float* w_s  = in_s + 16*ROWS;
        *reinterpret_cast<float4*>(&in_s[ty*ROWS + tx*8])     = ra;
        *reinterpret_cast<float4*>(&in_s[ty*ROWS + tx*8 + 4]) = rb;
        w_s[(q1*4+0)*ROWS + oc1] = rwa.x; w_s[(q1*4+1)*ROWS + oc1] = rwa.y;
        w_s[(q1*4+2)*ROWS + oc1] = rwa.z; w_s[(q1*4+3)*ROWS + oc1] = rwa.w;
        w_s[(q1*4+0)*ROWS + oc1+64] = rwb.x; w_s[(q1*4+1)*ROWS + oc1+64] = rwb.y;
        w_s[(q1*4+2)*ROWS + oc1+64] = rwb.z; w_s[(q1*4+3)*ROWS + oc1+64] = rwb.w;
    };

    load_chunk(0); store_stage(0);
    load_chunk(1);
    __syncthreads();
    for (int kc = 0; kc < 8; kc++) {
        if (kc + 1 < 8) store_stage((kc + 1) & 1);
        if (kc + 2 < 8) load_chunk(kc + 2);
        const float* base = sraw + (kc & 1)*STAGE_F;
        gemm_chunk_f2(base, base + 16*ROWS, ty, tx, acc);
        __syncthreads();
    }

    if (TR == 0) {
        #pragma unroll
        for (int j = 0; j < 4; j++) {
            float lo[8], hi[8];
            #pragma unroll
            for (int p = 0; p < 8; p++) {
                unsigned a, c; UNPK2(a, c, acc[j][p]);
                lo[p] = __uint_as_float(a); hi[p] = __uint_as_float(c);
            }
            #pragma unroll
            for (int hh2 = 0; hh2 < 2; hh2++) {
                int oc = ty*8 + 2*j + hh2;
                const float* src = hh2 ? hi : lo;
                float bi = bias[oc], s = bns[oc], bb2 = bnb[oc];
                float zt[8];
                #pragma unroll
                for (int p = 0; p < 8; p++) {
                    float z = s*(src[p] + bi) + bb2;
                    zt[p] = z > 0.f ? z : 0.f;
                }
                float* op = &out[((b*128 + oc)*HWX) + pp];
                *reinterpret_cast<float4*>(op + tx*4)      = make_float4(zt[0], zt[1], zt[2], zt[3]);
                *reinterpret_cast<float4*>(op + 64 + tx*4) = make_float4(zt[4], zt[5], zt[6], zt[7]);
            }
        }
    } else {
        // 4-pass transpose via smem staging (reuses sraw; needs 32*129 floats)
        float* stage = sraw;
        for (int g = 0; g < 4; g++) {
            __syncthreads();
            if ((ty >> 2) == g) {
                #pragma unroll
                for (int j = 0; j < 4; j++) {
                    unsigned a, c;
                    float lo[8], hi[8];
                    #pragma unroll
                    for (int p = 0; p < 8; p++) {
                        UNPK2(a, c, acc[j][p]);
                        lo[p] = __uint_as_float(a); hi[p] = __uint_as_float(c);
                    }
                    int oc = ty*8 + 2*j;
                    int ocl = oc - g*32;
                    float bi0 = bias[oc],   s0 = bns[oc],   b0 = bnb[oc];
                    float bi1 = bias[oc+1], s1 = bns[oc+1], b1 = bnb[oc+1];
                    #pragma unroll
                    for (int p = 0; p < 8; p++) {
                        int col = (p < 4) ? (tx*4 + p) : (64 + tx*4 + p - 4);
                        float z0 = s0*(lo[p] + bi0) + b0;
                        float z1 = s1*(hi[p] + bi1) + b1;
                        stage[ocl*129 + col]     = z0 > 0.f ? z0 : 0.f;
                        stage[(ocl+1)*129 + col] = z1 > 0.f ? z1 : 0.f;
                    }
                }
            }
            __syncthreads();
            for (int t2 = tid; t2 < 1024; t2 += 256) {
                int pix = t2 >> 3, c4 = t2 & 7;
                float4 v;
                v.x = stage[(c4*4+0)*129 + pix];
                v.y = stage[(c4*4+1)*129 + pix];
                v.z = stage[(c4*4+2)*129 + pix];
                v.w = stage[(c4*4+3)*129 + pix];
                *reinterpret_cast<float4*>(&out[(size_t)(b*HWX + pp + pix)*128 + g*32 + c4*4]) = v;
            }
        }
    }
}

// =====================================================================
// resA main: out = bn3(lrelu(c5 @ concat + c5_b)), K=384, single accumulator
// =====================================================================
__global__ __launch_bounds__(256, 2)
void resa_main_k(const float* __restrict__ r1, const float* __restrict__ r2,
                 const float* __restrict__ r3,
                 const float* __restrict__ c5w, const float* __restrict__ c5b,
                 const float* __restrict__ bns, const float* __restrict__ bnb,
                 float* __restrict__ out)
{
    __shared__ __align__(16) float sraw[2*STAGE_F];
    const int gp = blockIdx.x * 128;
    const int b = gp / HWX, pp = gp - b*HWX;
    const int tid = threadIdx.x, ty = tid >> 4, tx = tid & 15;
    const int oc1 = tid >> 2, q1 = tid & 3;
    U64 acc[4][8];
    #pragma unroll
    for (int j = 0; j < 4; j++)
        #pragma unroll
        for (int p = 0; p < 8; p++) acc[j][p] = 0ULL;

    float4 ra, rb, rwa, rwb;
    auto load_c = [&](int c) {
        const float* src = c < 8 ? r1 : (c < 16 ? r2 : r3);
        int chb = (c & 7)*16;
        const float* sp = &src[((b*128 + chb + ty)*HWX) + pp + tx*8];
        ra = *reinterpret_cast<const float4*>(sp);
        rb = *reinterpret_cast<const float4*>(sp + 4);
        rwa = *reinterpret_cast<const float4*>(&c5w[oc1*384 + c*16 + q1*4]);
        rwb = *reinterpret_cast<const float4*>(&c5w[(oc1 + 64)*384 + c*16 + q1*4]);
    };
    auto store_stage = [&](int st) {
        float* in_s = sraw + st*STAGE_F;
        float* w_s  = in_s + 16*ROWS;
        *reinterpret_cast<float4*>(&in_s[ty*ROWS + tx*8])     = ra;
        *reinterpret_cast<float4*>(&in_s[ty*ROWS + tx*8 + 4]) = rb;
        w_s[(q1*4+0)*ROWS + oc1] = rwa.x; w_s[(q1*4+1)*ROWS + oc1] = rwa.y;
        w_s[(q1*4+2)*ROWS + oc1] = rwa.z; w_s[(q1*4+3)*ROWS + oc1] = rwa.w;
        w_s[(q1*4+0)*ROWS + oc1+64] = rwb.x; w_s[(q1*4+1)*ROWS + oc1+64] = rwb.y;
        w_s[(q1*4+2)*ROWS + oc1+64] = rwb.z; w_s[(q1*4+3)*ROWS + oc1+64] = rwb.w;
    };

    load_c(0); store_stage(0);
    load_c(1);
    __syncthreads();
    for (int c = 0; c < 24; c++) {
        if (c + 1 < 24) store_stage((c + 1) & 1);
        if (c + 2 < 24) load_c(c + 2);
        const float* base = sraw + (c & 1)*STAGE_F;
        gemm_chunk_f2(base, base + 16*ROWS, ty, tx, acc);
        __syncthreads();
    }

    #pragma unroll
    for (int j = 0; j < 4; j++) {
        float lo[8], hi[8];
        #pragma unroll
        for (int p = 0; p < 8; p++) {
            unsigned a, c; UNPK2(a, c, acc[j][p]);
            lo[p] = __uint_as_float(a); hi[p] = __uint_as_float(c);
        }
        #pragma unroll
        for (int hh2 = 0; hh2 < 2; hh2++) {
            int oc = ty*8 + 2*j + hh2;
            const float* m = hh2 ? hi : lo;
            float b5 = c5b[oc], s = bns[oc], bb2 = bnb[oc];
            float zt[8];
            #pragma unroll
            for (int p = 0; p < 8; p++)
                zt[p] = s*lrelu01(m[p] + b5) + bb2;
            float* op = &out[((b*128 + oc)*HWX) + pp];
            *reinterpret_cast<float4*>(op + tx*4)      = make_float4(zt[0], zt[1], zt[2], zt[3]);
            *reinterpret_cast<float4*>(op + 64 + tx*4) = make_float4(zt[4], zt[5], zt[6], zt[7]);
        }
    }
}

// =====================================================================
// resA shortcut add: out += lrelu(c1 @ x + c1_b), K=64, single accumulator
// =====================================================================
__global__ __launch_bounds__(256, 2)
void resa_add_k(const float* __restrict__ x,
                const float* __restrict__ c1w, const float* __restrict__ c1b,
                float* __restrict__ out)
{
    __shared__ __align__(16) float sraw[2*STAGE_F];
    const int gp = blockIdx.x * 128;
    const int b = gp / HWX, pp = gp - b*HWX;
    const int tid = threadIdx.x, ty = tid >> 4, tx = tid & 15;
    const int oc1 = tid >> 2, q1 = tid & 3;
    U64 acc[4][8];
    #pragma unroll
    for (int j = 0; j < 4; j++)
        #pragma unroll
        for (int p = 0; p < 8; p++) acc[j][p] = 0ULL;

    float4 ra, rb, rwa, rwb;
    auto load_c = [&](int kc) {
        const float* sp = &x[((b*64 + kc*16 + ty)*HWX) + pp + tx*8];
        ra = *reinterpret_cast<const float4*>(sp);
        rb = *reinterpret_cast<const float4*>(sp + 4);
        rwa = *reinterpret_cast<const float4*>(&c1w[oc1*64 + kc*16 + q1*4]);
        rwb = *reinterpret_cast<const float4*>(&c1w[(oc1 + 64)*64 + kc*16 + q1*4]);
    };
    auto store_stage = [&](int st) {
        float* in_s = sraw + st*STAGE_F;
        float* w_s  = in_s + 16*ROWS;
        *reinterpret_cast<float4*>(&in_s[ty*ROWS + tx*8])     = ra;
        *reinterpret_cast<float4*>(&in_s[ty*ROWS + tx*8 + 4]) = rb;
        w_s[(q1*4+0)*ROWS + oc1] = rwa.x; w_s[(q1*4+1)*ROWS + oc1] = rwa.y;
        w_s[(q1*4+2)*ROWS + oc1] = rwa.z; w_s[(q1*4+3)*ROWS + oc1] = rwa.w;
        w_s[(q1*4+0)*ROWS + oc1+64] = rwb.x; w_s[(q1*4+1)*ROWS + oc1+64] = rwb.y;
        w_s[(q1*4+2)*ROWS + oc1+64] = rwb.z; w_s[(q1*4+3)*ROWS + oc1+64] = rwb.w;
    };

    load_c(0); store_stage(0);
    load_c(1);
    __syncthreads();
    for (int kc = 0; kc < 4; kc++) {
        if (kc + 1 < 4) store_stage((kc + 1) & 1);
        if (kc + 2 < 4) load_c(kc + 2);
        const float* base = sraw + (kc & 1)*STAGE_F;
        gemm_chunk_f2(base, base + 16*ROWS, ty, tx, acc);
        __syncthreads();
    }

    #pragma unroll
    for (int j = 0; j < 4; j++) {
        float lo[8], hi[8];
        #pragma unroll
        for (int p = 0; p < 8; p++) {
            unsigned a, c; UNPK2(a, c, acc[j][p]);
            lo[p] = __uint_as_float(a); hi[p] = __uint_as_float(c);
        }
        #pragma unroll
        for (int hh2 = 0; hh2 < 2; hh2++) {
            int oc = ty*8 + 2*j + hh2;
            const float* m = hh2 ? hi : lo;
            float b1 = c1b[oc];
            float* op = &out[((b*128 + oc)*HWX) + pp];
            float4 o0 = *reinterpret_cast<const float4*>(op + tx*4);
            float4 o1 = *reinterpret_cast<const float4*>(op + 64 + tx*4);
            o0.x += lrelu01(m[0] + b1); o0.y += lrelu01(m[1] + b1);
            o0.z += lrelu01(m[2] + b1); o0.w += lrelu01(m[3] + b1);
            o1.x += lrelu01(m[4] + b1); o1.y += lrelu01(m[5] + b1);
            o1.z += lrelu01(m[6] + b1); o1.w += lrelu01(m[7] + b1);
            *reinterpret_cast<float4*>(op + tx*4)      = o0;
            *reinterpret_cast<float4*>(op + 64 + tx*4) = o1;
        }
    }
}

// =====================================================================
// WeightNet: gxyz -> 8 -> 8 -> 16, per (b, k, pixel)
// =====================================================================
__global__ __launch_bounds__(256)
void weightnet_k(const float* __restrict__ xyz,
                 const float* __restrict__ w1w, const float* __restrict__ w1b,
                 const float* __restrict__ w2w, const float* __restrict__ w2b,
                 const float* __restrict__ w3w, const float* __restrict__ w3b,
                 const float* __restrict__ s1, const float* __restrict__ b1,
                 const float* __restrict__ s2, const float* __restrict__ b2,
                 const float* __restrict__ s3, const float* __restrict__ b3,
                 float* __restrict__ out)
{
    int g = blockIdx.x*256 + threadIdx.x;   // B*25*NP2 = 819200
    int pix = g & (NP2 - 1);
    int rest = g >> 14;
    int k = rest % 25, b = rest / 25;
    int h2 = pix >> 9, w2 = pix & 511;
    int hi = 2*h2 - 2 + k/5, wi = 2*w2 - 2 + (k % 5);
    bool inb = ((unsigned)hi < (unsigned)HH) && ((unsigned)wi < (unsigned)WW);
    float gv[3];
    #pragma unroll
    for (int c = 0; c < 3; c++) {
        float ctr = xyz[(b*3 + c)*HWX + (2*h2)*WW + 2*w2];
        float nb  = inb ? xyz[(b*3 + c)*HWX + hi*WW + wi] : 0.f;
        gv[c] = nb - ctr;
    }
    float a1[8];
    #pragma unroll
    for (int j = 0; j < 8; j++) {
        float z = w1b[j];
        #pragma unroll
        for (int c = 0; c < 3; c++) z += w1w[j*3 + c]*gv[c];
        z = s1[j]*z + b1[j];
        a1[j] = z > 0.f ? z : 0.f;
    }
    float a2[8];
    #pragma unroll
    for (int j = 0; j < 8; j++) {
        float z = w2b[j];
        #pragma unroll
        for (int i = 0; i < 8; i++) z += w2w[j*8 + i]*a1[i];
        z = s2[j]*z + b2[j];
        a2[j] = z > 0.f ? z : 0.f;
    }
    float o[16];
    #pragma unroll
    for (int n = 0; n < 16; n++) {
        float z = w3b[n];
        #pragma unroll
        for (int i = 0; i < 8; i++) z += w3w[n*8 + i]*a2[i];
        z = s3[n]*z + b3[n];
        o[n] = z > 0.f ? z : 0.f;
    }
    size_t base = (((size_t)(b*NP2 + pix))*25 + k)*16;
    #pragma unroll
    for (int q = 0; q < 4; q++)
        *reinterpret_cast<float4*>(&out[base + q*4]) =
            make_float4(o[q*4], o[q*4+1], o[q*4+2], o[q*4+3]);
}

// =====================================================================
// Einsum: y[pix][c*16+n] = sum_k unf(hT)[c][k] * wn[pix][k][n], 2 pixels/block
// =====================================================================
__global__ __launch_bounds__(128)
void einsum_k(const float* __restrict__ hT, const float* __restrict__ wn,
              float* __restrict__ y)
{
    __shared__ __align__(16) float u_s[2][25][128];
    __shared__ float wn_s[2][400];
    const int gpix = blockIdx.x*2;
    const int b = gpix / NP2;
    const int tid = threadIdx.x;

    for (int i = tid; i < 800; i += 128) {
        int pl = i / 400, r = i - pl*400;
        wn_s[pl][r] = wn[(size_t)(gpix + pl)*400 + r];
    }
    for (int idx = 0; idx < 50; idx++) {
        int pl = idx / 25, k = idx - pl*25;
        int pp = (gpix + pl) - b*NP2;
        int h2 = pp >> 9, w2 = pp & 511;
        int hi = 2*h2 - 2 + k/5, wi = 2*w2 - 2 + (k % 5);
        float v = 0.f;
        if ((unsigned)hi < (unsigned)HH && (unsigned)wi < (unsigned)WW)
            v = hT[((size_t)(b*HH + hi)*WW + wi)*128 + tid];
        u_s[pl][k][tid] = v;
    }
    __syncthreads();

    const int s = tid & 63, pl = tid >> 6;
    const int cg = s & 15, ng = s >> 4;
    float acc[8][4];
    #pragma unroll
    for (int i = 0; i < 8; i++)
        #pragma unroll
        for (int n = 0; n < 4; n++) acc[i][n] = 0.f;

    #pragma unroll
    for (int k = 0; k < 25; k++) {
        float4 ua = *reinterpret_cast<const float4*>(&u_s[pl][k][cg*4]);
        float4 ub = *reinterpret_cast<const float4*>(&u_s[pl][k][64 + cg*4]);
        float u[8] = {ua.x, ua.y, ua.z, ua.w, ub.x, ub.y, ub.z, ub.w};
        float4 wv = *reinterpret_cast<const float4*>(&wn_s[pl][k*16 + ng*4]);
        float wvv[4] = {wv.x, wv.y, wv.z, wv.w};
        #pragma unroll
        for (int i = 0; i < 8; i++)
            #pragma unroll
            for (int n = 0; n < 4; n++) acc[i][n] += u[i]*wvv[n];
    }
    size_t base = (size_t)(gpix + pl)*2048;
    #pragma unroll
    for (int i = 0; i < 8; i++) {
        int c = (i < 4) ? (cg*4 + i) : (64 + cg*4 + i - 4);
        *reinterpret_cast<float4*>(&y[base + c*16 + ng*4]) =
            make_float4(acc[i][0], acc[i][1], acc[i][2], acc[i][3]);
    }
}

// =====================================================================
// Final GEMM: K=2048, y pixel-major in, resB NCHW out, relu(bn(.)), double-buffered
// =====================================================================
__global__ __launch_bounds__(256, 2)
void final_f2_k(const float* __restrict__ y, const float* __restrict__ lw,
                const float* __restrict__ lb, const float* __restrict__ bns,
                const float* __restrict__ bnb, float* __restrict__ out)
{
    __shared__ __align__(16) float sraw[2*STAGE_F];
    const int gp = blockIdx.x * 128;          // over B*NP2
    const int b = gp / NP2, pp = gp - b*NP2;
    const int tid = threadIdx.x, ty = tid >> 4, tx = tid & 15;
    const int oc1 = tid >> 2, q1 = tid & 3;
    U64 acc[4][8];
    #pragma unroll
    for (int j = 0; j < 4; j++)
        #pragma unroll
        for (int p = 0; p < 8; p++) acc[j][p] = 0ULL;

    float4 ra, rb, rwa, rwb;
    auto load_chunk = [&](int kc) {
        ra  = *reinterpret_cast<const float4*>(&y[(size_t)(gp + oc1)*2048 + kc*16 + q1*4]);
        rb  = *reinterpret_cast<const float4*>(&y[(size_t)(gp + oc1 + 64)*2048 + kc*16 + q1*4]);
        rwa = *reinterpret_cast<const float4*>(&lw[oc1*2048 + kc*16 + q1*4]);
        rwb = *reinterpret_cast<const float4*>(&lw[(oc1 + 64)*2048 + kc*16 + q1*4]);
    };
    auto store_stage = [&](int st) {
        float* in_s = sraw + st*STAGE_F;
        float* w_s  = in_s + 16*ROWS;
        in_s[(q1*4+0)*ROWS + oc1] = ra.x; in_s[(q1*4+1)*ROWS + oc1] = ra.y;
        in_s[(q1*4+2)*ROWS + oc1] = ra.z; in_s[(q1*4+3)*ROWS + oc1] = ra.w;
        in_s[(q1*4+0)*ROWS + oc1+64] = rb.x; in_s[(q1*4+1)*ROWS + oc1+64] = rb.y;
        in_s[(q1*4+2)*ROWS + oc1+64] = rb.z; in_s[(q1*4+3)*ROWS + oc1+64] = rb.w;
        w_s[(q1*4+0)*ROWS + oc1] = rwa.x; w_s[(q1*4+1)*ROWS + oc1] = rwa.y;
        w_s[(q1*4+2)*ROWS + oc1] = rwa.z; w_s[(q1*4+3)*ROWS + oc1] = rwa.w;
        w_s[(q1*4+0)*ROWS + oc1+64] = rwb.x; w_s[(q1*4+1)*ROWS + oc1+64] = rwb.y;
        w_s[(q1*4+2)*ROWS + oc1+64] = rwb.z; w_s[(q1*4+3)*ROWS + oc1+64] = rwb.w;
    };

    load_chunk(0); store_stage(0);
    load_chunk(1);
    __syncthreads();
    for (int kc = 0; kc < 128; kc++) {
        if (kc + 1 < 128) store_stage((kc + 1) & 1);
        if (kc + 2 < 128) load_chunk(kc + 2);
        const float* base = sraw + (kc & 1)*STAGE_F;
        gemm_chunk_f2(base, base + 16*ROWS, ty, tx, acc);
        __syncthreads();
    }
    #pragma unroll
    for (int j = 0; j < 4; j++) {
        float lo[8], hi[8];
        #pragma unroll
        for (int p = 0; p < 8; p++) {
            unsigned a, c; UNPK2(a, c, acc[j][p]);
            lo[p] = __uint_as_float(a); hi[p] = __uint_as_float(c);
        }
        #pragma unroll
        for (int hh2 = 0; hh2 < 2; hh2++) {
            int oc = ty*8 + 2*j + hh2;
            const float* src = hh2 ? hi : lo;
            float bi = lb[oc], s = bns[oc], bb2 = bnb[oc];
            float zt[8];
            #pragma unroll
            for (int p = 0; p < 8; p++) {
                float z = s*(src[p] + bi) + bb2;
                zt[p] = z > 0.f ? z : 0.f;
            }
            float* op = &out[((b*128 + oc)*NP2) + pp];
            *reinterpret_cast<float4*>(op + tx*4)      = make_float4(zt[0], zt[1], zt[2], zt[3]);
            *reinterpret_cast<float4*>(op + 64 + tx*4) = make_float4(zt[4], zt[5], zt[6], zt[7]);
        }
    }
}

// =====================================================================
// host launcher
// =====================================================================
extern "C" void kernel_launch(void* const* d_in, const int* in_sizes, int n_in,
                              void* d_out, int out_size)
{
    const float* x      = (const float*)d_in[0];
    const float* xyz    = (const float*)d_in[1];
    const float* c1_w   = (const float*)d_in[2];
    const float* c1_b   = (const float*)d_in[3];
    const float* c2_w   = (const float*)d_in[4];
    const float* c2_b   = (const float*)d_in[5];
    const float* c3_w   = (const float*)d_in[6];
    const float* c3_b   = (const float*)d_in[7];
    const float* c4_w   = (const float*)d_in[8];
    const float* c4_b   = (const float*)d_in[9];
    const float* c5_w   = (const float*)d_in[10];
    const float* c5_b   = (const float*)d_in[11];
    const float* rbn_s  = (const float*)d_in[12];
    const float* rbn_b  = (const float*)d_in[13];
    const float* p_w    = (const float*)d_in[14];
    const float* p_b    = (const float*)d_in[15];
    const float* pbn_s  = (const float*)d_in[16];
    const float* pbn_b  = (const float*)d_in[17];
    const float* lin_w  = (const float*)d_in[18];
    const float* lin_b  = (const float*)d_in[19];
    const float* w1_w   = (const float*)d_in[20];
    const float* w1_b   = (const float*)d_in[21];
    const float* w2_w   = (const float*)d_in[22];
    const float* w2_b   = (const float*)d_in[23];
    const float* w3_w   = (const float*)d_in[24];
    const float* w3_b   = (const float*)d_in[25];
    const float* wbn1_s = (const float*)d_in[26];
    const float* wbn1_b = (const float*)d_in[27];
    const float* wbn2_s = (const float*)d_in[28];
    const float* wbn2_b = (const float*)d_in[29];
    const float* wbn3_s = (const float*)d_in[30];
    const float* wbn3_b = (const float*)d_in[31];

    float* outp = (float*)d_out;
    float* resB = outp;                 // [B,128,H2,W2]
    float* resA = outp + RESB_ELEMS;    // [B,128,H,W]

    float *A1, *A2, *A3, *B1, *B2, *HT, *WN, *Y;
    cudaGetSymbolAddress((void**)&A1, g_resA1);
    cudaGetSymbolAddress((void**)&A2, g_resA2);
    cudaGetSymbolAddress((void**)&A3, g_resA3);
    cudaGetSymbolAddress((void**)&B1, g_buf1);
    cudaGetSymbolAddress((void**)&B2, g_buf2);
    cudaGetSymbolAddress((void**)&HT, g_hT);
    cudaGetSymbolAddress((void**)&WN, g_wn);
    cudaGetSymbolAddress((void**)&Y,  g_y);

    dim3 cgrid(8, 64, 2);   // (4 px-tiles x 2 oc-halves, rows, batch)
    // ResBlock trunk (CC=2 for 3x3 convs -> no spills at 2 CTAs/SM; CC=4 for 2x2)
    conv_f2_k<64, 3, 1, 1, 2><<<cgrid, 256>>>(x,  c2_w, c2_b, rbn_s,       rbn_b,       A1);
    conv_f2_k<128,3, 2, 2, 2><<<cgrid, 256>>>(A1, c3_w, c3_b, rbn_s + 128, rbn_b + 128, A2);
    conv_f2_k<128,2, 2, 1, 4><<<cgrid, 256>>>(A2, c4_w, c4_b, rbn_s + 256, rbn_b + 256, A3);
    resa_main_k<<<BB*HWX/128, 256>>>(A1, A2, A3, c5_w, c5_b,
                                     rbn_s + 384, rbn_b + 384, resA);
    resa_add_k<<<BB*HWX/128, 256>>>(x, c1_w, c1_b, resA);
    // Pointwise MLP (3rd layer writes transposed for the unfold gather)
    gemm128_f2_k<0><<<BB*HWX/128, 256>>>(resA, p_w,          p_b,       pbn_s,       pbn_b,       B1);
    gemm128_f2_k<0><<<BB*HWX/128, 256>>>(B1,   p_w + 16384,  p_b + 128, pbn_s + 128, pbn_b + 128, B2);
    gemm128_f2_k<1><<<BB*HWX/128, 256>>>(B2,   p_w + 32768,  p_b + 256, pbn_s + 256, pbn_b + 256, HT);
    // WeightNet on geometry
    weightnet_k<<<(BB*25*NP2)/256, 256>>>(xyz, w1_w, w1_b, w2_w, w2_b, w3_w, w3_b,
                                          wbn1_s, wbn1_b, wbn2_s, wbn2_b, wbn3_s, wbn3_b, WN);
    // unfold x wn einsum -> y (pixel-major)
    einsum_k<<<BB*NP2/2, 128>>>(HT, WN, Y);
    // final 128x2048 pointwise GEMM -> resB
    final_f2_k<<<BB*NP2/128, 256>>>(Y, lin_w, lin_b, pbn_s + 384, pbn_b + 384, resB);
}

// round 13
// speedup vs baseline: 1.3124x; 1.0276x over previous
#include <cuda_runtime.h>
#include <cuda_bf16.h>
#include <cstddef>
#include <cstdint>

// ---------------- problem constants ----------------
#define BB   2
#define CINX 64
#define CH   128
#define HH   64
#define WW   1024
#define HWX  (HH*WW)          // 65536
#define H2X  32
#define W2X  512
#define NP2  (H2X*W2X)        // 16384
#define RESB_ELEMS (BB*CH*NP2)   // 4194304

typedef unsigned long long U64;

// f32x2 packed FMA (Blackwell): c = a*b + c elementwise on 2 packed fp32
#define FMA2(c, a, b) asm("fma.rn.f32x2 %0, %1, %2, %0;" : "+l"(c) : "l"(a), "l"(b))
#define PACK2(d, x)   asm("mov.b64 %0, {%1, %1};" : "=l"(d) : "r"(__float_as_uint(x)))
#define UNPK2(lo, hi, d) asm("mov.b64 {%0, %1}, %2;" : "=r"(lo), "=r"(hi) : "l"(d))

// GEMM smem tile geometry: 16 K x 128 px (stride 132), 16 K x 128 oc (stride 132)
#define ROWS 132
#define STAGE_F (16*ROWS*2)    // floats per stage (in + w)

// ---------------- scratch (static device memory; no allocation) ----------------
__device__ float g_resA1[BB*CH*HWX];
__device__ float g_resA2[BB*CH*HWX];
__device__ float g_resA3[BB*CH*HWX];
__device__ float g_buf1 [BB*CH*HWX];
__device__ float g_buf2 [BB*CH*HWX];
__device__ float g_hT   [BB*HWX*CH];          // transposed h: [B][H][W][C]
__device__ float g_wn   [BB*NP2*25*16];       // [B*NP2][25][16]
__device__ float g_y    [(size_t)BB*NP2*2048];// pixel-major: [B*NP2][2048]

__device__ __forceinline__ float lrelu01(float z) { return z > 0.f ? z : 0.01f*z; }

// =====================================================================
// GEMM inner: 16-K chunk, 8 oc x 8 px per thread (pixel-split 4+4), f32x2
// =====================================================================
__device__ __forceinline__ void gemm_chunk_f2(const float* __restrict__ in_s,
                                              const float* __restrict__ w_s,
                                              int ty, int tx, U64 acc[4][8])
{
    #pragma unroll
    for (int kk = 0; kk < 16; kk++) {
        ulonglong2 wa = *reinterpret_cast<const ulonglong2*>(w_s + kk*ROWS + ty*8);
        ulonglong2 wb = *reinterpret_cast<const ulonglong2*>(w_s + kk*ROWS + ty*8 + 4);
        U64 wp[4] = {wa.x, wa.y, wb.x, wb.y};
        float4 xa = *reinterpret_cast<const float4*>(in_s + kk*ROWS + tx*4);
        float4 xb = *reinterpret_cast<const float4*>(in_s + kk*ROWS + 64 + tx*4);
        float xs[8] = {xa.x, xa.y, xa.z, xa.w, xb.x, xb.y, xb.z, xb.w};
        U64 xp[8];
        #pragma unroll
        for (int p = 0; p < 8; p++) PACK2(xp[p], xs[p]);
        #pragma unroll
        for (int j = 0; j < 4; j++)
            #pragma unroll
            for (int p = 0; p < 8; p++)
                FMA2(acc[j][p], wp[j], xp[p]);
    }
}

// =====================================================================
// Direct conv, double-buffered: block = 64 oc x 256 px (one row).
// =====================================================================
template<int CIN, int KS, int DIL, int PAD, int CC>
__global__ __launch_bounds__(256, 2)
void conv_f2_k(const float* __restrict__ in, const float* __restrict__ wg,
               const float* __restrict__ bias, const float* __restrict__ bns,
               const float* __restrict__ bnb, float* __restrict__ out)
{
    constexpr int WT = 256, KK = KS*KS, IWP = 260;
    constexpr int INTOT = CC*KS*IWP;
    constexpr int NIN   = (INTOT + 255)/256;
    constexpr int WROW  = 68;
    constexpr int WTOT  = CC*KK*WROW;
    constexpr int WPO   = CC*KK;
    constexpr int WELEM = 64*WPO;
    constexpr int NCH   = CIN/CC;
    constexpr bool W4   = (WPO % 4) == 0;
    constexpr int NW    = W4 ? (WELEM + 1023)/1024 : 1;
    constexpr int NWS   = W4 ? 1 : (WELEM + 255)/256;

    __shared__ __align__(16) float in_s[2][INTOT];
    __shared__ __align__(16) float w_s[2][WTOT];

    const int bx  = blockIdx.x;
    const int w0  = (bx >> 1) * WT;
    const int oc0 = (bx & 1) * 64;
    const int h   = blockIdx.y;
    const int b   = blockIdx.z;
    const int tid = threadIdx.x;
    const int ty = tid >> 5, tx = tid & 31;

    U64 acc[4][8];
    #pragma unroll
    for (int j = 0; j < 4; j++)
        #pragma unroll
        for (int p = 0; p < 8; p++) acc[j][p] = 0ULL;

    float  rin[NIN];
    float4 rw4[NW];
    float  rws[NWS];

    auto load_chunk = [&](int cb) {
        #pragma unroll
        for (int j = 0; j < NIN; j++) {
            int idx = tid + j*256;
            float v = 0.f;
            if (idx < INTOT) {
                int ci  = idx / (KS*IWP);
                int rem = idx - ci*(KS*IWP);
                int r = rem / IWP, col = rem - r*IWP;
                int gy = h - PAD + r*DIL;
                int gx = w0 - PAD + col;
                if ((unsigned)gy < (unsigned)HH && (unsigned)gx < (unsigned)WW)
                    v = in[((b*CIN + cb + ci)*HH + gy)*WW + gx];
            }
            rin[j] = v;
        }
        if constexpr (W4) {
            #pragma unroll
            for (int j = 0; j < NW; j++) {
                int idx = tid*4 + j*1024;
                if (idx < WELEM) {
                    int ocl = idx / WPO;
                    int r   = idx - ocl*WPO;
                    rw4[j] = *reinterpret_cast<const float4*>(&wg[((oc0 + ocl)*CIN + cb)*KK + r]);
                }
            }
        } else {
            #pragma unroll
            for (int j = 0; j < NWS; j++) {
                int idx = tid + j*256;
                if (idx < WELEM) {
                    int ocl = idx / WPO;
                    int r   = idx - ocl*WPO;
                    rws[j] = wg[((oc0 + ocl)*CIN + cb)*KK + r];
                }
            }
        }
    };
    auto store_stage = [&](int st) {
        #pragma unroll
        for (int j = 0; j < NIN; j++) {
            int idx = tid + j*256;
            if (idx < INTOT) in_s[st][idx] = rin[j];
        }
        if constexpr (W4) {
            #pragma unroll
            for (int j = 0; j < NW; j++) {
                int idx = tid*4 + j*1024;
                if (idx < WELEM) {
                    int ocl = idx / WPO;
                    int r   = idx - ocl*WPO;
                    float vv[4] = {rw4[j].x, rw4[j].y, rw4[j].z, rw4[j].w};
                    #pragma unroll
                    for (int jj = 0; jj < 4; jj++)
                        w_s[st][(r + jj)*WROW + ocl] = vv[jj];
                }
            }
        } else {
            #pragma unroll
            for (int j = 0; j < NWS; j++) {
                int idx = tid + j*256;
                if (idx < WELEM) {
                    int ocl = idx / WPO;
                    int r   = idx - ocl*WPO;
                    w_s[st][r*WROW + ocl] = rws[j];
                }
            }
        }
    };

    load_chunk(0);
    store_stage(0);
    if (NCH > 1) load_chunk(CC);
    __syncthreads();

    for (int c = 0; c < NCH; c++) {
        if (c + 1 < NCH) store_stage((c + 1) & 1);
        if (c + 2 < NCH) load_chunk((c + 2)*CC);
        const int st = c & 1;
        #pragma unroll
        for (int ci = 0; ci < CC; ci++) {
            #pragma unroll
            for (int kh = 0; kh < KS; kh++) {
                const float* xrow = &in_s[st][(ci*KS + kh)*IWP];
                float xr1[8], xr2[8];
                *reinterpret_cast<float4*>(&xr1[0]) = *reinterpret_cast<const float4*>(xrow + tx*4);
                *reinterpret_cast<float4*>(&xr1[4]) = *reinterpret_cast<const float4*>(xrow + tx*4 + 4);
                *reinterpret_cast<float4*>(&xr2[0]) = *reinterpret_cast<const float4*>(xrow + 128 + tx*4);
                *reinterpret_cast<float4*>(&xr2[4]) = *reinterpret_cast<const float4*>(xrow + 128 + tx*4 + 4);
                #pragma unroll
                for (int kw = 0; kw < KS; kw++) {
                    const float* wrow = &w_s[st][(ci*KK + kh*KS + kw)*WROW + ty*8];
                    ulonglong2 wa = *reinterpret_cast<const ulonglong2*>(wrow);
                    ulonglong2 wb = *reinterpret_cast<const ulonglong2*>(wrow + 4);
                    U64 wp[4] = {wa.x, wa.y, wb.x, wb.y};
                    U64 xp[8];
                    #pragma unroll
                    for (int p = 0; p < 4; p++) PACK2(xp[p], xr1[p + kw*DIL]);
                    #pragma unroll
                    for (int p = 4; p < 8; p++) PACK2(xp[p], xr2[p - 4 + kw*DIL]);
                    #pragma unroll
                    for (int j = 0; j < 4; j++)
                        #pragma unroll
                        for (int p = 0; p < 8; p++)
                            FMA2(acc[j][p], wp[j], xp[p]);
                }
            }
        }
        __syncthreads();
    }
    #pragma unroll
    for (int j = 0; j < 4; j++) {
        float lo[8], hi[8];
        #pragma unroll
        for (int p = 0; p < 8; p++) {
            unsigned a, c; UNPK2(a, c, acc[j][p]);
            lo[p] = __uint_as_float(a); hi[p] = __uint_as_float(c);
        }
        #pragma unroll
        for (int hh2 = 0; hh2 < 2; hh2++) {
            int oc = oc0 + ty*8 + 2*j + hh2;
            const float* src = hh2 ? hi : lo;
            float bi = bias[oc], s = bns[oc], bb2 = bnb[oc];
            float zt[8];
            #pragma unroll
            for (int p = 0; p < 8; p++) zt[p] = s*lrelu01(src[p] + bi) + bb2;
            float* op = &out[((b*128 + oc)*HH + h)*WW + w0];
            *reinterpret_cast<float4*>(op + tx*4)       = make_float4(zt[0], zt[1], zt[2], zt[3]);
            *reinterpret_cast<float4*>(op + 128 + tx*4) = make_float4(zt[4], zt[5], zt[6], zt[7]);
        }
    }
}

// =====================================================================
// Pointwise 128->128, double-buffered, NCHW in, relu(bn(Wx+b)).
// TR=1 writes transposed [pix][C]. 128 px per block.
// =====================================================================
template<int TR>
__global__ __launch_bounds__(256, 2)
void gemm128_f2_k(const float* __restrict__ in, const float* __restrict__ wg,
                  const float* __restrict__ bias, const float* __restrict__ bns,
                  const float* __restrict__ bnb, float* __restrict__ out)
{
    __shared__ __align__(16) float sraw[2*STAGE_F];
    const int gp = blockIdx.x * 128;
    const int b = gp / HWX, pp = gp - b*HWX;
    const int tid = threadIdx.x, ty = tid >> 4, tx = tid & 15;
    const int oc1 = tid >> 2, q1 = tid & 3;
    U64 acc[4][8];
    #pragma unroll
    for (int j = 0; j < 4; j++)
        #pragma unroll
        for (int p = 0; p < 8; p++) acc[j][p] = 0ULL;

    float4 ra, rb, rwa, rwb;
    auto load_chunk = [&](int kc) {
        const float* sp = &in[((b*128 + kc*16 + ty)*HWX) + pp + tx*8];
        ra = *reinterpret_cast<const float4*>(sp);
        rb = *reinterpret_cast<const float4*>(sp + 4);
        rwa = *reinterpret_cast<const float4*>(&wg[oc1*128 + kc*16 + q1*4]);
        rwb = *reinterpret_cast<const float4*>(&wg[(oc1 + 64)*128 + kc*16 + q1*4]);
    };
    auto store_stage = [&](int st) {
        float* in_s = sraw + st*STAGE_F;
        float* w_s  = in_s + 16*ROWS;
        *reinterpret_cast<float4*>(&in_s[ty*ROWS + tx*8])     = ra;
        *reinterpret_cast<float4*>(&in_s[ty*ROWS + tx*8 + 4]) = rb;
        w_s[(q1*4+0)*ROWS + oc1] = rwa.x; w_s[(q1*4+1)*ROWS + oc1] = rwa.y;
        w_s[(q1*4+2)*ROWS + oc1] = rwa.z; w_s[(q1*4+3)*ROWS + oc1] = rwa.w;
        w_s[(q1*4+0)*ROWS + oc1+64] = rwb.x; w_s[(q1*4+1)*ROWS + oc1+64] = rwb.y;
        w_s[(q1*4+2)*ROWS + oc1+64] = rwb.z; w_s[(q1*4+3)*ROWS + oc1+64] = rwb.w;
    };

    load_chunk(0); store_stage(0);
    load_chunk(1);
    __syncthreads();
    for (int kc = 0; kc < 8; kc++) {
        if (kc + 1 < 8) store_stage((kc + 1) & 1);
        if (kc + 2 < 8) load_chunk(kc + 2);
        const float* base = sraw + (kc & 1)*STAGE_F;
        gemm_chunk_f2(base, base + 16*ROWS, ty, tx, acc);
        __syncthreads();
    }

    if (TR == 0) {
        #pragma unroll
        for (int j = 0; j < 4; j++) {
            float lo[8], hi[8];
            #pragma unroll
            for (int p = 0; p < 8; p++) {
                unsigned a, c; UNPK2(a, c, acc[j][p]);
                lo[p] = __uint_as_float(a); hi[p] = __uint_as_float(c);
            }
            #pragma unroll
            for (int hh2 = 0; hh2 < 2; hh2++) {
                int oc = ty*8 + 2*j + hh2;
                const float* src = hh2 ? hi : lo;
                float bi = bias[oc], s = bns[oc], bb2 = bnb[oc];
                float zt[8];
                #pragma unroll
                for (int p = 0; p < 8; p++) {
                    float z = s*(src[p] + bi) + bb2;
                    zt[p] = z > 0.f ? z : 0.f;
                }
                float* op = &out[((b*128 + oc)*HWX) + pp];
                *reinterpret_cast<float4*>(op + tx*4)      = make_float4(zt[0], zt[1], zt[2], zt[3]);
                *reinterpret_cast<float4*>(op + 64 + tx*4) = make_float4(zt[4], zt[5], zt[6], zt[7]);
            }
        }
    } else {
        float* stage = sraw;
        for (int g = 0; g < 4; g++) {
            __syncthreads();
            if ((ty >> 2) == g) {
                #pragma unroll
                for (int j = 0; j < 4; j++) {
                    unsigned a, c;
                    float lo[8], hi[8];
                    #pragma unroll
                    for (int p = 0; p < 8; p++) {
                        UNPK2(a, c, acc[j][p]);
                        lo[p] = __uint_as_float(a); hi[p] = __uint_as_float(c);
                    }
                    int oc = ty*8 + 2*j;
                    int ocl = oc - g*32;
                    float bi0 = bias[oc],   s0 = bns[oc],   b0 = bnb[oc];
                    float bi1 = bias[oc+1], s1 = bns[oc+1], b1 = bnb[oc+1];
                    #pragma unroll
                    for (int p = 0; p < 8; p++) {
                        int col = (p < 4) ? (tx*4 + p) : (64 + tx*4 + p - 4);
                        float z0 = s0*(lo[p] + bi0) + b0;
                        float z1 = s1*(hi[p] + bi1) + b1;
                        stage[ocl*129 + col]     = z0 > 0.f ? z0 : 0.f;
                        stage[(ocl+1)*129 + col] = z1 > 0.f ? z1 : 0.f;
                    }
                }
            }
            __syncthreads();
            for (int t2 = tid; t2 < 1024; t2 += 256) {
                int pix = t2 >> 3, c4 = t2 & 7;
                float4 v;
                v.x = stage[(c4*4+0)*129 + pix];
                v.y = stage[(c4*4+1)*129 + pix];
                v.z = stage[(c4*4+2)*129 + pix];
                v.w = stage[(c4*4+3)*129 + pix];
                *reinterpret_cast<float4*>(&out[(size_t)(b*HWX + pp + pix)*128 + g*32 + c4*4]) = v;
            }
        }
    }
}

// =====================================================================
// resA main: out = bn3(lrelu(c5 @ concat + c5_b)), K=384, single accumulator
// =====================================================================
__global__ __launch_bounds__(256, 2)
void resa_main_k(const float* __restrict__ r1, const float* __restrict__ r2,
                 const float* __restrict__ r3,
                 const float* __restrict__ c5w, const float* __restrict__ c5b,
                 const float* __restrict__ bns, const float* __restrict__ bnb,
                 float* __restrict__ out)
{
    __shared__ __align__(16) float sraw[2*STAGE_F];
    const int gp = blockIdx.x * 128;
    const int b = gp / HWX, pp = gp - b*HWX;
    const int tid = threadIdx.x, ty = tid >> 4, tx = tid & 15;
    const int oc1 = tid >> 2, q1 = tid & 3;
    U64 acc[4][8];
    #pragma unroll
    for (int j = 0; j < 4; j++)
        #pragma unroll
        for (int p = 0; p < 8; p++) acc[j][p] = 0ULL;

    float4 ra, rb, rwa, rwb;
    auto load_c = [&](int c) {
        const float* src = c < 8 ? r1 : (c < 16 ? r2 : r3);
        int chb = (c & 7)*16;
        const float* sp = &src[((b*128 + chb + ty)*HWX) + pp + tx*8];
        ra = *reinterpret_cast<const float4*>(sp);
        rb = *reinterpret_cast<const float4*>(sp + 4);
        rwa = *reinterpret_cast<const float4*>(&c5w[oc1*384 + c*16 + q1*4]);
        rwb = *reinterpret_cast<const float4*>(&c5w[(oc1 + 64)*384 + c*16 + q1*4]);
    };
    auto store_stage = [&](int st) {
        float* in_s = sraw + st*STAGE_F;
        float* w_s  = in_s + 16*ROWS;
        *reinterpret_cast<float4*>(&in_s[ty*ROWS + tx*8])     = ra;
        *reinterpret_cast<float4*>(&in_s[ty*ROWS + tx*8 + 4]) = rb;
        w_s[(q1*4+0)*ROWS + oc1] = rwa.x; w_s[(q1*4+1)*ROWS + oc1] = rwa.y;
        w_s[(q1*4+2)*ROWS + oc1] = rwa.z; w_s[(q1*4+3)*ROWS + oc1] = rwa.w;
        w_s[(q1*4+0)*ROWS + oc1+64] = rwb.x; w_s[(q1*4+1)*ROWS + oc1+64] = rwb.y;
        w_s[(q1*4+2)*ROWS + oc1+64] = rwb.z; w_s[(q1*4+3)*ROWS + oc1+64] = rwb.w;
    };

    load_c(0); store_stage(0);
    load_c(1);
    __syncthreads();
    for (int c = 0; c < 24; c++) {
        if (c + 1 < 24) store_stage((c + 1) & 1);
        if (c + 2 < 24) load_c(c + 2);
        const float* base = sraw + (c & 1)*STAGE_F;
        gemm_chunk_f2(base, base + 16*ROWS, ty, tx, acc);
        __syncthreads();
    }

    #pragma unroll
    for (int j = 0; j < 4; j++) {
        float lo[8], hi[8];
        #pragma unroll
        for (int p = 0; p < 8; p++) {
            unsigned a, c; UNPK2(a, c, acc[j][p]);
            lo[p] = __uint_as_float(a); hi[p] = __uint_as_float(c);
        }
        #pragma unroll
        for (int hh2 = 0; hh2 < 2; hh2++) {
            int oc = ty*8 + 2*j + hh2;
            const float* m = hh2 ? hi : lo;
            float b5 = c5b[oc], s = bns[oc], bb2 = bnb[oc];
            float zt[8];
            #pragma unroll
            for (int p = 0; p < 8; p++)
                zt[p] = s*lrelu01(m[p] + b5) + bb2;
            float* op = &out[((b*128 + oc)*HWX) + pp];
            *reinterpret_cast<float4*>(op + tx*4)      = make_float4(zt[0], zt[1], zt[2], zt[3]);
            *reinterpret_cast<float4*>(op + 64 + tx*4) = make_float4(zt[4], zt[5], zt[6], zt[7]);
        }
    }
}

// =====================================================================
// resA shortcut add: out += lrelu(c1 @ x + c1_b), K=64, single accumulator
// =====================================================================
__global__ __launch_bounds__(256, 2)
void resa_add_k(const float* __restrict__ x,
                const float* __restrict__ c1w, const float* __restrict__ c1b,
                float* __restrict__ out)
{
    __shared__ __align__(16) float sraw[2*STAGE_F];
    const int gp = blockIdx.x * 128;
    const int b = gp / HWX, pp = gp - b*HWX;
    const int tid = threadIdx.x, ty = tid >> 4, tx = tid & 15;
    const int oc1 = tid >> 2, q1 = tid & 3;
    U64 acc[4][8];
    #pragma unroll
    for (int j = 0; j < 4; j++)
        #pragma unroll
        for (int p = 0; p < 8; p++) acc[j][p] = 0ULL;

    float4 ra, rb, rwa, rwb;
    auto load_c = [&](int kc) {
        const float* sp = &x[((b*64 + kc*16 + ty)*HWX) + pp + tx*8];
        ra = *reinterpret_cast<const float4*>(sp);
        rb = *reinterpret_cast<const float4*>(sp + 4);
        rwa = *reinterpret_cast<const float4*>(&c1w[oc1*64 + kc*16 + q1*4]);
        rwb = *reinterpret_cast<const float4*>(&c1w[(oc1 + 64)*64 + kc*16 + q1*4]);
    };
    auto store_stage = [&](int st) {
        float* in_s = sraw + st*STAGE_F;
        float* w_s  = in_s + 16*ROWS;
        *reinterpret_cast<float4*>(&in_s[ty*ROWS + tx*8])     = ra;
        *reinterpret_cast<float4*>(&in_s[ty*ROWS + tx*8 + 4]) = rb;
        w_s[(q1*4+0)*ROWS + oc1] = rwa.x; w_s[(q1*4+1)*ROWS + oc1] = rwa.y;
        w_s[(q1*4+2)*ROWS + oc1] = rwa.z; w_s[(q1*4+3)*ROWS + oc1] = rwa.w;
        w_s[(q1*4+0)*ROWS + oc1+64] = rwb.x; w_s[(q1*4+1)*ROWS + oc1+64] = rwb.y;
        w_s[(q1*4+2)*ROWS + oc1+64] = rwb.z; w_s[(q1*4+3)*ROWS + oc1+64] = rwb.w;
    };

    load_c(0); store_stage(0);
    load_c(1);
    __syncthreads();
    for (int kc = 0; kc < 4; kc++) {
        if (kc + 1 < 4) store_stage((kc + 1) & 1);
        if (kc + 2 < 4) load_c(kc + 2);
        const float* base = sraw + (kc & 1)*STAGE_F;
        gemm_chunk_f2(base, base + 16*ROWS, ty, tx, acc);
        __syncthreads();
    }

    #pragma unroll
    for (int j = 0; j < 4; j++) {
        float lo[8], hi[8];
        #pragma unroll
        for (int p = 0; p < 8; p++) {
            unsigned a, c; UNPK2(a, c, acc[j][p]);
            lo[p] = __uint_as_float(a); hi[p] = __uint_as_float(c);
        }
        #pragma unroll
        for (int hh2 = 0; hh2 < 2; hh2++) {
            int oc = ty*8 + 2*j + hh2;
            const float* m = hh2 ? hi : lo;
            float b1 = c1b[oc];
            float* op = &out[((b*128 + oc)*HWX) + pp];
            float4 o0 = *reinterpret_cast<const float4*>(op + tx*4);
            float4 o1 = *reinterpret_cast<const float4*>(op + 64 + tx*4);
            o0.x += lrelu01(m[0] + b1); o0.y += lrelu01(m[1] + b1);
            o0.z += lrelu01(m[2] + b1); o0.w += lrelu01(m[3] + b1);
            o1.x += lrelu01(m[4] + b1); o1.y += lrelu01(m[5] + b1);
            o1.z += lrelu01(m[6] + b1); o1.w += lrelu01(m[7] + b1);
            *reinterpret_cast<float4*>(op + tx*4)      = o0;
            *reinterpret_cast<float4*>(op + 64 + tx*4) = o1;
        }
    }
}

// =====================================================================
// WeightNet: gxyz -> 8 -> 8 -> 16, per (b, k, pixel)
// =====================================================================
__global__ __launch_bounds__(256)
void weightnet_k(const float* __restrict__ xyz,
                 const float* __restrict__ w1w, const float* __restrict__ w1b,
                 const float* __restrict__ w2w, const float* __restrict__ w2b,
                 const float* __restrict__ w3w, const float* __restrict__ w3b,
                 const float* __restrict__ s1, const float* __restrict__ b1,
                 const float* __restrict__ s2, const float* __restrict__ b2,
                 const float* __restrict__ s3, const float* __restrict__ b3,
                 float* __restrict__ out)
{
    int g = blockIdx.x*256 + threadIdx.x;   // B*25*NP2 = 819200
    int pix = g & (NP2 - 1);
    int rest = g >> 14;
    int k = rest % 25, b = rest / 25;
    int h2 = pix >> 9, w2 = pix & 511;
    int hi = 2*h2 - 2 + k/5, wi = 2*w2 - 2 + (k % 5);
    bool inb = ((unsigned)hi < (unsigned)HH) && ((unsigned)wi < (unsigned)WW);
    float gv[3];
    #pragma unroll
    for (int c = 0; c < 3; c++) {
        float ctr = xyz[(b*3 + c)*HWX + (2*h2)*WW + 2*w2];
        float nb  = inb ? xyz[(b*3 + c)*HWX + hi*WW + wi] : 0.f;
        gv[c] = nb - ctr;
    }
    float a1[8];
    #pragma unroll
    for (int j = 0; j < 8; j++) {
        float z = w1b[j];
        #pragma unroll
        for (int c = 0; c < 3; c++) z += w1w[j*3 + c]*gv[c];
        z = s1[j]*z + b1[j];
        a1[j] = z > 0.f ? z : 0.f;
    }
    float a2[8];
    #pragma unroll
    for (int j = 0; j < 8; j++) {
        float z = w2b[j];
        #pragma unroll
        for (int i = 0; i < 8; i++) z += w2w[j*8 + i]*a1[i];
        z = s2[j]*z + b2[j];
        a2[j] = z > 0.f ? z : 0.f;
    }
    float o[16];
    #pragma unroll
    for (int n = 0; n < 16; n++) {
        float z = w3b[n];
        #pragma unroll
        for (int i = 0; i < 8; i++) z += w3w[n*8 + i]*a2[i];
        z = s3[n]*z + b3[n];
        o[n] = z > 0.f ? z : 0.f;
    }
    size_t base = (((size_t)(b*NP2 + pix))*25 + k)*16;
    #pragma unroll
    for (int q = 0; q < 4; q++)
        *reinterpret_cast<float4*>(&out[base + q*4]) =
            make_float4(o[q*4], o[q*4+1], o[q*4+2], o[q*4+3]);
}

// =====================================================================
// Einsum: y[pix][c*16+n] = sum_k unf(hT)[c][k] * wn[pix][k][n], 2 pixels/block
// =====================================================================
__global__ __launch_bounds__(128)
void einsum_k(const float* __restrict__ hT, const float* __restrict__ wn,
              float* __restrict__ y)
{
    __shared__ __align__(16) float u_s[2][25][128];
    __shared__ float wn_s[2][400];
    const int gpix = blockIdx.x*2;
    const int b = gpix / NP2;
    const int tid = threadIdx.x;

    for (int i = tid; i < 800; i += 128) {
        int pl = i / 400, r = i - pl*400;
        wn_s[pl][r] = wn[(size_t)(gpix + pl)*400 + r];
    }
    for (int idx = 0; idx < 50; idx++) {
        int pl = idx / 25, k = idx - pl*25;
        int pp = (gpix + pl) - b*NP2;
        int h2 = pp >> 9, w2 = pp & 511;
        int hi = 2*h2 - 2 + k/5, wi = 2*w2 - 2 + (k % 5);
        float v = 0.f;
        if ((unsigned)hi < (unsigned)HH && (unsigned)wi < (unsigned)WW)
            v = hT[((size_t)(b*HH + hi)*WW + wi)*128 + tid];
        u_s[pl][k][tid] = v;
    }
    __syncthreads();

    const int s = tid & 63, pl = tid >> 6;
    const int cg = s & 15, ng = s >> 4;
    float acc[8][4];
    #pragma unroll
    for (int i = 0; i < 8; i++)
        #pragma unroll
        for (int n = 0; n < 4; n++) acc[i][n] = 0.f;

    #pragma unroll
    for (int k = 0; k < 25; k++) {
        float4 ua = *reinterpret_cast<const float4*>(&u_s[pl][k][cg*4]);
        float4 ub = *reinterpret_cast<const float4*>(&u_s[pl][k][64 + cg*4]);
        float u[8] = {ua.x, ua.y, ua.z, ua.w, ub.x, ub.y, ub.z, ub.w};
        float4 wv = *reinterpret_cast<const float4*>(&wn_s[pl][k*16 + ng*4]);
        float wvv[4] = {wv.x, wv.y, wv.z, wv.w};
        #pragma unroll
        for (int i = 0; i < 8; i++)
            #pragma unroll
            for (int n = 0; n < 4; n++) acc[i][n] += u[i]*wvv[n];
    }
    size_t base = (size_t)(gpix + pl)*2048;
    #pragma unroll
    for (int i = 0; i < 8; i++) {
        int c = (i < 4) ? (cg*4 + i) : (64 + cg*4 + i - 4);
        *reinterpret_cast<float4*>(&y[base + c*16 + ng*4]) =
            make_float4(acc[i][0], acc[i][1], acc[i][2], acc[i][3]);
    }
}

// =====================================================================
// Final GEMM on mma.sync bf16x3 (m16n8k16, HMMA):
//   D[128 oc][128 px] = lw[128][2048] x y[px][2048]^T per CTA tile.
// 8 warps = 2(m) x 4(n); warp tile 64 oc x 32 px = 4x4 m16n8 frags.
// Smem: fp32 -> bf16 hi/lo tiles [row][k], KC=32, row stride 40 bf16
// (20 words -> conflict-free fragment LDS.32), double-buffered (80 KB).
// Split: ah*bh + al*bh + ah*bl (error ~2^-16, << 1e-3 tol).
// =====================================================================
#define FM_KC     32
#define FM_NCH    64
#define FM_STR    40
#define FM_TILE   (128*FM_STR)            // 5120 bf16 per tile
#define FM_SMEM   (2*4*FM_TILE*2)         // 81920 bytes

static __device__ __forceinline__ uint32_t pkbf(__nv_bfloat16 a, __nv_bfloat16 b) {
    return (uint32_t)__bfloat16_as_ushort(a) | ((uint32_t)__bfloat16_as_ushort(b) << 16);
}
static __device__ __forceinline__ void mma_bf16(float d[4], const uint32_t a[4],
                                                uint32_t b0, uint32_t b1) {
    asm volatile(
        "mma.sync.aligned.m16n8k16.row.col.f32.bf16.bf16.f32 "
        "{%0,%1,%2,%3}, {%4,%5,%6,%7}, {%8,%9}, {%0,%1,%2,%3};\n"
        : "+f"(d[0]), "+f"(d[1]), "+f"(d[2]), "+f"(d[3])
        : "r"(a[0]), "r"(a[1]), "r"(a[2]), "r"(a[3]), "r"(b0), "r"(b1));
}

__global__ __launch_bounds__(256)
void final_mma_k(const float* __restrict__ y, const float* __restrict__ lw,
                 const float* __restrict__ lbias, const float* __restrict__ bns,
                 const float* __restrict__ bnb, float* __restrict__ out)
{
    extern __shared__ __align__(16) __nv_bfloat16 sm2[];
    const int gp = blockIdx.x * 128;          // over B*NP2
    const int b  = gp / NP2, pp = gp - b*NP2;
    const int tid = threadIdx.x;
    const int wid = tid >> 5, lane = tid & 31;
    const int g = lane >> 2, t = lane & 3;
    const int warp_m = wid & 1, warp_n = wid >> 1;
    const int row = tid >> 1, half = tid & 1;

    float acc[4][4][4];
    #pragma unroll
    for (int mt = 0; mt < 4; mt++)
        #pragma unroll
        for (int nt = 0; nt < 4; nt++)
            #pragma unroll
            for (int q = 0; q < 4; q++) acc[mt][nt][q] = 0.f;

    float4 ra[4], rbv[4];
    auto load_chunk = [&](int ch) {
        int kc = ch*FM_KC;
        const float* as = lw + row*2048 + kc + half*16;
        const float* bs = y + (size_t)(gp + row)*2048 + kc + half*16;
        #pragma unroll
        for (int q = 0; q < 4; q++) {
            ra[q]  = *reinterpret_cast<const float4*>(as + q*4);
            rbv[q] = *reinterpret_cast<const float4*>(bs + q*4);
        }
    };
    auto store_stage = [&](int st) {
        __nv_bfloat16* base = sm2 + st*4*FM_TILE;
        int off = row*FM_STR + half*16;
        #pragma unroll
        for (int t2 = 0; t2 < 2; t2++) {
            __nv_bfloat16* dh = base + (t2 ? 2 : 0)*FM_TILE + off;
            __nv_bfloat16* dl = base + (t2 ? 3 : 1)*FM_TILE + off;
            #pragma unroll
            for (int q = 0; q < 4; q++) {
                float4 v = t2 ? rbv[q] : ra[q];
                float f[4] = {v.x, v.y, v.z, v.w};
                __nv_bfloat16 h[4], l[4];
                #pragma unroll
                for (int p = 0; p < 4; p++) {
                    h[p] = __float2bfloat16(f[p]);
                    l[p] = __float2bfloat16(f[p] - __bfloat162float(h[p]));
                }
                *reinterpret_cast<uint2*>(dh + q*4) = make_uint2(pkbf(h[0],h[1]), pkbf(h[2],h[3]));
                *reinterpret_cast<uint2*>(dl + q*4) = make_uint2(pkbf(l[0],l[1]), pkbf(l[2],l[3]));
            }
        }
    };

    load_chunk(0); store_stage(0);
    load_chunk(1);
    __syncthreads();

    for (int ch = 0; ch < FM_NCH; ch++) {
        if (ch + 1 < FM_NCH) store_stage((ch + 1) & 1);
        if (ch + 2 < FM_NCH) load_chunk(ch + 2);
        const __nv_bfloat16* Ah = sm2 + (ch & 1)*4*FM_TILE;
        const __nv_bfloat16* Al = Ah + FM_TILE;
        const __nv_bfloat16* Bh = Ah + 2*FM_TILE;
        const __nv_bfloat16* Bl = Ah + 3*FM_TILE;
        #pragma unroll
        for (int ks = 0; ks < 2; ks++) {
            const int kb = ks*16 + t*2;
            uint32_t ah[4][4], al[4][4];
            #pragma unroll
            for (int mt = 0; mt < 4; mt++) {
                int r0 = (warp_m*64 + mt*16 + g)*FM_STR;
                ah[mt][0] = *reinterpret_cast<const uint32_t*>(Ah + r0 + kb);
                ah[mt][1] = *reinterpret_cast<const uint32_t*>(Ah + r0 + 8*FM_STR + kb);
                ah[mt][2] = *reinterpret_cast<const uint32_t*>(Ah + r0 + kb + 8);
                ah[mt][3] = *reinterpret_cast<const uint32_t*>(Ah + r0 + 8*FM_STR + kb + 8);
                al[mt][0] = *reinterpret_cast<const uint32_t*>(Al + r0 + kb);
                al[mt][1] = *reinterpret_cast<const uint32_t*>(Al + r0 + 8*FM_STR + kb);
                al[mt][2] = *reinterpret_cast<const uint32_t*>(Al + r0 + kb + 8);
                al[mt][3] = *reinterpret_cast<const uint32_t*>(Al + r0 + 8*FM_STR + kb + 8);
            }
            #pragma unroll
            for (int nt = 0; nt < 4; nt++) {
                int c0 = (warp_n*32 + nt*8 + g)*FM_STR;
                uint32_t bh0 = *reinterpret_cast<const uint32_t*>(Bh + c0 + kb);
                uint32_t bh1 = *reinterpret_cast<const uint32_t*>(Bh + c0 + kb + 8);
                uint32_t bl0 = *reinterpret_cast<const uint32_t*>(Bl + c0 + kb);
                uint32_t bl1 = *reinterpret_cast<const uint32_t*>(Bl + c0 + kb + 8);
                #pragma unroll
                for (int mt = 0; mt < 4; mt++) {
                    mma_bf16(acc[mt][nt], ah[mt], bh0, bh1);
                    mma_bf16(acc[mt][nt], al[mt], bh0, bh1);
                    mma_bf16(acc[mt][nt], ah[mt], bl0, bl1);
                }
            }
        }
        __syncthreads();
    }

    // epilogue: relu(bn(d + bias)), NCHW out
    #pragma unroll
    for (int mt = 0; mt < 4; mt++) {
        #pragma unroll
        for (int r2 = 0; r2 < 2; r2++) {
            int oc = warp_m*64 + mt*16 + g + r2*8;
            float s = bns[oc], bb = bnb[oc], bi = lbias[oc];
            float* op = out + ((size_t)(b*128 + oc))*NP2 + pp + warp_n*32;
            #pragma unroll
            for (int nt = 0; nt < 4; nt++) {
                float z0 = s*(acc[mt][nt][r2*2+0] + bi) + bb;
                float z1 = s*(acc[mt][nt][r2*2+1] + bi) + bb;
                float2 v;
                v.x = z0 > 0.f ? z0 : 0.f;
                v.y = z1 > 0.f ? z1 : 0.f;
                *reinterpret_cast<float2*>(op + nt*8 + t*2) = v;
            }
        }
    }
}

// =====================================================================
// host launcher
// =====================================================================
extern "C" void kernel_launch(void* const* d_in, const int* in_sizes, int n_in,
                              void* d_out, int out_size)
{
    const float* x      = (const float*)d_in[0];
    const float* xyz    = (const float*)d_in[1];
    const float* c1_w   = (const float*)d_in[2];
    const float* c1_b   = (const float*)d_in[3];
    const float* c2_w   = (const float*)d_in[4];
    const float* c2_b   = (const float*)d_in[5];
    const float* c3_w   = (const float*)d_in[6];
    const float* c3_b   = (const float*)d_in[7];
    const float* c4_w   = (const float*)d_in[8];
    const float* c4_b   = (const float*)d_in[9];
    const float* c5_w   = (const float*)d_in[10];
    const float* c5_b   = (const float*)d_in[11];
    const float* rbn_s  = (const float*)d_in[12];
    const float* rbn_b  = (const float*)d_in[13];
    const float* p_w    = (const float*)d_in[14];
    const float* p_b    = (const float*)d_in[15];
    const float* pbn_s  = (const float*)d_in[16];
    const float* pbn_b  = (const float*)d_in[17];
    const float* lin_w  = (const float*)d_in[18];
    const float* lin_b  = (const float*)d_in[19];
    const float* w1_w   = (const float*)d_in[20];
    const float* w1_b   = (const float*)d_in[21];
    const float* w2_w   = (const float*)d_in[22];
    const float* w2_b   = (const float*)d_in[23];
    const float* w3_w   = (const float*)d_in[24];
    const float* w3_b   = (const float*)d_in[25];
    const float* wbn1_s = (const float*)d_in[26];
    const float* wbn1_b = (const float*)d_in[27];
    const float* wbn2_s = (const float*)d_in[28];
    const float* wbn2_b = (const float*)d_in[29];
    const float* wbn3_s = (const float*)d_in[30];
    const float* wbn3_b = (const float*)d_in[31];

    float* outp = (float*)d_out;
    float* resB = outp;                 // [B,128,H2,W2]
    float* resA = outp + RESB_ELEMS;    // [B,128,H,W]

    float *A1, *A2, *A3, *B1, *B2, *HT, *WN, *Y;
    cudaGetSymbolAddress((void**)&A1, g_resA1);
    cudaGetSymbolAddress((void**)&A2, g_resA2);
    cudaGetSymbolAddress((void**)&A3, g_resA3);
    cudaGetSymbolAddress((void**)&B1, g_buf1);
    cudaGetSymbolAddress((void**)&B2, g_buf2);
    cudaGetSymbolAddress((void**)&HT, g_hT);
    cudaGetSymbolAddress((void**)&WN, g_wn);
    cudaGetSymbolAddress((void**)&Y,  g_y);

    dim3 cgrid(8, 64, 2);   // (4 px-tiles x 2 oc-halves, rows, batch)
    // ResBlock trunk (CC=2 for 3x3 convs -> no spills at 2 CTAs/SM; CC=4 for 2x2)
    conv_f2_k<64, 3, 1, 1, 2><<<cgrid, 256>>>(x,  c2_w, c2_b, rbn_s,       rbn_b,       A1);
    conv_f2_k<128,3, 2, 2, 2><<<cgrid, 256>>>(A1, c3_w, c3_b, rbn_s + 128, rbn_b + 128, A2);
    conv_f2_k<128,2, 2, 1, 4><<<cgrid, 256>>>(A2, c4_w, c4_b, rbn_s + 256, rbn_b + 256, A3);
    resa_main_k<<<BB*HWX/128, 256>>>(A1, A2, A3, c5_w, c5_b,
                                     rbn_s + 384, rbn_b + 384, resA);
    resa_add_k<<<BB*HWX/128, 256>>>(x, c1_w, c1_b, resA);
    // Pointwise MLP (3rd layer writes transposed for the unfold gather)
    gemm128_f2_k<0><<<BB*HWX/128, 256>>>(resA, p_w,          p_b,       pbn_s,       pbn_b,       B1);
    gemm128_f2_k<0><<<BB*HWX/128, 256>>>(B1,   p_w + 16384,  p_b + 128, pbn_s + 128, pbn_b + 128, B2);
    gemm128_f2_k<1><<<BB*HWX/128, 256>>>(B2,   p_w + 32768,  p_b + 256, pbn_s + 256, pbn_b + 256, HT);
    // WeightNet on geometry
    weightnet_k<<<(BB*25*NP2)/256, 256>>>(xyz, w1_w, w1_b, w2_w, w2_b, w3_w, w3_b,
                                          wbn1_s, wbn1_b, wbn2_s, wbn2_b, wbn3_s, wbn3_b, WN);
    // unfold x wn einsum -> y (pixel-major)
    einsum_k<<<BB*NP2/2, 128>>>(HT, WN, Y);
    // final 128x2048 GEMM on mma.sync bf16x3 -> resB
    cudaFuncSetAttribute(final_mma_k, cudaFuncAttributeMaxDynamicSharedMemorySize, FM_SMEM);
    final_mma_k<<<BB*NP2/128, 256, FM_SMEM>>>(Y, lin_w, lin_b, pbn_s + 384, pbn_b + 384, resB);
}

// round 15
// speedup vs baseline: 1.3502x; 1.0289x over previous
#include <cuda_runtime.h>
#include <cuda_bf16.h>
#include <cstddef>
#include <cstdint>

// ---------------- problem constants ----------------
#define BB   2
#define CINX 64
#define CH   128
#define HH   64
#define WW   1024
#define HWX  (HH*WW)          // 65536
#define H2X  32
#define W2X  512
#define NP2  (H2X*W2X)        // 16384
#define RESB_ELEMS (BB*CH*NP2)   // 4194304

typedef unsigned long long U64;

// f32x2 packed FMA (Blackwell)
#define FMA2(c, a, b) asm("fma.rn.f32x2 %0, %1, %2, %0;" : "+l"(c) : "l"(a), "l"(b))
#define PACK2(d, x)   asm("mov.b64 %0, {%1, %1};" : "=l"(d) : "r"(__float_as_uint(x)))
#define UNPK2(lo, hi, d) asm("mov.b64 {%0, %1}, %2;" : "=r"(lo), "=r"(hi) : "l"(d))

#define ROWS 132
#define STAGE_F (16*ROWS*2)

// mma tile geometry
#define FM_STR    40                      // bf16 row stride (20 words -> CF frags)
#define FM_TILE   (128*FM_STR)            // 5120 bf16 per tile
#define FM_SMEM   (2*4*FM_TILE*2)         // 81920 bytes (2 stages x 4 tiles)

// precomputed weight offsets (bf16 elements)
#define WOFF_LW   0
#define WOFF_C5   262144                  // 128*2048
#define WOFF_P    311296                  // + 128*384
#define WTOTAL    360448                  // + 3*128*128

// ---------------- scratch ----------------
__device__ float g_resA1[BB*CH*HWX];
__device__ float g_resA2[BB*CH*HWX];
__device__ float g_resA3[BB*CH*HWX];
__device__ float g_buf1 [BB*CH*HWX];
__device__ float g_buf2 [BB*CH*HWX];
__device__ float g_hT   [BB*HWX*CH];
__device__ float g_wn   [BB*NP2*25*16];
__device__ __nv_bfloat16 g_yh[(size_t)BB*NP2*2048];
__device__ __nv_bfloat16 g_yl[(size_t)BB*NP2*2048];
__device__ __nv_bfloat16 g_wh[WTOTAL];
__device__ __nv_bfloat16 g_wl[WTOTAL];

__device__ __forceinline__ float lrelu01(float z) { return z > 0.f ? z : 0.01f*z; }
static __device__ __forceinline__ uint32_t pkbf(__nv_bfloat16 a, __nv_bfloat16 b) {
    return (uint32_t)__bfloat16_as_ushort(a) | ((uint32_t)__bfloat16_as_ushort(b) << 16);
}
static __device__ __forceinline__ void mma_bf16(float d[4], const uint32_t a[4],
                                                uint32_t b0, uint32_t b1) {
    asm volatile(
        "mma.sync.aligned.m16n8k16.row.col.f32.bf16.bf16.f32 "
        "{%0,%1,%2,%3}, {%4,%5,%6,%7}, {%8,%9}, {%0,%1,%2,%3};\n"
        : "+f"(d[0]), "+f"(d[1]), "+f"(d[2]), "+f"(d[3])
        : "r"(a[0]), "r"(a[1]), "r"(a[2]), "r"(a[3]), "r"(b0), "r"(b1));
}

// =====================================================================
// prep: fp32 weights -> bf16 hi/lo (lw | c5w | p_w)
// =====================================================================
__global__ __launch_bounds__(256)
void prep_w_k(const float* __restrict__ lw, const float* __restrict__ c5w,
              const float* __restrict__ pw,
              __nv_bfloat16* __restrict__ wh, __nv_bfloat16* __restrict__ wl)
{
    int idx = blockIdx.x*256 + threadIdx.x;
    if (idx >= WTOTAL) return;
    float v;
    if (idx < WOFF_C5)      v = lw[idx];
    else if (idx < WOFF_P)  v = c5w[idx - WOFF_C5];
    else                    v = pw[idx - WOFF_P];
    __nv_bfloat16 h = __float2bfloat16(v);
    wh[idx] = h;
    wl[idx] = __float2bfloat16(v - __bfloat162float(h));
}

// =====================================================================
// f32x2 GEMM inner (kept for conv / resa_add / TR kernel)
// =====================================================================
__device__ __forceinline__ void gemm_chunk_f2(const float* __restrict__ in_s,
                                              const float* __restrict__ w_s,
                                              int ty, int tx, U64 acc[4][8])
{
    #pragma unroll
    for (int kk = 0; kk < 16; kk++) {
        ulonglong2 wa = *reinterpret_cast<const ulonglong2*>(w_s + kk*ROWS + ty*8);
        ulonglong2 wb = *reinterpret_cast<const ulonglong2*>(w_s + kk*ROWS + ty*8 + 4);
        U64 wp[4] = {wa.x, wa.y, wb.x, wb.y};
        float4 xa = *reinterpret_cast<const float4*>(in_s + kk*ROWS + tx*4);
        float4 xb = *reinterpret_cast<const float4*>(in_s + kk*ROWS + 64 + tx*4);
        float xs[8] = {xa.x, xa.y, xa.z, xa.w, xb.x, xb.y, xb.z, xb.w};
        U64 xp[8];
        #pragma unroll
        for (int p = 0; p < 8; p++) PACK2(xp[p], xs[p]);
        #pragma unroll
        for (int j = 0; j < 4; j++)
            #pragma unroll
            for (int p = 0; p < 8; p++)
                FMA2(acc[j][p], wp[j], xp[p]);
    }
}

// =====================================================================
// Direct conv, double-buffered (unchanged R9 winner)
// =====================================================================
template<int CIN, int KS, int DIL, int PAD, int CC>
__global__ __launch_bounds__(256, 2)
void conv_f2_k(const float* __restrict__ in, const float* __restrict__ wg,
               const float* __restrict__ bias, const float* __restrict__ bns,
               const float* __restrict__ bnb, float* __restrict__ out)
{
    constexpr int WT = 256, KK = KS*KS, IWP = 260;
    constexpr int INTOT = CC*KS*IWP;
    constexpr int NIN   = (INTOT + 255)/256;
    constexpr int WROW  = 68;
    constexpr int WTOT  = CC*KK*WROW;
    constexpr int WPO   = CC*KK;
    constexpr int WELEM = 64*WPO;
    constexpr int NCH   = CIN/CC;
    constexpr bool W4   = (WPO % 4) == 0;
    constexpr int NW    = W4 ? (WELEM + 1023)/1024 : 1;
    constexpr int NWS   = W4 ? 1 : (WELEM + 255)/256;

    __shared__ __align__(16) float in_s[2][INTOT];
    __shared__ __align__(16) float w_s[2][WTOT];

    const int bx  = blockIdx.x;
    const int w0  = (bx >> 1) * WT;
    const int oc0 = (bx & 1) * 64;
    const int h   = blockIdx.y;
    const int b   = blockIdx.z;
    const int tid = threadIdx.x;
    const int ty = tid >> 5, tx = tid & 31;

    U64 acc[4][8];
    #pragma unroll
    for (int j = 0; j < 4; j++)
        #pragma unroll
        for (int p = 0; p < 8; p++) acc[j][p] = 0ULL;

    float  rin[NIN];
    float4 rw4[NW];
    float  rws[NWS];

    auto load_chunk = [&](int cb) {
        #pragma unroll
        for (int j = 0; j < NIN; j++) {
            int idx = tid + j*256;
            float v = 0.f;
            if (idx < INTOT) {
                int ci  = idx / (KS*IWP);
                int rem = idx - ci*(KS*IWP);
                int r = rem / IWP, col = rem - r*IWP;
                int gy = h - PAD + r*DIL;
                int gx = w0 - PAD + col;
                if ((unsigned)gy < (unsigned)HH && (unsigned)gx < (unsigned)WW)
                    v = in[((b*CIN + cb + ci)*HH + gy)*WW + gx];
            }
            rin[j] = v;
        }
        if constexpr (W4) {
            #pragma unroll
            for (int j = 0; j < NW; j++) {
                int idx = tid*4 + j*1024;
                if (idx < WELEM) {
                    int ocl = idx / WPO;
                    int r   = idx - ocl*WPO;
                    rw4[j] = *reinterpret_cast<const float4*>(&wg[((oc0 + ocl)*CIN + cb)*KK + r]);
                }
            }
        } else {
            #pragma unroll
            for (int j = 0; j < NWS; j++) {
                int idx = tid + j*256;
                if (idx < WELEM) {
                    int ocl = idx / WPO;
                    int r   = idx - ocl*WPO;
                    rws[j] = wg[((oc0 + ocl)*CIN + cb)*KK + r];
                }
            }
        }
    };
    auto store_stage = [&](int st) {
        #pragma unroll
        for (int j = 0; j < NIN; j++) {
            int idx = tid + j*256;
            if (idx < INTOT) in_s[st][idx] = rin[j];
        }
        if constexpr (W4) {
            #pragma unroll
            for (int j = 0; j < NW; j++) {
                int idx = tid*4 + j*1024;
                if (idx < WELEM) {
                    int ocl = idx / WPO;
                    int r   = idx - ocl*WPO;
                    float vv[4] = {rw4[j].x, rw4[j].y, rw4[j].z, rw4[j].w};
                    #pragma unroll
                    for (int jj = 0; jj < 4; jj++)
                        w_s[st][(r + jj)*WROW + ocl] = vv[jj];
                }
            }
        } else {
            #pragma unroll
            for (int j = 0; j < NWS; j++) {
                int idx = tid + j*256;
                if (idx < WELEM) {
                    int ocl = idx / WPO;
                    int r   = idx - ocl*WPO;
                    w_s[st][r*WROW + ocl] = rws[j];
                }
            }
        }
    };

    load_chunk(0);
    store_stage(0);
    if (NCH > 1) load_chunk(CC);
    __syncthreads();

    for (int c = 0; c < NCH; c++) {
        if (c + 1 < NCH) store_stage((c + 1) & 1);
        if (c + 2 < NCH) load_chunk((c + 2)*CC);
        const int st = c & 1;
        #pragma unroll
        for (int ci = 0; ci < CC; ci++) {
            #pragma unroll
            for (int kh = 0; kh < KS; kh++) {
                const float* xrow = &in_s[st][(ci*KS + kh)*IWP];
                float xr1[8], xr2[8];
                *reinterpret_cast<float4*>(&xr1[0]) = *reinterpret_cast<const float4*>(xrow + tx*4);
                *reinterpret_cast<float4*>(&xr1[4]) = *reinterpret_cast<const float4*>(xrow + tx*4 + 4);
                *reinterpret_cast<float4*>(&xr2[0]) = *reinterpret_cast<const float4*>(xrow + 128 + tx*4);
                *reinterpret_cast<float4*>(&xr2[4]) = *reinterpret_cast<const float4*>(xrow + 128 + tx*4 + 4);
                #pragma unroll
                for (int kw = 0; kw < KS; kw++) {
                    const float* wrow = &w_s[st][(ci*KK + kh*KS + kw)*WROW + ty*8];
                    ulonglong2 wa = *reinterpret_cast<const ulonglong2*>(wrow);
                    ulonglong2 wb = *reinterpret_cast<const ulonglong2*>(wrow + 4);
                    U64 wp[4] = {wa.x, wa.y, wb.x, wb.y};
                    U64 xp[8];
                    #pragma unroll
                    for (int p = 0; p < 4; p++) PACK2(xp[p], xr1[p + kw*DIL]);
                    #pragma unroll
                    for (int p = 4; p < 8; p++) PACK2(xp[p], xr2[p - 4 + kw*DIL]);
                    #pragma unroll
                    for (int j = 0; j < 4; j++)
                        #pragma unroll
                        for (int p = 0; p < 8; p++)
                            FMA2(acc[j][p], wp[j], xp[p]);
                }
            }
        }
        __syncthreads();
    }
    #pragma unroll
    for (int j = 0; j < 4; j++) {
        float lo[8], hi[8];
        #pragma unroll
        for (int p = 0; p < 8; p++) {
            unsigned a, c; UNPK2(a, c, acc[j][p]);
            lo[p] = __uint_as_float(a); hi[p] = __uint_as_float(c);
        }
        #pragma unroll
        for (int hh2 = 0; hh2 < 2; hh2++) {
            int oc = oc0 + ty*8 + 2*j + hh2;
            const float* src = hh2 ? hi : lo;
            float bi = bias[oc], s = bns[oc], bb2 = bnb[oc];
            float zt[8];
            #pragma unroll
            for (int p = 0; p < 8; p++) zt[p] = s*lrelu01(src[p] + bi) + bb2;
            float* op = &out[((b*128 + oc)*HH + h)*WW + w0];
            *reinterpret_cast<float4*>(op + tx*4)       = make_float4(zt[0], zt[1], zt[2], zt[3]);
            *reinterpret_cast<float4*>(op + 128 + tx*4) = make_float4(zt[4], zt[5], zt[6], zt[7]);
        }
    }
}

// =====================================================================
// Generic NCHW-input mma.sync bf16x3 GEMM: D[128oc][128px] per CTA.
// =====================================================================
template<int KTOT, int NSRC, int ACT>
__global__ __launch_bounds__(256)
void mma_nchw_k(const float* __restrict__ r1, const float* __restrict__ r2,
                const float* __restrict__ r3,
                const __nv_bfloat16* __restrict__ wh, const __nv_bfloat16* __restrict__ wl,
                const float* __restrict__ bias, const float* __restrict__ bns,
                const float* __restrict__ bnb, float* __restrict__ out)
{
    constexpr int NCH = KTOT/32;
    extern __shared__ __align__(16) __nv_bfloat16 sm2[];
    const int gp = blockIdx.x * 128;
    const int b  = gp / HWX, pp = gp - b*HWX;
    const int tid = threadIdx.x;
    const int wid = tid >> 5, lane = tid & 31;
    const int g = lane >> 2, t = lane & 3;
    const int warp_m = wid & 1, warp_n = wid >> 1;
    const int arow = tid >> 1, ahalf = tid & 1;   // A fill (16 bf16 = 2 x uint4)
    const int bp = tid >> 4, bl = tid & 15;       // B fill (ch pair, px lane)

    float acc[4][4][4];
    #pragma unroll
    for (int mt = 0; mt < 4; mt++)
        #pragma unroll
        for (int nt = 0; nt < 4; nt++)
            #pragma unroll
            for (int q = 0; q < 4; q++) acc[mt][nt][q] = 0.f;

    uint4 rah[2], ral[2];
    float rbf[16];
    auto load_chunk = [&](int c) {
        int kc = c*32;
        size_t aoff = (size_t)arow*KTOT + kc + ahalf*16;
        rah[0] = *reinterpret_cast<const uint4*>(wh + aoff);
        rah[1] = *reinterpret_cast<const uint4*>(wh + aoff + 8);
        ral[0] = *reinterpret_cast<const uint4*>(wl + aoff);
        ral[1] = *reinterpret_cast<const uint4*>(wl + aoff + 8);
        const float* src; int chb;
        if (NSRC == 3) { src = (c < 4) ? r1 : (c < 8 ? r2 : r3); chb = (c & 3)*32; }
        else           { src = r1; chb = c*32; }
        const float* s0 = src + ((size_t)(b*128 + chb + 2*bp))*HWX + pp + bl;
        const float* s1 = s0 + HWX;
        #pragma unroll
        for (int j = 0; j < 8; j++) { rbf[j] = s0[16*j]; rbf[8+j] = s1[16*j]; }
    };
    auto store_stage = [&](int st) {
        __nv_bfloat16* base = sm2 + st*4*FM_TILE;
        int off = arow*FM_STR + ahalf*16;
        *reinterpret_cast<uint4*>(base + off)               = rah[0];
        *reinterpret_cast<uint4*>(base + off + 8)           = rah[1];
        *reinterpret_cast<uint4*>(base + FM_TILE + off)     = ral[0];
        *reinterpret_cast<uint4*>(base + FM_TILE + off + 8) = ral[1];
        __nv_bfloat16* Bh = base + 2*FM_TILE;
        __nv_bfloat16* Bl = base + 3*FM_TILE;
        #pragma unroll
        for (int j = 0; j < 8; j++) {
            int px = bl + 16*j;
            float f0 = rbf[j], f1 = rbf[8+j];
            __nv_bfloat16 h0 = __float2bfloat16(f0);
            __nv_bfloat16 h1 = __float2bfloat16(f1);
            __nv_bfloat16 l0 = __float2bfloat16(f0 - __bfloat162float(h0));
            __nv_bfloat16 l1 = __float2bfloat16(f1 - __bfloat162float(h1));
            *reinterpret_cast<uint32_t*>(Bh + px*FM_STR + 2*bp) = pkbf(h0, h1);
            *reinterpret_cast<uint32_t*>(Bl + px*FM_STR + 2*bp) = pkbf(l0, l1);
        }
    };

    load_chunk(0); store_stage(0);
    if (NCH > 1) load_chunk(1);
    __syncthreads();

    for (int ch = 0; ch < NCH; ch++) {
        if (ch + 1 < NCH) store_stage((ch + 1) & 1);
        if (ch + 2 < NCH) load_chunk(ch + 2);
        const __nv_bfloat16* Ah = sm2 + (ch & 1)*4*FM_TILE;
        const __nv_bfloat16* Al = Ah + FM_TILE;
        const __nv_bfloat16* Bh = Ah + 2*FM_TILE;
        const __nv_bfloat16* Bl = Ah + 3*FM_TILE;
        #pragma unroll
        for (int ks = 0; ks < 2; ks++) {
            const int kb = ks*16 + t*2;
            uint32_t ah[4][4], al[4][4];
            #pragma unroll
            for (int mt = 0; mt < 4; mt++) {
                int r0 = (warp_m*64 + mt*16 + g)*FM_STR;
                ah[mt][0] = *reinterpret_cast<const uint32_t*>(Ah + r0 + kb);
                ah[mt][1] = *reinterpret_cast<const uint32_t*>(Ah + r0 + 8*FM_STR + kb);
                ah[mt][2] = *reinterpret_cast<const uint32_t*>(Ah + r0 + kb + 8);
                ah[mt][3] = *reinterpret_cast<const uint32_t*>(Ah + r0 + 8*FM_STR + kb + 8);
                al[mt][0] = *reinterpret_cast<const uint32_t*>(Al + r0 + kb);
                al[mt][1] = *reinterpret_cast<const uint32_t*>(Al + r0 + 8*FM_STR + kb);
                al[mt][2] = *reinterpret_cast<const uint32_t*>(Al + r0 + kb + 8);
                al[mt][3] = *reinterpret_cast<const uint32_t*>(Al + r0 + 8*FM_STR + kb + 8);
            }
            #pragma unroll
            for (int nt = 0; nt < 4; nt++) {
                int c0 = (warp_n*32 + nt*8 + g)*FM_STR;
                uint32_t bh0 = *reinterpret_cast<const uint32_t*>(Bh + c0 + kb);
                uint32_t bh1 = *reinterpret_cast<const uint32_t*>(Bh + c0 + kb + 8);
                uint32_t bl0 = *reinterpret_cast<const uint32_t*>(Bl + c0 + kb);
                uint32_t bl1 = *reinterpret_cast<const uint32_t*>(Bl + c0 + kb + 8);
                #pragma unroll
                for (int mt = 0; mt < 4; mt++) {
                    mma_bf16(acc[mt][nt], ah[mt], bh0, bh1);
                    mma_bf16(acc[mt][nt], al[mt], bh0, bh1);
                    mma_bf16(acc[mt][nt], ah[mt], bl0, bl1);
                }
            }
        }
        __syncthreads();
    }

    #pragma unroll
    for (int mt = 0; mt < 4; mt++) {
        #pragma unroll
        for (int r2q = 0; r2q < 2; r2q++) {
            int oc = warp_m*64 + mt*16 + g + r2q*8;
            float s = bns[oc], bb = bnb[oc], bi = bias[oc];
            float* op = out + ((size_t)(b*128 + oc))*HWX + pp + warp_n*32;
            #pragma unroll
            for (int nt = 0; nt < 4; nt++) {
                float d0 = acc[mt][nt][r2q*2+0], d1 = acc[mt][nt][r2q*2+1];
                float z0, z1;
                if (ACT == 1) { z0 = s*lrelu01(d0 + bi) + bb; z1 = s*lrelu01(d1 + bi) + bb; }
                else {
                    z0 = s*(d0 + bi) + bb; z0 = z0 > 0.f ? z0 : 0.f;
                    z1 = s*(d1 + bi) + bb; z1 = z1 > 0.f ? z1 : 0.f;
                }
                *reinterpret_cast<float2*>(op + nt*8 + t*2) = make_float2(z0, z1);
            }
        }
    }
}

// =====================================================================
// MLP layer 3 (TR): f32x2, writes transposed [pix][C]
// =====================================================================
__global__ __launch_bounds__(256, 2)
void gemm128_tr_k(const float* __restrict__ in, const float* __restrict__ wg,
                  const float* __restrict__ bias, const float* __restrict__ bns,
                  const float* __restrict__ bnb, float* __restrict__ out)
{
    __shared__ __align__(16) float sraw[2*STAGE_F];
    const int gp = blockIdx.x * 128;
    const int b = gp / HWX, pp = gp - b*HWX;
    const int tid = threadIdx.x, ty = tid >> 4, tx = tid & 15;
    const int oc1 = tid >> 2, q1 = tid & 3;
    U64 acc[4][8];
    #pragma unroll
    for (int j = 0; j < 4; j++)
        #pragma unroll
        for (int p = 0; p < 8; p++) acc[j][p] = 0ULL;

    float4 ra, rb, rwa, rwb;
    auto load_chunk = [&](int kc) {
        const float* sp = &in[((b*128 + kc*16 + ty)*HWX) + pp + tx*8];
        ra = *reinterpret_cast<const float4*>(sp);
        rb = *reinterpret_cast<const float4*>(sp + 4);
        rwa = *reinterpret_cast<const float4*>(&wg[oc1*128 + kc*16 + q1*4]);
        rwb = *reinterpret_cast<const float4*>(&wg[(oc1 + 64)*128 + kc*16 + q1*4]);
    };
    auto store_stage = [&](int st) {
        float* in_s = sraw + st*STAGE_F;
        float* w_s  = in_s + 16*ROWS;
        *reinterpret_cast<float4*>(&in_s[ty*ROWS + tx*8])     = ra;
        *reinterpret_cast<float4*>(&in_s[ty*ROWS + tx*8 + 4]) = rb;
        w_s[(q1*4+0)*ROWS + oc1] = rwa.x; w_s[(q1*4+1)*ROWS + oc1] = rwa.y;
        w_s[(q1*4+2)*ROWS + oc1] = rwa.z; w_s[(q1*4+3)*ROWS + oc1] = rwa.w;
        w_s[(q1*4+0)*ROWS + oc1+64] = rwb.x; w_s[(q1*4+1)*ROWS + oc1+64] = rwb.y;
        w_s[(q1*4+2)*ROWS + oc1+64] = rwb.z; w_s[(q1*4+3)*ROWS + oc1+64] = rwb.w;
    };

    load_chunk(0); store_stage(0);
    load_chunk(1);
    __syncthreads();
    for (int kc = 0; kc < 8; kc++) {
        if (kc + 1 < 8) store_stage((kc + 1) & 1);
        if (kc + 2 < 8) load_chunk(kc + 2);
        const float* base = sraw + (kc & 1)*STAGE_F;
        gemm_chunk_f2(base, base + 16*ROWS, ty, tx, acc);
        __syncthreads();
    }

    float* stage = sraw;
    for (int gq = 0; gq < 4; gq++) {
        __syncthreads();
        if ((ty >> 2) == gq) {
            #pragma unroll
            for (int j = 0; j < 4; j++) {
                unsigned a, c;
                float lo[8], hi[8];
                #pragma unroll
                for (int p = 0; p < 8; p++) {
                    UNPK2(a, c, acc[j][p]);
                    lo[p] = __uint_as_float(a); hi[p] = __uint_as_float(c);
                }
                int oc = ty*8 + 2*j;
                int ocl = oc - gq*32;
                float bi0 = bias[oc],   s0 = bns[oc],   b0 = bnb[oc];
                float bi1 = bias[oc+1], s1 = bns[oc+1], b1 = bnb[oc+1];
                #pragma unroll
                for (int p = 0; p < 8; p++) {
                    int col = (p < 4) ? (tx*4 + p) : (64 + tx*4 + p - 4);
                    float z0 = s0*(lo[p] + bi0) + b0;
                    float z1 = s1*(hi[p] + bi1) + b1;
                    stage[ocl*129 + col]     = z0 > 0.f ? z0 : 0.f;
                    stage[(ocl+1)*129 + col] = z1 > 0.f ? z1 : 0.f;
                }
            }
        }
        __syncthreads();
        for (int t2 = tid; t2 < 1024; t2 += 256) {
            int pix = t2 >> 3, c4 = t2 & 7;
            float4 v;
            v.x = stage[(c4*4+0)*129 + pix];
            v.y = stage[(c4*4+1)*129 + pix];
            v.z = stage[(c4*4+2)*129 + pix];
            v.w = stage[(c4*4+3)*129 + pix];
            *reinterpret_cast<float4*>(&out[(size_t)(b*HWX + pp + pix)*128 + gq*32 + c4*4]) = v;
        }
    }
}

// =====================================================================
// resA shortcut add: out += lrelu(c1 @ x + c1_b), K=64 (f32x2)
// =====================================================================
__global__ __launch_bounds__(256, 2)
void resa_add_k(const float* __restrict__ x,
                const float* __restrict__ c1w, const float* __restrict__ c1b,
                float* __restrict__ out)
{
    __shared__ __align__(16) float sraw[2*STAGE_F];
    const int gp = blockIdx.x * 128;
    const int b = gp / HWX, pp = gp - b*HWX;
    const int tid = threadIdx.x, ty = tid >> 4, tx = tid & 15;
    const int oc1 = tid >> 2, q1 = tid & 3;
    U64 acc[4][8];
    #pragma unroll
    for (int j = 0; j < 4; j++)
        #pragma unroll
        for (int p = 0; p < 8; p++) acc[j][p] = 0ULL;

    float4 ra, rb, rwa, rwb;
    auto load_c = [&](int kc) {
        const float* sp = &x[((b*64 + kc*16 + ty)*HWX) + pp + tx*8];
        ra = *reinterpret_cast<const float4*>(sp);
        rb = *reinterpret_cast<const float4*>(sp + 4);
        rwa = *reinterpret_cast<const float4*>(&c1w[oc1*64 + kc*16 + q1*4]);
        rwb = *reinterpret_cast<const float4*>(&c1w[(oc1 + 64)*64 + kc*16 + q1*4]);
    };
    auto store_stage = [&](int st) {
        float* in_s = sraw + st*STAGE_F;
        float* w_s  = in_s + 16*ROWS;
        *reinterpret_cast<float4*>(&in_s[ty*ROWS + tx*8])     = ra;
        *reinterpret_cast<float4*>(&in_s[ty*ROWS + tx*8 + 4]) = rb;
        w_s[(q1*4+0)*ROWS + oc1] = rwa.x; w_s[(q1*4+1)*ROWS + oc1] = rwa.y;
        w_s[(q1*4+2)*ROWS + oc1] = rwa.z; w_s[(q1*4+3)*ROWS + oc1] = rwa.w;
        w_s[(q1*4+0)*ROWS + oc1+64] = rwb.x; w_s[(q1*4+1)*ROWS + oc1+64] = rwb.y;
        w_s[(q1*4+2)*ROWS + oc1+64] = rwb.z; w_s[(q1*4+3)*ROWS + oc1+64] = rwb.w;
    };

    load_c(0); store_stage(0);
    load_c(1);
    __syncthreads();
    for (int kc = 0; kc < 4; kc++) {
        if (kc + 1 < 4) store_stage((kc + 1) & 1);
        if (kc + 2 < 4) load_c(kc + 2);
        const float* base = sraw + (kc & 1)*STAGE_F;
        gemm_chunk_f2(base, base + 16*ROWS, ty, tx, acc);
        __syncthreads();
    }

    #pragma unroll
    for (int j = 0; j < 4; j++) {
        float lo[8], hi[8];
        #pragma unroll
        for (int p = 0; p < 8; p++) {
            unsigned a, c; UNPK2(a, c, acc[j][p]);
            lo[p] = __uint_as_float(a); hi[p] = __uint_as_float(c);
        }
        #pragma unroll
        for (int hh2 = 0; hh2 < 2; hh2++) {
            int oc = ty*8 + 2*j + hh2;
            const float* m = hh2 ? hi : lo;
            float b1 = c1b[oc];
            float* op = &out[((b*128 + oc)*HWX) + pp];
            float4 o0 = *reinterpret_cast<const float4*>(op + tx*4);
            float4 o1 = *reinterpret_cast<const float4*>(op + 64 + tx*4);
            o0.x += lrelu01(m[0] + b1); o0.y += lrelu01(m[1] + b1);
            o0.z += lrelu01(m[2] + b1); o0.w += lrelu01(m[3] + b1);
            o1.x += lrelu01(m[4] + b1); o1.y += lrelu01(m[5] + b1);
            o1.z += lrelu01(m[6] + b1); o1.w += lrelu01(m[7] + b1);
            *reinterpret_cast<float4*>(op + tx*4)      = o0;
            *reinterpret_cast<float4*>(op + 64 + tx*4) = o1;
        }
    }
}

// =====================================================================
// WeightNet
// =====================================================================
__global__ __launch_bounds__(256)
void weightnet_k(const float* __restrict__ xyz,
                 const float* __restrict__ w1w, const float* __restrict__ w1b,
                 const float* __restrict__ w2w, const float* __restrict__ w2b,
                 const float* __restrict__ w3w, const float* __restrict__ w3b,
                 const float* __restrict__ s1, const float* __restrict__ b1,
                 const float* __restrict__ s2, const float* __restrict__ b2,
                 const float* __restrict__ s3, const float* __restrict__ b3,
                 float* __restrict__ out)
{
    int g = blockIdx.x*256 + threadIdx.x;
    int pix = g & (NP2 - 1);
    int rest = g >> 14;
    int k = rest % 25, b = rest / 25;
    int h2 = pix >> 9, w2 = pix & 511;
    int hi = 2*h2 - 2 + k/5, wi = 2*w2 - 2 + (k % 5);
    bool inb = ((unsigned)hi < (unsigned)HH) && ((unsigned)wi < (unsigned)WW);
    float gv[3];
    #pragma unroll
    for (int c = 0; c < 3; c++) {
        float ctr = xyz[(b*3 + c)*HWX + (2*h2)*WW + 2*w2];
        float nb  = inb ? xyz[(b*3 + c)*HWX + hi*WW + wi] : 0.f;
        gv[c] = nb - ctr;
    }
    float a1[8];
    #pragma unroll
    for (int j = 0; j < 8; j++) {
        float z = w1b[j];
        #pragma unroll
        for (int c = 0; c < 3; c++) z += w1w[j*3 + c]*gv[c];
        z = s1[j]*z + b1[j];
        a1[j] = z > 0.f ? z : 0.f;
    }
    float a2[8];
    #pragma unroll
    for (int j = 0; j < 8; j++) {
        float z = w2b[j];
        #pragma unroll
        for (int i = 0; i < 8; i++) z += w2w[j*8 + i]*a1[i];
        z = s2[j]*z + b2[j];
        a2[j] = z > 0.f ? z : 0.f;
    }
    float o[16];
    #pragma unroll
    for (int n = 0; n < 16; n++) {
        float z = w3b[n];
        #pragma unroll
        for (int i = 0; i < 8; i++) z += w3w[n*8 + i]*a2[i];
        z = s3[n]*z + b3[n];
        o[n] = z > 0.f ? z : 0.f;
    }
    size_t base = (((size_t)(b*NP2 + pix))*25 + k)*16;
    #pragma unroll
    for (int q = 0; q < 4; q++)
        *reinterpret_cast<float4*>(&out[base + q*4]) =
            make_float4(o[q*4], o[q*4+1], o[q*4+2], o[q*4+3]);
}

// =====================================================================
// Einsum -> writes y directly as bf16 hi/lo (pixel-major [px][2048])
// =====================================================================
__global__ __launch_bounds__(128)
void einsum_k(const float* __restrict__ hT, const float* __restrict__ wn,
              __nv_bfloat16* __restrict__ yh, __nv_bfloat16* __restrict__ yl)
{
    __shared__ __align__(16) float u_s[2][25][128];
    __shared__ float wn_s[2][400];
    const int gpix = blockIdx.x*2;
    const int b = gpix / NP2;
    const int tid = threadIdx.x;

    for (int i = tid; i < 800; i += 128) {
        int pl = i / 400, r = i - pl*400;
        wn_s[pl][r] = wn[(size_t)(gpix + pl)*400 + r];
    }
    for (int idx = 0; idx < 50; idx++) {
        int pl = idx / 25, k = idx - pl*25;
        int pp = (gpix + pl) - b*NP2;
        int h2 = pp >> 9, w2 = pp & 511;
        int hi = 2*h2 - 2 + k/5, wi = 2*w2 - 2 + (k % 5);
        float v = 0.f;
        if ((unsigned)hi < (unsigned)HH && (unsigned)wi < (unsigned)WW)
            v = hT[((size_t)(b*HH + hi)*WW + wi)*128 + tid];
        u_s[pl][k][tid] = v;
    }
    __syncthreads();

    const int s = tid & 63, pl = tid >> 6;
    const int cg = s & 15, ng = s >> 4;
    float acc[8][4];
    #pragma unroll
    for (int i = 0; i < 8; i++)
        #pragma unroll
        for (int n = 0; n < 4; n++) acc[i][n] = 0.f;

    #pragma unroll
    for (int k = 0; k < 25; k++) {
        float4 ua = *reinterpret_cast<const float4*>(&u_s[pl][k][cg*4]);
        float4 ub = *reinterpret_cast<const float4*>(&u_s[pl][k][64 + cg*4]);
        float u[8] = {ua.x, ua.y, ua.z, ua.w, ub.x, ub.y, ub.z, ub.w};
        float4 wv = *reinterpret_cast<const float4*>(&wn_s[pl][k*16 + ng*4]);
        float wvv[4] = {wv.x, wv.y, wv.z, wv.w};
        #pragma unroll
        for (int i = 0; i < 8; i++)
            #pragma unroll
            for (int n = 0; n < 4; n++) acc[i][n] += u[i]*wvv[n];
    }
    size_t base = (size_t)(gpix + pl)*2048;
    #pragma unroll
    for (int i = 0; i < 8; i++) {
        int c = (i < 4) ? (cg*4 + i) : (64 + cg*4 + i - 4);
        __nv_bfloat16 h[4], l[4];
        #pragma unroll
        for (int n = 0; n < 4; n++) {
            h[n] = __float2bfloat16(acc[i][n]);
            l[n] = __float2bfloat16(acc[i][n] - __bfloat162float(h[n]));
        }
        *reinterpret_cast<uint2*>(&yh[base + c*16 + ng*4]) = make_uint2(pkbf(h[0],h[1]), pkbf(h[2],h[3]));
        *reinterpret_cast<uint2*>(&yl[base + c*16 + ng*4]) = make_uint2(pkbf(l[0],l[1]), pkbf(l[2],l[3]));
    }
}

// =====================================================================
// Final GEMM (mma.sync bf16x3) with pure-copy fills (precomputed bf16 inputs)
// =====================================================================
__global__ __launch_bounds__(256)
void final_mma_k(const __nv_bfloat16* __restrict__ yh, const __nv_bfloat16* __restrict__ yl,
                 const __nv_bfloat16* __restrict__ lwh, const __nv_bfloat16* __restrict__ lwl,
                 const float* __restrict__ lbias, const float* __restrict__ bns,
                 const float* __restrict__ bnb, float* __restrict__ out)
{
    extern __shared__ __align__(16) __nv_bfloat16 sm2[];
    const int gp = blockIdx.x * 128;
    const int b  = gp / NP2, pp = gp - b*NP2;
    const int tid = threadIdx.x;
    const int wid = tid >> 5, lane = tid & 31;
    const int g = lane >> 2, t = lane & 3;
    const int warp_m = wid & 1, warp_n = wid >> 1;
    const int row = tid >> 1, half = tid & 1;

    float acc[4][4][4];
    #pragma unroll
    for (int mt = 0; mt < 4; mt++)
        #pragma unroll
        for (int nt = 0; nt < 4; nt++)
            #pragma unroll
            for (int q = 0; q < 4; q++) acc[mt][nt][q] = 0.f;

    uint4 rah[2], ral[2], rbh[2], rbl[2];
    auto load_chunk = [&](int ch) {
        int kc = ch*32;
        size_t aoff = (size_t)row*2048 + kc + half*16;
        size_t boff = (size_t)(gp + row)*2048 + kc + half*16;
        rah[0] = *reinterpret_cast<const uint4*>(lwh + aoff);
        rah[1] = *reinterpret_cast<const uint4*>(lwh + aoff + 8);
        ral[0] = *reinterpret_cast<const uint4*>(lwl + aoff);
        ral[1] = *reinterpret_cast<const uint4*>(lwl + aoff + 8);
        rbh[0] = *reinterpret_cast<const uint4*>(yh + boff);
        rbh[1] = *reinterpret_cast<const uint4*>(yh + boff + 8);
        rbl[0] = *reinterpret_cast<const uint4*>(yl + boff);
        rbl[1] = *reinterpret_cast<const uint4*>(yl + boff + 8);
    };
    auto store_stage = [&](int st) {
        __nv_bfloat16* base = sm2 + st*4*FM_TILE;
        int off = row*FM_STR + half*16;
        *reinterpret_cast<uint4*>(base + off)                   = rah[0];
        *reinterpret_cast<uint4*>(base + off + 8)               = rah[1];
        *reinterpret_cast<uint4*>(base + FM_TILE + off)         = ral[0];
        *reinterpret_cast<uint4*>(base + FM_TILE + off + 8)     = ral[1];
        *reinterpret_cast<uint4*>(base + 2*FM_TILE + off)       = rbh[0];
        *reinterpret_cast<uint4*>(base + 2*FM_TILE + off + 8)   = rbh[1];
        *reinterpret_cast<uint4*>(base + 3*FM_TILE + off)       = rbl[0];
        *reinterpret_cast<uint4*>(base + 3*FM_TILE + off + 8)   = rbl[1];
    };

    load_chunk(0); store_stage(0);
    load_chunk(1);
    __syncthreads();

    for (int ch = 0; ch < 64; ch++) {
        if (ch + 1 < 64) store_stage((ch + 1) & 1);
        if (ch + 2 < 64) load_chunk(ch + 2);
        const __nv_bfloat16* Ah = sm2 + (ch & 1)*4*FM_TILE;
        const __nv_bfloat16* Al = Ah + FM_TILE;
        const __nv_bfloat16* Bh = Ah + 2*FM_TILE;
        const __nv_bfloat16* Bl = Ah + 3*FM_TILE;
        #pragma unroll
        for (int ks = 0; ks < 2; ks++) {
            const int kb = ks*16 + t*2;
            uint32_t ah[4][4], al[4][4];
            #pragma unroll
            for (int mt = 0; mt < 4; mt++) {
                int r0 = (warp_m*64 + mt*16 + g)*FM_STR;
                ah[mt][0] = *reinterpret_cast<const uint32_t*>(Ah + r0 + kb);
                ah[mt][1] = *reinterpret_cast<const uint32_t*>(Ah + r0 + 8*FM_STR + kb);
                ah[mt][2] = *reinterpret_cast<const uint32_t*>(Ah + r0 + kb + 8);
                ah[mt][3] = *reinterpret_cast<const uint32_t*>(Ah + r0 + 8*FM_STR + kb + 8);
                al[mt][0] = *reinterpret_cast<const uint32_t*>(Al + r0 + kb);
                al[mt][1] = *reinterpret_cast<const uint32_t*>(Al + r0 + 8*FM_STR + kb);
                al[mt][2] = *reinterpret_cast<const uint32_t*>(Al + r0 + kb + 8);
                al[mt][3] = *reinterpret_cast<const uint32_t*>(Al + r0 + 8*FM_STR + kb + 8);
            }
            #pragma unroll
            for (int nt = 0; nt < 4; nt++) {
                int c0 = (warp_n*32 + nt*8 + g)*FM_STR;
                uint32_t bh0 = *reinterpret_cast<const uint32_t*>(Bh + c0 + kb);
                uint32_t bh1 = *reinterpret_cast<const uint32_t*>(Bh + c0 + kb + 8);
                uint32_t bl0 = *reinterpret_cast<const uint32_t*>(Bl + c0 + kb);
                uint32_t bl1 = *reinterpret_cast<const uint32_t*>(Bl + c0 + kb + 8);
                #pragma unroll
                for (int mt = 0; mt < 4; mt++) {
                    mma_bf16(acc[mt][nt], ah[mt], bh0, bh1);
                    mma_bf16(acc[mt][nt], al[mt], bh0, bh1);
                    mma_bf16(acc[mt][nt], ah[mt], bl0, bl1);
                }
            }
        }
        __syncthreads();
    }

    #pragma unroll
    for (int mt = 0; mt < 4; mt++) {
        #pragma unroll
        for (int r2 = 0; r2 < 2; r2++) {
            int oc = warp_m*64 + mt*16 + g + r2*8;
            float s = bns[oc], bb = bnb[oc], bi = lbias[oc];
            float* op = out + ((size_t)(b*128 + oc))*NP2 + pp + warp_n*32;
            #pragma unroll
            for (int nt = 0; nt < 4; nt++) {
                float z0 = s*(acc[mt][nt][r2*2+0] + bi) + bb;
                float z1 = s*(acc[mt][nt][r2*2+1] + bi) + bb;
                float2 v;
                v.x = z0 > 0.f ? z0 : 0.f;
                v.y = z1 > 0.f ? z1 : 0.f;
                *reinterpret_cast<float2*>(op + nt*8 + t*2) = v;
            }
        }
    }
}

// =====================================================================
// host launcher
// =====================================================================
extern "C" void kernel_launch(void* const* d_in, const int* in_sizes, int n_in,
                              void* d_out, int out_size)
{
    const float* x      = (const float*)d_in[0];
    const float* xyz    = (const float*)d_in[1];
    const float* c1_w   = (const float*)d_in[2];
    const float* c1_b   = (const float*)d_in[3];
    const float* c2_w   = (const float*)d_in[4];
    const float* c2_b   = (const float*)d_in[5];
    const float* c3_w   = (const float*)d_in[6];
    const float* c3_b   = (const float*)d_in[7];
    const float* c4_w   = (const float*)d_in[8];
    const float* c4_b   = (const float*)d_in[9];
    const float* c5_w   = (const float*)d_in[10];
    const float* c5_b   = (const float*)d_in[11];
    const float* rbn_s  = (const float*)d_in[12];
    const float* rbn_b  = (const float*)d_in[13];
    const float* p_w    = (const float*)d_in[14];
    const float* p_b    = (const float*)d_in[15];
    const float* pbn_s  = (const float*)d_in[16];
    const float* pbn_b  = (const float*)d_in[17];
    const float* lin_w  = (const float*)d_in[18];
    const float* lin_b  = (const float*)d_in[19];
    const float* w1_w   = (const float*)d_in[20];
    const float* w1_b   = (const float*)d_in[21];
    const float* w2_w   = (const float*)d_in[22];
    const float* w2_b   = (const float*)d_in[23];
    const float* w3_w   = (const float*)d_in[24];
    const float* w3_b   = (const float*)d_in[25];
    const float* wbn1_s = (const float*)d_in[26];
    const float* wbn1_b = (const float*)d_in[27];
    const float* wbn2_s = (const float*)d_in[28];
    const float* wbn2_b = (const float*)d_in[29];
    const float* wbn3_s = (const float*)d_in[30];
    const float* wbn3_b = (const float*)d_in[31];

    float* outp = (float*)d_out;
    float* resB = outp;                 // [B,128,H2,W2]
    float* resA = outp + RESB_ELEMS;    // [B,128,H,W]

    float *A1, *A2, *A3, *B1, *B2, *HT, *WN;
    __nv_bfloat16 *YH, *YL, *WHp, *WLp;
    cudaGetSymbolAddress((void**)&A1, g_resA1);
    cudaGetSymbolAddress((void**)&A2, g_resA2);
    cudaGetSymbolAddress((void**)&A3, g_resA3);
    cudaGetSymbolAddress((void**)&B1, g_buf1);
    cudaGetSymbolAddress((void**)&B2, g_buf2);
    cudaGetSymbolAddress((void**)&HT, g_hT);
    cudaGetSymbolAddress((void**)&WN, g_wn);
    cudaGetSymbolAddress((void**)&YH, g_yh);
    cudaGetSymbolAddress((void**)&YL, g_yl);
    cudaGetSymbolAddress((void**)&WHp, g_wh);
    cudaGetSymbolAddress((void**)&WLp, g_wl);

    cudaFuncSetAttribute(final_mma_k, cudaFuncAttributeMaxDynamicSharedMemorySize, FM_SMEM);
    cudaFuncSetAttribute(mma_nchw_k<384,3,1>, cudaFuncAttributeMaxDynamicSharedMemorySize, FM_SMEM);
    cudaFuncSetAttribute(mma_nchw_k<128,1,0>, cudaFuncAttributeMaxDynamicSharedMemorySize, FM_SMEM);

    // weight precompute (bf16 hi/lo)
    prep_w_k<<<(WTOTAL + 255)/256, 256>>>(lin_w, c5_w, p_w, WHp, WLp);

    dim3 cgrid(8, 64, 2);
    conv_f2_k<64, 3, 1, 1, 2><<<cgrid, 256>>>(x,  c2_w, c2_b, rbn_s,       rbn_b,       A1);
    conv_f2_k<128,3, 2, 2, 2><<<cgrid, 256>>>(A1, c3_w, c3_b, rbn_s + 128, rbn_b + 128, A2);
    conv_f2_k<128,2, 2, 1, 4><<<cgrid, 256>>>(A2, c4_w, c4_b, rbn_s + 256, rbn_b + 256, A3);
    // resA main via mma (K=384, lrelu+bn)
    mma_nchw_k<384,3,1><<<BB*HWX/128, 256, FM_SMEM>>>(A1, A2, A3,
        WHp + WOFF_C5, WLp + WOFF_C5, c5_b, rbn_s + 384, rbn_b + 384, resA);
    resa_add_k<<<BB*HWX/128, 256>>>(x, c1_w, c1_b, resA);
    // MLP layers 1,2 via mma (K=128, relu(bn))
    mma_nchw_k<128,1,0><<<BB*HWX/128, 256, FM_SMEM>>>(resA, resA, resA,
        WHp + WOFF_P, WLp + WOFF_P, p_b, pbn_s, pbn_b, B1);
    mma_nchw_k<128,1,0><<<BB*HWX/128, 256, FM_SMEM>>>(B1, B1, B1,
        WHp + WOFF_P + 16384, WLp + WOFF_P + 16384, p_b + 128, pbn_s + 128, pbn_b + 128, B2);
    // MLP layer 3: f32, transposed output for unfold gather
    gemm128_tr_k<<<BB*HWX/128, 256>>>(B2, p_w + 32768, p_b + 256, pbn_s + 256, pbn_b + 256, HT);
    // WeightNet
    weightnet_k<<<(BB*25*NP2)/256, 256>>>(xyz, w1_w, w1_b, w2_w, w2_b, w3_w, w3_b,
                                          wbn1_s, wbn1_b, wbn2_s, wbn2_b, wbn3_s, wbn3_b, WN);
    // einsum -> y (bf16 hi/lo, pixel-major)
    einsum_k<<<BB*NP2/2, 128>>>(HT, WN, YH, YL);
    // final GEMM (copy-fill mma)
    final_mma_k<<<BB*NP2/128, 256, FM_SMEM>>>(YH, YL, WHp, WLp,
                                              lin_b, pbn_s + 384, pbn_b + 384, resB);
}

// round 16
// speedup vs baseline: 1.5590x; 1.1546x over previous
#include <cuda_runtime.h>
#include <cuda_bf16.h>
#include <cstddef>
#include <cstdint>

// ---------------- problem constants ----------------
#define BB   2
#define CINX 64
#define CH   128
#define HH   64
#define WW   1024
#define HWX  (HH*WW)          // 65536
#define H2X  32
#define W2X  512
#define NP2  (H2X*W2X)        // 16384
#define RESB_ELEMS (BB*CH*NP2)   // 4194304

typedef unsigned long long U64;

// f32x2 packed FMA (Blackwell)
#define FMA2(c, a, b) asm("fma.rn.f32x2 %0, %1, %2, %0;" : "+l"(c) : "l"(a), "l"(b))
#define PACK2(d, x)   asm("mov.b64 %0, {%1, %1};" : "=l"(d) : "r"(__float_as_uint(x)))
#define UNPK2(lo, hi, d) asm("mov.b64 {%0, %1}, %2;" : "=r"(lo), "=r"(hi) : "l"(d))

#define ROWS 132
#define STAGE_F (16*ROWS*2)

// mma tile geometry
#define FM_STR    40                      // bf16 row stride (20 words -> CF frags)
#define FM_TILE   (128*FM_STR)            // 5120 bf16 per tile
#define FM_SMEM   (2*4*FM_TILE*2)         // 81920 bytes (2 stages x 4 tiles)

// precomputed weight offsets (bf16 elements)
#define WOFF_LW   0
#define WOFF_C5   262144                  // +128*2048
#define WOFF_P    311296                  // +128*384
#define WOFF_C2   360448                  // +3*128*128
#define WOFF_C3   434176                  // +128*576
#define WOFF_C4   581632                  // +128*1152
#define WTOTAL    647168                  // +128*512

// ---------------- scratch ----------------
__device__ float g_resA1[BB*CH*HWX];
__device__ float g_resA2[BB*CH*HWX];
__device__ float g_resA3[BB*CH*HWX];
__device__ float g_buf1 [BB*CH*HWX];
__device__ float g_buf2 [BB*CH*HWX];
__device__ float g_hT   [BB*HWX*CH];
__device__ float g_wn   [BB*NP2*25*16];
__device__ __nv_bfloat16 g_yh[(size_t)BB*NP2*2048];
__device__ __nv_bfloat16 g_yl[(size_t)BB*NP2*2048];
__device__ __nv_bfloat16 g_wh[WTOTAL];
__device__ __nv_bfloat16 g_wl[WTOTAL];

__device__ __forceinline__ float lrelu01(float z) { return z > 0.f ? z : 0.01f*z; }
static __device__ __forceinline__ uint32_t pkbf(__nv_bfloat16 a, __nv_bfloat16 b) {
    return (uint32_t)__bfloat16_as_ushort(a) | ((uint32_t)__bfloat16_as_ushort(b) << 16);
}
static __device__ __forceinline__ void mma_bf16(float d[4], const uint32_t a[4],
                                                uint32_t b0, uint32_t b1) {
    asm volatile(
        "mma.sync.aligned.m16n8k16.row.col.f32.bf16.bf16.f32 "
        "{%0,%1,%2,%3}, {%4,%5,%6,%7}, {%8,%9}, {%0,%1,%2,%3};\n"
        : "+f"(d[0]), "+f"(d[1]), "+f"(d[2]), "+f"(d[3])
        : "r"(a[0]), "r"(a[1]), "r"(a[2]), "r"(a[3]), "r"(b0), "r"(b1));
}

// =====================================================================
// prep: fp32 weights -> bf16 hi/lo (lw | c5w | p_w | c2w | c3w | c4w)
// =====================================================================
__global__ __launch_bounds__(256)
void prep_w_k(const float* __restrict__ lw, const float* __restrict__ c5w,
              const float* __restrict__ pw, const float* __restrict__ c2w,
              const float* __restrict__ c3w, const float* __restrict__ c4w,
              __nv_bfloat16* __restrict__ wh, __nv_bfloat16* __restrict__ wl)
{
    int idx = blockIdx.x*256 + threadIdx.x;
    if (idx >= WTOTAL) return;
    float v;
    if (idx < WOFF_C5)      v = lw[idx];
    else if (idx < WOFF_P)  v = c5w[idx - WOFF_C5];
    else if (idx < WOFF_C2) v = pw[idx - WOFF_P];
    else if (idx < WOFF_C3) v = c2w[idx - WOFF_C2];
    else if (idx < WOFF_C4) v = c3w[idx - WOFF_C3];
    else                    v = c4w[idx - WOFF_C4];
    __nv_bfloat16 h = __float2bfloat16(v);
    wh[idx] = h;
    wl[idx] = __float2bfloat16(v - __bfloat162float(h));
}

// =====================================================================
// mma fragment compute: shared by all HMMA kernels. acc += A*B (bf16x3).
// =====================================================================
static __device__ __forceinline__ void mma_tiles(const __nv_bfloat16* Ah,
                                                 int warp_m, int warp_n,
                                                 int g, int t,
                                                 float acc[4][4][4])
{
    const __nv_bfloat16* Al = Ah + FM_TILE;
    const __nv_bfloat16* Bh = Ah + 2*FM_TILE;
    const __nv_bfloat16* Bl = Ah + 3*FM_TILE;
    #pragma unroll
    for (int ks = 0; ks < 2; ks++) {
        const int kb = ks*16 + t*2;
        uint32_t ah[4][4], al[4][4];
        #pragma unroll
        for (int mt = 0; mt < 4; mt++) {
            int r0 = (warp_m*64 + mt*16 + g)*FM_STR;
            ah[mt][0] = *reinterpret_cast<const uint32_t*>(Ah + r0 + kb);
            ah[mt][1] = *reinterpret_cast<const uint32_t*>(Ah + r0 + 8*FM_STR + kb);
            ah[mt][2] = *reinterpret_cast<const uint32_t*>(Ah + r0 + kb + 8);
            ah[mt][3] = *reinterpret_cast<const uint32_t*>(Ah + r0 + 8*FM_STR + kb + 8);
            al[mt][0] = *reinterpret_cast<const uint32_t*>(Al + r0 + kb);
            al[mt][1] = *reinterpret_cast<const uint32_t*>(Al + r0 + 8*FM_STR + kb);
            al[mt][2] = *reinterpret_cast<const uint32_t*>(Al + r0 + kb + 8);
            al[mt][3] = *reinterpret_cast<const uint32_t*>(Al + r0 + 8*FM_STR + kb + 8);
        }
        #pragma unroll
        for (int nt = 0; nt < 4; nt++) {
            int c0 = (warp_n*32 + nt*8 + g)*FM_STR;
            uint32_t bh0 = *reinterpret_cast<const uint32_t*>(Bh + c0 + kb);
            uint32_t bh1 = *reinterpret_cast<const uint32_t*>(Bh + c0 + kb + 8);
            uint32_t bl0 = *reinterpret_cast<const uint32_t*>(Bl + c0 + kb);
            uint32_t bl1 = *reinterpret_cast<const uint32_t*>(Bl + c0 + kb + 8);
            #pragma unroll
            for (int mt = 0; mt < 4; mt++) {
                mma_bf16(acc[mt][nt], ah[mt], bh0, bh1);
                mma_bf16(acc[mt][nt], al[mt], bh0, bh1);
                mma_bf16(acc[mt][nt], ah[mt], bl0, bl1);
            }
        }
    }
}

// =====================================================================
// Conv via mma.sync bf16x3 (implicit im2col). D[128oc][128px] per CTA,
// one output row h. K = CIN*KS*KS, chunks of 32. Epilogue bn(lrelu(.)).
// =====================================================================
template<int CIN, int KS, int DIL, int PAD>
__global__ __launch_bounds__(256)
void mma_conv_k(const float* __restrict__ in,
                const __nv_bfloat16* __restrict__ wh, const __nv_bfloat16* __restrict__ wl,
                const float* __restrict__ bias, const float* __restrict__ bns,
                const float* __restrict__ bnb, float* __restrict__ out)
{
    constexpr int KK = KS*KS, KTOT = CIN*KK, NCH = KTOT/32;
    extern __shared__ __align__(16) __nv_bfloat16 sm2[];
    const int w0 = blockIdx.x * 128;
    const int h  = blockIdx.y;
    const int b  = blockIdx.z;
    const int tid = threadIdx.x;
    const int wid = tid >> 5, lane = tid & 31;
    const int g = lane >> 2, t = lane & 3;
    const int warp_m = wid & 1, warp_n = wid >> 1;
    const int arow = tid >> 1, ahalf = tid & 1;
    const int bp = tid >> 4, bl = tid & 15;

    float acc[4][4][4];
    #pragma unroll
    for (int mt = 0; mt < 4; mt++)
        #pragma unroll
        for (int nt = 0; nt < 4; nt++)
            #pragma unroll
            for (int q = 0; q < 4; q++) acc[mt][nt][q] = 0.f;

    uint4 rah[2], ral[2];
    float rbf[16];
    auto load_chunk = [&](int c) {
        int kc = c*32;
        size_t aoff = (size_t)arow*KTOT + kc + ahalf*16;
        rah[0] = *reinterpret_cast<const uint4*>(wh + aoff);
        rah[1] = *reinterpret_cast<const uint4*>(wh + aoff + 8);
        ral[0] = *reinterpret_cast<const uint4*>(wl + aoff);
        ral[1] = *reinterpret_cast<const uint4*>(wl + aoff + 8);
        #pragma unroll
        for (int e = 0; e < 2; e++) {
            int k  = kc + 2*bp + e;
            int ci = k / KK;
            int r  = k - ci*KK;
            int kh = r / KS, kw = r - kh*KS;
            int gy = h - PAD + kh*DIL;
            bool yok = (unsigned)gy < (unsigned)HH;
            const float* rowp = in + ((size_t)(b*CIN + ci)*HH + gy)*WW;
            int gx0 = w0 - PAD + kw*DIL + bl;
            #pragma unroll
            for (int j = 0; j < 8; j++) {
                int gx = gx0 + 16*j;
                rbf[e*8 + j] = (yok && (unsigned)gx < (unsigned)WW) ? rowp[gx] : 0.f;
            }
        }
    };
    auto store_stage = [&](int st) {
        __nv_bfloat16* base = sm2 + st*4*FM_TILE;
        int off = arow*FM_STR + ahalf*16;
        *reinterpret_cast<uint4*>(base + off)               = rah[0];
        *reinterpret_cast<uint4*>(base + off + 8)           = rah[1];
        *reinterpret_cast<uint4*>(base + FM_TILE + off)     = ral[0];
        *reinterpret_cast<uint4*>(base + FM_TILE + off + 8) = ral[1];
        __nv_bfloat16* Bh = base + 2*FM_TILE;
        __nv_bfloat16* Bl = base + 3*FM_TILE;
        #pragma unroll
        for (int j = 0; j < 8; j++) {
            int px = bl + 16*j;
            float f0 = rbf[j], f1 = rbf[8+j];
            __nv_bfloat16 h0 = __float2bfloat16(f0);
            __nv_bfloat16 h1 = __float2bfloat16(f1);
            __nv_bfloat16 l0 = __float2bfloat16(f0 - __bfloat162float(h0));
            __nv_bfloat16 l1 = __float2bfloat16(f1 - __bfloat162float(h1));
            *reinterpret_cast<uint32_t*>(Bh + px*FM_STR + 2*bp) = pkbf(h0, h1);
            *reinterpret_cast<uint32_t*>(Bl + px*FM_STR + 2*bp) = pkbf(l0, l1);
        }
    };

    load_chunk(0); store_stage(0);
    if (NCH > 1) load_chunk(1);
    __syncthreads();

    for (int ch = 0; ch < NCH; ch++) {
        if (ch + 1 < NCH) store_stage((ch + 1) & 1);
        if (ch + 2 < NCH) load_chunk(ch + 2);
        mma_tiles(sm2 + (ch & 1)*4*FM_TILE, warp_m, warp_n, g, t, acc);
        __syncthreads();
    }

    #pragma unroll
    for (int mt = 0; mt < 4; mt++) {
        #pragma unroll
        for (int r2q = 0; r2q < 2; r2q++) {
            int oc = warp_m*64 + mt*16 + g + r2q*8;
            float s = bns[oc], bb = bnb[oc], bi = bias[oc];
            float* op = out + ((size_t)(b*128 + oc)*HH + h)*WW + w0 + warp_n*32;
            #pragma unroll
            for (int nt = 0; nt < 4; nt++) {
                float z0 = s*lrelu01(acc[mt][nt][r2q*2+0] + bi) + bb;
                float z1 = s*lrelu01(acc[mt][nt][r2q*2+1] + bi) + bb;
                *reinterpret_cast<float2*>(op + nt*8 + t*2) = make_float2(z0, z1);
            }
        }
    }
}

// =====================================================================
// Generic NCHW-input mma.sync bf16x3 GEMM: D[128oc][128px] per CTA.
// =====================================================================
template<int KTOT, int NSRC, int ACT>
__global__ __launch_bounds__(256)
void mma_nchw_k(const float* __restrict__ r1, const float* __restrict__ r2,
                const float* __restrict__ r3,
                const __nv_bfloat16* __restrict__ wh, const __nv_bfloat16* __restrict__ wl,
                const float* __restrict__ bias, const float* __restrict__ bns,
                const float* __restrict__ bnb, float* __restrict__ out)
{
    constexpr int NCH = KTOT/32;
    extern __shared__ __align__(16) __nv_bfloat16 sm2[];
    const int gp = blockIdx.x * 128;
    const int b  = gp / HWX, pp = gp - b*HWX;
    const int tid = threadIdx.x;
    const int wid = tid >> 5, lane = tid & 31;
    const int g = lane >> 2, t = lane & 3;
    const int warp_m = wid & 1, warp_n = wid >> 1;
    const int arow = tid >> 1, ahalf = tid & 1;
    const int bp = tid >> 4, bl = tid & 15;

    float acc[4][4][4];
    #pragma unroll
    for (int mt = 0; mt < 4; mt++)
        #pragma unroll
        for (int nt = 0; nt < 4; nt++)
            #pragma unroll
            for (int q = 0; q < 4; q++) acc[mt][nt][q] = 0.f;

    uint4 rah[2], ral[2];
    float rbf[16];
    auto load_chunk = [&](int c) {
        int kc = c*32;
        size_t aoff = (size_t)arow*KTOT + kc + ahalf*16;
        rah[0] = *reinterpret_cast<const uint4*>(wh + aoff);
        rah[1] = *reinterpret_cast<const uint4*>(wh + aoff + 8);
        ral[0] = *reinterpret_cast<const uint4*>(wl + aoff);
        ral[1] = *reinterpret_cast<const uint4*>(wl + aoff + 8);
        const float* src; int chb;
        if (NSRC == 3) { src = (c < 4) ? r1 : (c < 8 ? r2 : r3); chb = (c & 3)*32; }
        else           { src = r1; chb = c*32; }
        const float* s0 = src + ((size_t)(b*128 + chb + 2*bp))*HWX + pp + bl;
        const float* s1 = s0 + HWX;
        #pragma unroll
        for (int j = 0; j < 8; j++) { rbf[j] = s0[16*j]; rbf[8+j] = s1[16*j]; }
    };
    auto store_stage = [&](int st) {
        __nv_bfloat16* base = sm2 + st*4*FM_TILE;
        int off = arow*FM_STR + ahalf*16;
        *reinterpret_cast<uint4*>(base + off)               = rah[0];
        *reinterpret_cast<uint4*>(base + off + 8)           = rah[1];
        *reinterpret_cast<uint4*>(base + FM_TILE + off)     = ral[0];
        *reinterpret_cast<uint4*>(base + FM_TILE + off + 8) = ral[1];
        __nv_bfloat16* Bh = base + 2*FM_TILE;
        __nv_bfloat16* Bl = base + 3*FM_TILE;
        #pragma unroll
        for (int j = 0; j < 8; j++) {
            int px = bl + 16*j;
            float f0 = rbf[j], f1 = rbf[8+j];
            __nv_bfloat16 h0 = __float2bfloat16(f0);
            __nv_bfloat16 h1 = __float2bfloat16(f1);
            __nv_bfloat16 l0 = __float2bfloat16(f0 - __bfloat162float(h0));
            __nv_bfloat16 l1 = __float2bfloat16(f1 - __bfloat162float(h1));
            *reinterpret_cast<uint32_t*>(Bh + px*FM_STR + 2*bp) = pkbf(h0, h1);
            *reinterpret_cast<uint32_t*>(Bl + px*FM_STR + 2*bp) = pkbf(l0, l1);
        }
    };

    load_chunk(0); store_stage(0);
    if (NCH > 1) load_chunk(1);
    __syncthreads();

    for (int ch = 0; ch < NCH; ch++) {
        if (ch + 1 < NCH) store_stage((ch + 1) & 1);
        if (ch + 2 < NCH) load_chunk(ch + 2);
        mma_tiles(sm2 + (ch & 1)*4*FM_TILE, warp_m, warp_n, g, t, acc);
        __syncthreads();
    }

    #pragma unroll
    for (int mt = 0; mt < 4; mt++) {
        #pragma unroll
        for (int r2q = 0; r2q < 2; r2q++) {
            int oc = warp_m*64 + mt*16 + g + r2q*8;
            float s = bns[oc], bb = bnb[oc], bi = bias[oc];
            float* op = out + ((size_t)(b*128 + oc))*HWX + pp + warp_n*32;
            #pragma unroll
            for (int nt = 0; nt < 4; nt++) {
                float d0 = acc[mt][nt][r2q*2+0], d1 = acc[mt][nt][r2q*2+1];
                float z0, z1;
                if (ACT == 1) { z0 = s*lrelu01(d0 + bi) + bb; z1 = s*lrelu01(d1 + bi) + bb; }
                else {
                    z0 = s*(d0 + bi) + bb; z0 = z0 > 0.f ? z0 : 0.f;
                    z1 = s*(d1 + bi) + bb; z1 = z1 > 0.f ? z1 : 0.f;
                }
                *reinterpret_cast<float2*>(op + nt*8 + t*2) = make_float2(z0, z1);
            }
        }
    }
}

// =====================================================================
// f32x2 GEMM inner (kept for resa_add / TR kernel)
// =====================================================================
__device__ __forceinline__ void gemm_chunk_f2(const float* __restrict__ in_s,
                                              const float* __restrict__ w_s,
                                              int ty, int tx, U64 acc[4][8])
{
    #pragma unroll
    for (int kk = 0; kk < 16; kk++) {
        ulonglong2 wa = *reinterpret_cast<const ulonglong2*>(w_s + kk*ROWS + ty*8);
        ulonglong2 wb = *reinterpret_cast<const ulonglong2*>(w_s + kk*ROWS + ty*8 + 4);
        U64 wp[4] = {wa.x, wa.y, wb.x, wb.y};
        float4 xa = *reinterpret_cast<const float4*>(in_s + kk*ROWS + tx*4);
        float4 xb = *reinterpret_cast<const float4*>(in_s + kk*ROWS + 64 + tx*4);
        float xs[8] = {xa.x, xa.y, xa.z, xa.w, xb.x, xb.y, xb.z, xb.w};
        U64 xp[8];
        #pragma unroll
        for (int p = 0; p < 8; p++) PACK2(xp[p], xs[p]);
        #pragma unroll
        for (int j = 0; j < 4; j++)
            #pragma unroll
            for (int p = 0; p < 8; p++)
                FMA2(acc[j][p], wp[j], xp[p]);
    }
}

// =====================================================================
// MLP layer 3 (TR): f32x2, writes transposed [pix][C]
// =====================================================================
__global__ __launch_bounds__(256, 2)
void gemm128_tr_k(const float* __restrict__ in, const float* __restrict__ wg,
                  const float* __restrict__ bias, const float* __restrict__ bns,
                  const float* __restrict__ bnb, float* __restrict__ out)
{
    __shared__ __align__(16) float sraw[2*STAGE_F];
    const int gp = blockIdx.x * 128;
    const int b = gp / HWX, pp = gp - b*HWX;
    const int tid = threadIdx.x, ty = tid >> 4, tx = tid & 15;
    const int oc1 = tid >> 2, q1 = tid & 3;
    U64 acc[4][8];
    #pragma unroll
    for (int j = 0; j < 4; j++)
        #pragma unroll
        for (int p = 0; p < 8; p++) acc[j][p] = 0ULL;

    float4 ra, rb, rwa, rwb;
    auto load_chunk = [&](int kc) {
        const float* sp = &in[((b*128 + kc*16 + ty)*HWX) + pp + tx*8];
        ra = *reinterpret_cast<const float4*>(sp);
        rb = *reinterpret_cast<const float4*>(sp + 4);
        rwa = *reinterpret_cast<const float4*>(&wg[oc1*128 + kc*16 + q1*4]);
        rwb = *reinterpret_cast<const float4*>(&wg[(oc1 + 64)*128 + kc*16 + q1*4]);
    };
    auto store_stage = [&](int st) {
        float* in_s = sraw + st*STAGE_F;
        float* w_s  = in_s + 16*ROWS;
        *reinterpret_cast<float4*>(&in_s[ty*ROWS + tx*8])     = ra;
        *reinterpret_cast<float4*>(&in_s[ty*ROWS + tx*8 + 4]) = rb;
        w_s[(q1*4+0)*ROWS + oc1] = rwa.x; w_s[(q1*4+1)*ROWS + oc1] = rwa.y;
        w_s[(q1*4+2)*ROWS + oc1] = rwa.z; w_s[(q1*4+3)*ROWS + oc1] = rwa.w;
        w_s[(q1*4+0)*ROWS + oc1+64] = rwb.x; w_s[(q1*4+1)*ROWS + oc1+64] = rwb.y;
        w_s[(q1*4+2)*ROWS + oc1+64] = rwb.z; w_s[(q1*4+3)*ROWS + oc1+64] = rwb.w;
    };

    load_chunk(0); store_stage(0);
    load_chunk(1);
    __syncthreads();
    for (int kc = 0; kc < 8; kc++) {
        if (kc + 1 < 8) store_stage((kc + 1) & 1);
        if (kc + 2 < 8) load_chunk(kc + 2);
        const float* base = sraw + (kc & 1)*STAGE_F;
        gemm_chunk_f2(base, base + 16*ROWS, ty, tx, acc);
        __syncthreads();
    }

    float* stage = sraw;
    for (int gq = 0; gq < 4; gq++) {
        __syncthreads();
        if ((ty >> 2) == gq) {
            #pragma unroll
            for (int j = 0; j < 4; j++) {
                unsigned a, c;
                float lo[8], hi[8];
                #pragma unroll
                for (int p = 0; p < 8; p++) {
                    UNPK2(a, c, acc[j][p]);
                    lo[p] = __uint_as_float(a); hi[p] = __uint_as_float(c);
                }
                int oc = ty*8 + 2*j;
                int ocl = oc - gq*32;
                float bi0 = bias[oc],   s0 = bns[oc],   b0 = bnb[oc];
                float bi1 = bias[oc+1], s1 = bns[oc+1], b1 = bnb[oc+1];
                #pragma unroll
                for (int p = 0; p < 8; p++) {
                    int col = (p < 4) ? (tx*4 + p) : (64 + tx*4 + p - 4);
                    float z0 = s0*(lo[p] + bi0) + b0;
                    float z1 = s1*(hi[p] + bi1) + b1;
                    stage[ocl*129 + col]     = z0 > 0.f ? z0 : 0.f;
                    stage[(ocl+1)*129 + col] = z1 > 0.f ? z1 : 0.f;
                }
            }
        }
        __syncthreads();
        for (int t2 = tid; t2 < 1024; t2 += 256) {
            int pix = t2 >> 3, c4 = t2 & 7;
            float4 v;
            v.x = stage[(c4*4+0)*129 + pix];
            v.y = stage[(c4*4+1)*129 + pix];
            v.z = stage[(c4*4+2)*129 + pix];
            v.w = stage[(c4*4+3)*129 + pix];
            *reinterpret_cast<float4*>(&out[(size_t)(b*HWX + pp + pix)*128 + gq*32 + c4*4]) = v;
        }
    }
}

// =====================================================================
// resA shortcut add: out += lrelu(c1 @ x + c1_b), K=64 (f32x2)
// =====================================================================
__global__ __launch_bounds__(256, 2)
void resa_add_k(const float* __restrict__ x,
                const float* __restrict__ c1w, const float* __restrict__ c1b,
                float* __restrict__ out)
{
    __shared__ __align__(16) float sraw[2*STAGE_F];
    const int gp = blockIdx.x * 128;
    const int b = gp / HWX, pp = gp - b*HWX;
    const int tid = threadIdx.x, ty = tid >> 4, tx = tid & 15;
    const int oc1 = tid >> 2, q1 = tid & 3;
    U64 acc[4][8];
    #pragma unroll
    for (int j = 0; j < 4; j++)
        #pragma unroll
        for (int p = 0; p < 8; p++) acc[j][p] = 0ULL;

    float4 ra, rb, rwa, rwb;
    auto load_c = [&](int kc) {
        const float* sp = &x[((b*64 + kc*16 + ty)*HWX) + pp + tx*8];
        ra = *reinterpret_cast<const float4*>(sp);
        rb = *reinterpret_cast<const float4*>(sp + 4);
        rwa = *reinterpret_cast<const float4*>(&c1w[oc1*64 + kc*16 + q1*4]);
        rwb = *reinterpret_cast<const float4*>(&c1w[(oc1 + 64)*64 + kc*16 + q1*4]);
    };
    auto store_stage = [&](int st) {
        float* in_s = sraw + st*STAGE_F;
        float* w_s  = in_s + 16*ROWS;
        *reinterpret_cast<float4*>(&in_s[ty*ROWS + tx*8])     = ra;
        *reinterpret_cast<float4*>(&in_s[ty*ROWS + tx*8 + 4]) = rb;
        w_s[(q1*4+0)*ROWS + oc1] = rwa.x; w_s[(q1*4+1)*ROWS + oc1] = rwa.y;
        w_s[(q1*4+2)*ROWS + oc1] = rwa.z; w_s[(q1*4+3)*ROWS + oc1] = rwa.w;
        w_s[(q1*4+0)*ROWS + oc1+64] = rwb.x; w_s[(q1*4+1)*ROWS + oc1+64] = rwb.y;
        w_s[(q1*4+2)*ROWS + oc1+64] = rwb.z; w_s[(q1*4+3)*ROWS + oc1+64] = rwb.w;
    };

    load_c(0); store_stage(0);
    load_c(1);
    __syncthreads();
    for (int kc = 0; kc < 4; kc++) {
        if (kc + 1 < 4) store_stage((kc + 1) & 1);
        if (kc + 2 < 4) load_c(kc + 2);
        const float* base = sraw + (kc & 1)*STAGE_F;
        gemm_chunk_f2(base, base + 16*ROWS, ty, tx, acc);
        __syncthreads();
    }

    #pragma unroll
    for (int j = 0; j < 4; j++) {
        float lo[8], hi[8];
        #pragma unroll
        for (int p = 0; p < 8; p++) {
            unsigned a, c; UNPK2(a, c, acc[j][p]);
            lo[p] = __uint_as_float(a); hi[p] = __uint_as_float(c);
        }
        #pragma unroll
        for (int hh2 = 0; hh2 < 2; hh2++) {
            int oc = ty*8 + 2*j + hh2;
            const float* m = hh2 ? hi : lo;
            float b1 = c1b[oc];
            float* op = &out[((b*128 + oc)*HWX) + pp];
            float4 o0 = *reinterpret_cast<const float4*>(op + tx*4);
            float4 o1 = *reinterpret_cast<const float4*>(op + 64 + tx*4);
            o0.x += lrelu01(m[0] + b1); o0.y += lrelu01(m[1] + b1);
            o0.z += lrelu01(m[2] + b1); o0.w += lrelu01(m[3] + b1);
            o1.x += lrelu01(m[4] + b1); o1.y += lrelu01(m[5] + b1);
            o1.z += lrelu01(m[6] + b1); o1.w += lrelu01(m[7] + b1);
            *reinterpret_cast<float4*>(op + tx*4)      = o0;
            *reinterpret_cast<float4*>(op + 64 + tx*4) = o1;
        }
    }
}

// =====================================================================
// WeightNet
// =====================================================================
__global__ __launch_bounds__(256)
void weightnet_k(const float* __restrict__ xyz,
                 const float* __restrict__ w1w, const float* __restrict__ w1b,
                 const float* __restrict__ w2w, const float* __restrict__ w2b,
                 const float* __restrict__ w3w, const float* __restrict__ w3b,
                 const float* __restrict__ s1, const float* __restrict__ b1,
                 const float* __restrict__ s2, const float* __restrict__ b2,
                 const float* __restrict__ s3, const float* __restrict__ b3,
                 float* __restrict__ out)
{
    int g = blockIdx.x*256 + threadIdx.x;
    int pix = g & (NP2 - 1);
    int rest = g >> 14;
    int k = rest % 25, b = rest / 25;
    int h2 = pix >> 9, w2 = pix & 511;
    int hi = 2*h2 - 2 + k/5, wi = 2*w2 - 2 + (k % 5);
    bool inb = ((unsigned)hi < (unsigned)HH) && ((unsigned)wi < (unsigned)WW);
    float gv[3];
    #pragma unroll
    for (int c = 0; c < 3; c++) {
        float ctr = xyz[(b*3 + c)*HWX + (2*h2)*WW + 2*w2];
        float nb  = inb ? xyz[(b*3 + c)*HWX + hi*WW + wi] : 0.f;
        gv[c] = nb - ctr;
    }
    float a1[8];
    #pragma unroll
    for (int j = 0; j < 8; j++) {
        float z = w1b[j];
        #pragma unroll
        for (int c = 0; c < 3; c++) z += w1w[j*3 + c]*gv[c];
        z = s1[j]*z + b1[j];
        a1[j] = z > 0.f ? z : 0.f;
    }
    float a2[8];
    #pragma unroll
    for (int j = 0; j < 8; j++) {
        float z = w2b[j];
        #pragma unroll
        for (int i = 0; i < 8; i++) z += w2w[j*8 + i]*a1[i];
        z = s2[j]*z + b2[j];
        a2[j] = z > 0.f ? z : 0.f;
    }
    float o[16];
    #pragma unroll
    for (int n = 0; n < 16; n++) {
        float z = w3b[n];
        #pragma unroll
        for (int i = 0; i < 8; i++) z += w3w[n*8 + i]*a2[i];
        z = s3[n]*z + b3[n];
        o[n] = z > 0.f ? z : 0.f;
    }
    size_t base = (((size_t)(b*NP2 + pix))*25 + k)*16;
    #pragma unroll
    for (int q = 0; q < 4; q++)
        *reinterpret_cast<float4*>(&out[base + q*4]) =
            make_float4(o[q*4], o[q*4+1], o[q*4+2], o[q*4+3]);
}

// =====================================================================
// Einsum -> writes y directly as bf16 hi/lo (pixel-major [px][2048])
// =====================================================================
__global__ __launch_bounds__(128)
void einsum_k(const float* __restrict__ hT, const float* __restrict__ wn,
              __nv_bfloat16* __restrict__ yh, __nv_bfloat16* __restrict__ yl)
{
    __shared__ __align__(16) float u_s[2][25][128];
    __shared__ float wn_s[2][400];
    const int gpix = blockIdx.x*2;
    const int b = gpix / NP2;
    const int tid = threadIdx.x;

    for (int i = tid; i < 800; i += 128) {
        int pl = i / 400, r = i - pl*400;
        wn_s[pl][r] = wn[(size_t)(gpix + pl)*400 + r];
    }
    for (int idx = 0; idx < 50; idx++) {
        int pl = idx / 25, k = idx - pl*25;
        int pp = (gpix + pl) - b*NP2;
        int h2 = pp >> 9, w2 = pp & 511;
        int hi = 2*h2 - 2 + k/5, wi = 2*w2 - 2 + (k % 5);
        float v = 0.f;
        if ((unsigned)hi < (unsigned)HH && (unsigned)wi < (unsigned)WW)
            v = hT[((size_t)(b*HH + hi)*WW + wi)*128 + tid];
        u_s[pl][k][tid] = v;
    }
    __syncthreads();

    const int s = tid & 63, pl = tid >> 6;
    const int cg = s & 15, ng = s >> 4;
    float acc[8][4];
    #pragma unroll
    for (int i = 0; i < 8; i++)
        #pragma unroll
        for (int n = 0; n < 4; n++) acc[i][n] = 0.f;

    #pragma unroll
    for (int k = 0; k < 25; k++) {
        float4 ua = *reinterpret_cast<const float4*>(&u_s[pl][k][cg*4]);
        float4 ub = *reinterpret_cast<const float4*>(&u_s[pl][k][64 + cg*4]);
        float u[8] = {ua.x, ua.y, ua.z, ua.w, ub.x, ub.y, ub.z, ub.w};
        float4 wv = *reinterpret_cast<const float4*>(&wn_s[pl][k*16 + ng*4]);
        float wvv[4] = {wv.x, wv.y, wv.z, wv.w};
        #pragma unroll
        for (int i = 0; i < 8; i++)
            #pragma unroll
            for (int n = 0; n < 4; n++) acc[i][n] += u[i]*wvv[n];
    }
    size_t base = (size_t)(gpix + pl)*2048;
    #pragma unroll
    for (int i = 0; i < 8; i++) {
        int c = (i < 4) ? (cg*4 + i) : (64 + cg*4 + i - 4);
        __nv_bfloat16 h[4], l[4];
        #pragma unroll
        for (int n = 0; n < 4; n++) {
            h[n] = __float2bfloat16(acc[i][n]);
            l[n] = __float2bfloat16(acc[i][n] - __bfloat162float(h[n]));
        }
        *reinterpret_cast<uint2*>(&yh[base + c*16 + ng*4]) = make_uint2(pkbf(h[0],h[1]), pkbf(h[2],h[3]));
        *reinterpret_cast<uint2*>(&yl[base + c*16 + ng*4]) = make_uint2(pkbf(l[0],l[1]), pkbf(l[2],l[3]));
    }
}

// =====================================================================
// Final GEMM (mma.sync bf16x3) with pure-copy fills
// =====================================================================
__global__ __launch_bounds__(256)
void final_mma_k(const __nv_bfloat16* __restrict__ yh, const __nv_bfloat16* __restrict__ yl,
                 const __nv_bfloat16* __restrict__ lwh, const __nv_bfloat16* __restrict__ lwl,
                 const float* __restrict__ lbias, const float* __restrict__ bns,
                 const float* __restrict__ bnb, float* __restrict__ out)
{
    extern __shared__ __align__(16) __nv_bfloat16 sm2[];
    const int gp = blockIdx.x * 128;
    const int b  = gp / NP2, pp = gp - b*NP2;
    const int tid = threadIdx.x;
    const int wid = tid >> 5, lane = tid & 31;
    const int g = lane >> 2, t = lane & 3;
    const int warp_m = wid & 1, warp_n = wid >> 1;
    const int row = tid >> 1, half = tid & 1;

    float acc[4][4][4];
    #pragma unroll
    for (int mt = 0; mt < 4; mt++)
        #pragma unroll
        for (int nt = 0; nt < 4; nt++)
            #pragma unroll
            for (int q = 0; q < 4; q++) acc[mt][nt][q] = 0.f;

    uint4 rah[2], ral[2], rbh[2], rbl[2];
    auto load_chunk = [&](int ch) {
        int kc = ch*32;
        size_t aoff = (size_t)row*2048 + kc + half*16;
        size_t boff = (size_t)(gp + row)*2048 + kc + half*16;
        rah[0] = *reinterpret_cast<const uint4*>(lwh + aoff);
        rah[1] = *reinterpret_cast<const uint4*>(lwh + aoff + 8);
        ral[0] = *reinterpret_cast<const uint4*>(lwl + aoff);
        ral[1] = *reinterpret_cast<const uint4*>(lwl + aoff + 8);
        rbh[0] = *reinterpret_cast<const uint4*>(yh + boff);
        rbh[1] = *reinterpret_cast<const uint4*>(yh + boff + 8);
        rbl[0] = *reinterpret_cast<const uint4*>(yl + boff);
        rbl[1] = *reinterpret_cast<const uint4*>(yl + boff + 8);
    };
    auto store_stage = [&](int st) {
        __nv_bfloat16* base = sm2 + st*4*FM_TILE;
        int off = row*FM_STR + half*16;
        *reinterpret_cast<uint4*>(base + off)                   = rah[0];
        *reinterpret_cast<uint4*>(base + off + 8)               = rah[1];
        *reinterpret_cast<uint4*>(base + FM_TILE + off)         = ral[0];
        *reinterpret_cast<uint4*>(base + FM_TILE + off + 8)     = ral[1];
        *reinterpret_cast<uint4*>(base + 2*FM_TILE + off)       = rbh[0];
        *reinterpret_cast<uint4*>(base + 2*FM_TILE + off + 8)   = rbh[1];
        *reinterpret_cast<uint4*>(base + 3*FM_TILE + off)       = rbl[0];
        *reinterpret_cast<uint4*>(base + 3*FM_TILE + off + 8)   = rbl[1];
    };

    load_chunk(0); store_stage(0);
    load_chunk(1);
    __syncthreads();

    for (int ch = 0; ch < 64; ch++) {
        if (ch + 1 < 64) store_stage((ch + 1) & 1);
        if (ch + 2 < 64) load_chunk(ch + 2);
        mma_tiles(sm2 + (ch & 1)*4*FM_TILE, warp_m, warp_n, g, t, acc);
        __syncthreads();
    }

    #pragma unroll
    for (int mt = 0; mt < 4; mt++) {
        #pragma unroll
        for (int r2 = 0; r2 < 2; r2++) {
            int oc = warp_m*64 + mt*16 + g + r2*8;
            float s = bns[oc], bb = bnb[oc], bi = lbias[oc];
            float* op = out + ((size_t)(b*128 + oc))*NP2 + pp + warp_n*32;
            #pragma unroll
            for (int nt = 0; nt < 4; nt++) {
                float z0 = s*(acc[mt][nt][r2*2+0] + bi) + bb;
                float z1 = s*(acc[mt][nt][r2*2+1] + bi) + bb;
                float2 v;
                v.x = z0 > 0.f ? z0 : 0.f;
                v.y = z1 > 0.f ? z1 : 0.f;
                *reinterpret_cast<float2*>(op + nt*8 + t*2) = v;
            }
        }
    }
}

// =====================================================================
// host launcher
// =====================================================================
extern "C" void kernel_launch(void* const* d_in, const int* in_sizes, int n_in,
                              void* d_out, int out_size)
{
    const float* x      = (const float*)d_in[0];
    const float* xyz    = (const float*)d_in[1];
    const float* c1_w   = (const float*)d_in[2];
    const float* c1_b   = (const float*)d_in[3];
    const float* c2_w   = (const float*)d_in[4];
    const float* c2_b   = (const float*)d_in[5];
    const float* c3_w   = (const float*)d_in[6];
    const float* c3_b   = (const float*)d_in[7];
    const float* c4_w   = (const float*)d_in[8];
    const float* c4_b   = (const float*)d_in[9];
    const float* c5_w   = (const float*)d_in[10];
    const float* c5_b   = (const float*)d_in[11];
    const float* rbn_s  = (const float*)d_in[12];
    const float* rbn_b  = (const float*)d_in[13];
    const float* p_w    = (const float*)d_in[14];
    const float* p_b    = (const float*)d_in[15];
    const float* pbn_s  = (const float*)d_in[16];
    const float* pbn_b  = (const float*)d_in[17];
    const float* lin_w  = (const float*)d_in[18];
    const float* lin_b  = (const float*)d_in[19];
    const float* w1_w   = (const float*)d_in[20];
    const float* w1_b   = (const float*)d_in[21];
    const float* w2_w   = (const float*)d_in[22];
    const float* w2_b   = (const float*)d_in[23];
    const float* w3_w   = (const float*)d_in[24];
    const float* w3_b   = (const float*)d_in[25];
    const float* wbn1_s = (const float*)d_in[26];
    const float* wbn1_b = (const float*)d_in[27];
    const float* wbn2_s = (const float*)d_in[28];
    const float* wbn2_b = (const float*)d_in[29];
    const float* wbn3_s = (const float*)d_in[30];
    const float* wbn3_b = (const float*)d_in[31];

    float* outp = (float*)d_out;
    float* resB = outp;                 // [B,128,H2,W2]
    float* resA = outp + RESB_ELEMS;    // [B,128,H,W]

    float *A1, *A2, *A3, *B1, *B2, *HT, *WN;
    __nv_bfloat16 *YH, *YL, *WHp, *WLp;
    cudaGetSymbolAddress((void**)&A1, g_resA1);
    cudaGetSymbolAddress((void**)&A2, g_resA2);
    cudaGetSymbolAddress((void**)&A3, g_resA3);
    cudaGetSymbolAddress((void**)&B1, g_buf1);
    cudaGetSymbolAddress((void**)&B2, g_buf2);
    cudaGetSymbolAddress((void**)&HT, g_hT);
    cudaGetSymbolAddress((void**)&WN, g_wn);
    cudaGetSymbolAddress((void**)&YH, g_yh);
    cudaGetSymbolAddress((void**)&YL, g_yl);
    cudaGetSymbolAddress((void**)&WHp, g_wh);
    cudaGetSymbolAddress((void**)&WLp, g_wl);

    cudaFuncSetAttribute(final_mma_k, cudaFuncAttributeMaxDynamicSharedMemorySize, FM_SMEM);
    cudaFuncSetAttribute(mma_nchw_k<384,3,1>, cudaFuncAttributeMaxDynamicSharedMemorySize, FM_SMEM);
    cudaFuncSetAttribute(mma_nchw_k<128,1,0>, cudaFuncAttributeMaxDynamicSharedMemorySize, FM_SMEM);
    cudaFuncSetAttribute(mma_conv_k<64,3,1,1>, cudaFuncAttributeMaxDynamicSharedMemorySize, FM_SMEM);
    cudaFuncSetAttribute(mma_conv_k<128,3,2,2>, cudaFuncAttributeMaxDynamicSharedMemorySize, FM_SMEM);
    cudaFuncSetAttribute(mma_conv_k<128,2,2,1>, cudaFuncAttributeMaxDynamicSharedMemorySize, FM_SMEM);

    // weight precompute (bf16 hi/lo)
    prep_w_k<<<(WTOTAL + 255)/256, 256>>>(lin_w, c5_w, p_w, c2_w, c3_w, c4_w, WHp, WLp);

    dim3 cgrid(WW/128, HH, BB);   // (8, 64, 2)
    // ResBlock trunk on HMMA (implicit im2col)
    mma_conv_k<64,3,1,1><<<cgrid, 256, FM_SMEM>>>(x,  WHp + WOFF_C2, WLp + WOFF_C2,
        c2_b, rbn_s,       rbn_b,       A1);
    mma_conv_k<128,3,2,2><<<cgrid, 256, FM_SMEM>>>(A1, WHp + WOFF_C3, WLp + WOFF_C3,
        c3_b, rbn_s + 128, rbn_b + 128, A2);
    mma_conv_k<128,2,2,1><<<cgrid, 256, FM_SMEM>>>(A2, WHp + WOFF_C4, WLp + WOFF_C4,
        c4_b, rbn_s + 256, rbn_b + 256, A3);
    // resA main via mma (K=384, lrelu+bn)
    mma_nchw_k<384,3,1><<<BB*HWX/128, 256, FM_SMEM>>>(A1, A2, A3,
        WHp + WOFF_C5, WLp + WOFF_C5, c5_b, rbn_s + 384, rbn_b + 384, resA);
    resa_add_k<<<BB*HWX/128, 256>>>(x, c1_w, c1_b, resA);
    // MLP layers 1,2 via mma (K=128, relu(bn))
    mma_nchw_k<128,1,0><<<BB*HWX/128, 256, FM_SMEM>>>(resA, resA, resA,
        WHp + WOFF_P, WLp + WOFF_P, p_b, pbn_s, pbn_b, B1);
    mma_nchw_k<128,1,0><<<BB*HWX/128, 256, FM_SMEM>>>(B1, B1, B1,
        WHp + WOFF_P + 16384, WLp + WOFF_P + 16384, p_b + 128, pbn_s + 128, pbn_b + 128, B2);
    // MLP layer 3: f32, transposed output for unfold gather
    gemm128_tr_k<<<BB*HWX/128, 256>>>(B2, p_w + 32768, p_b + 256, pbn_s + 256, pbn_b + 256, HT);
    // WeightNet
    weightnet_k<<<(BB*25*NP2)/256, 256>>>(xyz, w1_w, w1_b, w2_w, w2_b, w3_w, w3_b,
                                          wbn1_s, wbn1_b, wbn2_s, wbn2_b, wbn3_s, wbn3_b, WN);
    // einsum -> y (bf16 hi/lo, pixel-major)
    einsum_k<<<BB*NP2/2, 128>>>(HT, WN, YH, YL);
    // final GEMM (copy-fill mma)
    final_mma_k<<<BB*NP2/128, 256, FM_SMEM>>>(YH, YL, WHp, WLp,
                                              lin_b, pbn_s + 384, pbn_b + 384, resB);
}

// round 17
// speedup vs baseline: 1.6457x; 1.0556x over previous
#include <cuda_runtime.h>
#include <cuda_bf16.h>
#include <cstddef>
#include <cstdint>

// ---------------- problem constants ----------------
#define BB   2
#define CINX 64
#define CH   128
#define HH   64
#define WW   1024
#define HWX  (HH*WW)          // 65536
#define H2X  32
#define W2X  512
#define NP2  (H2X*W2X)        // 16384
#define RESB_ELEMS (BB*CH*NP2)   // 4194304

typedef unsigned long long U64;

// f32x2 packed FMA (Blackwell)
#define FMA2(c, a, b) asm("fma.rn.f32x2 %0, %1, %2, %0;" : "+l"(c) : "l"(a), "l"(b))
#define PACK2(d, x)   asm("mov.b64 %0, {%1, %1};" : "=l"(d) : "r"(__float_as_uint(x)))
#define UNPK2(lo, hi, d) asm("mov.b64 {%0, %1}, %2;" : "=r"(lo), "=r"(hi) : "l"(d))

#define ROWS 132
#define STAGE_F (16*ROWS*2)

// mma tile geometry
#define FM_STR    40                      // bf16 row stride (20 words -> CF frags)
#define FM_TILE   (128*FM_STR)            // 5120 bf16 per tile
#define FM_SMEM   (2*4*FM_TILE*2)         // 81920 bytes (2 stages x 4 tiles)

// precomputed weight offsets (bf16 elements)
#define WOFF_LW   0
#define WOFF_C5   262144                  // +128*2048
#define WOFF_P    311296                  // +128*384
#define WOFF_C2   360448                  // +3*128*128
#define WOFF_C3   434176                  // +128*576
#define WOFF_C4   581632                  // +128*1152
#define WTOTAL    647168                  // +128*512

// ---------------- scratch ----------------
__device__ float g_resA1[BB*CH*HWX];
__device__ float g_resA2[BB*CH*HWX];
__device__ float g_resA3[BB*CH*HWX];
__device__ float g_buf1 [BB*CH*HWX];
__device__ float g_buf2 [BB*CH*HWX];
__device__ float g_hT   [BB*HWX*CH];
__device__ float g_wn   [BB*NP2*25*16];
__device__ __nv_bfloat16 g_yh[(size_t)BB*NP2*2048];
__device__ __nv_bfloat16 g_yl[(size_t)BB*NP2*2048];
__device__ __nv_bfloat16 g_wh[WTOTAL];
__device__ __nv_bfloat16 g_wl[WTOTAL];

__device__ __forceinline__ float lrelu01(float z) { return z > 0.f ? z : 0.01f*z; }
static __device__ __forceinline__ uint32_t pkbf(__nv_bfloat16 a, __nv_bfloat16 b) {
    return (uint32_t)__bfloat16_as_ushort(a) | ((uint32_t)__bfloat16_as_ushort(b) << 16);
}
static __device__ __forceinline__ void mma_bf16(float d[4], const uint32_t a[4],
                                                uint32_t b0, uint32_t b1) {
    asm volatile(
        "mma.sync.aligned.m16n8k16.row.col.f32.bf16.bf16.f32 "
        "{%0,%1,%2,%3}, {%4,%5,%6,%7}, {%8,%9}, {%0,%1,%2,%3};\n"
        : "+f"(d[0]), "+f"(d[1]), "+f"(d[2]), "+f"(d[3])
        : "r"(a[0]), "r"(a[1]), "r"(a[2]), "r"(a[3]), "r"(b0), "r"(b1));
}

// =====================================================================
// prep: fp32 weights -> bf16 hi/lo (lw | c5w | p_w | c2w | c3w | c4w)
// =====================================================================
__global__ __launch_bounds__(256)
void prep_w_k(const float* __restrict__ lw, const float* __restrict__ c5w,
              const float* __restrict__ pw, const float* __restrict__ c2w,
              const float* __restrict__ c3w, const float* __restrict__ c4w,
              __nv_bfloat16* __restrict__ wh, __nv_bfloat16* __restrict__ wl)
{
    int idx = blockIdx.x*256 + threadIdx.x;
    if (idx >= WTOTAL) return;
    float v;
    if (idx < WOFF_C5)      v = lw[idx];
    else if (idx < WOFF_P)  v = c5w[idx - WOFF_C5];
    else if (idx < WOFF_C2) v = pw[idx - WOFF_P];
    else if (idx < WOFF_C3) v = c2w[idx - WOFF_C2];
    else if (idx < WOFF_C4) v = c3w[idx - WOFF_C3];
    else                    v = c4w[idx - WOFF_C4];
    __nv_bfloat16 h = __float2bfloat16(v);
    wh[idx] = h;
    wl[idx] = __float2bfloat16(v - __bfloat162float(h));
}

// =====================================================================
// mma fragment compute for 512-thread kernels: warp tile 32x32
// (2 m16 x 4 n8 frags), bf16x3 split.
// =====================================================================
static __device__ __forceinline__ void mma_tiles16(const __nv_bfloat16* Ah,
                                                   int warp_m, int warp_n,
                                                   int g, int t,
                                                   float acc[2][4][4])
{
    const __nv_bfloat16* Al = Ah + FM_TILE;
    const __nv_bfloat16* Bh = Ah + 2*FM_TILE;
    const __nv_bfloat16* Bl = Ah + 3*FM_TILE;
    #pragma unroll
    for (int ks = 0; ks < 2; ks++) {
        const int kb = ks*16 + t*2;
        uint32_t ah[2][4], al[2][4];
        #pragma unroll
        for (int mt = 0; mt < 2; mt++) {
            int r0 = (warp_m*32 + mt*16 + g)*FM_STR;
            ah[mt][0] = *reinterpret_cast<const uint32_t*>(Ah + r0 + kb);
            ah[mt][1] = *reinterpret_cast<const uint32_t*>(Ah + r0 + 8*FM_STR + kb);
            ah[mt][2] = *reinterpret_cast<const uint32_t*>(Ah + r0 + kb + 8);
            ah[mt][3] = *reinterpret_cast<const uint32_t*>(Ah + r0 + 8*FM_STR + kb + 8);
            al[mt][0] = *reinterpret_cast<const uint32_t*>(Al + r0 + kb);
            al[mt][1] = *reinterpret_cast<const uint32_t*>(Al + r0 + 8*FM_STR + kb);
            al[mt][2] = *reinterpret_cast<const uint32_t*>(Al + r0 + kb + 8);
            al[mt][3] = *reinterpret_cast<const uint32_t*>(Al + r0 + 8*FM_STR + kb + 8);
        }
        #pragma unroll
        for (int nt = 0; nt < 4; nt++) {
            int c0 = (warp_n*32 + nt*8 + g)*FM_STR;
            uint32_t bh0 = *reinterpret_cast<const uint32_t*>(Bh + c0 + kb);
            uint32_t bh1 = *reinterpret_cast<const uint32_t*>(Bh + c0 + kb + 8);
            uint32_t bl0 = *reinterpret_cast<const uint32_t*>(Bl + c0 + kb);
            uint32_t bl1 = *reinterpret_cast<const uint32_t*>(Bl + c0 + kb + 8);
            #pragma unroll
            for (int mt = 0; mt < 2; mt++) {
                mma_bf16(acc[mt][nt], ah[mt], bh0, bh1);
                mma_bf16(acc[mt][nt], al[mt], bh0, bh1);
                mma_bf16(acc[mt][nt], ah[mt], bl0, bl1);
            }
        }
    }
}

// =====================================================================
// Conv via mma.sync bf16x3 (implicit im2col), 512 threads.
// D[128oc][128px] per CTA, one output row h. Epilogue bn(lrelu(.)).
// =====================================================================
template<int CIN, int KS, int DIL, int PAD>
__global__ __launch_bounds__(512)
void mma_conv_k(const float* __restrict__ in,
                const __nv_bfloat16* __restrict__ wh, const __nv_bfloat16* __restrict__ wl,
                const float* __restrict__ bias, const float* __restrict__ bns,
                const float* __restrict__ bnb, float* __restrict__ out)
{
    constexpr int KK = KS*KS, KTOT = CIN*KK, NCH = KTOT/32;
    extern __shared__ __align__(16) __nv_bfloat16 sm2[];
    const int w0 = blockIdx.x * 128;
    const int h  = blockIdx.y;
    const int b  = blockIdx.z;
    const int tid = threadIdx.x;
    const int wid = tid >> 5, lane = tid & 31;
    const int g = lane >> 2, t = lane & 3;
    const int warp_m = wid & 3, warp_n = wid >> 2;
    const int arow = tid >> 2, aq = tid & 3;            // A fill: 8 bf16/thread
    const int jb = tid >> 8, bp = (tid >> 4) & 15, bl = tid & 15;  // B fill

    float acc[2][4][4];
    #pragma unroll
    for (int mt = 0; mt < 2; mt++)
        #pragma unroll
        for (int nt = 0; nt < 4; nt++)
            #pragma unroll
            for (int q = 0; q < 4; q++) acc[mt][nt][q] = 0.f;

    uint4 rah, ral;
    float rbf[8];
    auto load_chunk = [&](int c) {
        int kc = c*32;
        size_t aoff = (size_t)arow*KTOT + kc + aq*8;
        rah = *reinterpret_cast<const uint4*>(wh + aoff);
        ral = *reinterpret_cast<const uint4*>(wl + aoff);
        #pragma unroll
        for (int e = 0; e < 2; e++) {
            int k  = kc + 2*bp + e;
            int ci = k / KK;
            int r  = k - ci*KK;
            int kh = r / KS, kw = r - kh*KS;
            int gy = h - PAD + kh*DIL;
            bool yok = (unsigned)gy < (unsigned)HH;
            const float* rowp = in + ((size_t)(b*CIN + ci)*HH + gy)*WW;
            int gx0 = w0 - PAD + kw*DIL + bl;
            #pragma unroll
            for (int j = 0; j < 4; j++) {
                int gx = gx0 + 16*(jb*4 + j);
                rbf[e*4 + j] = (yok && (unsigned)gx < (unsigned)WW) ? rowp[gx] : 0.f;
            }
        }
    };
    auto store_stage = [&](int st) {
        __nv_bfloat16* base = sm2 + st*4*FM_TILE;
        int off = arow*FM_STR + aq*8;
        *reinterpret_cast<uint4*>(base + off)           = rah;
        *reinterpret_cast<uint4*>(base + FM_TILE + off) = ral;
        __nv_bfloat16* Bh = base + 2*FM_TILE;
        __nv_bfloat16* Bl = base + 3*FM_TILE;
        #pragma unroll
        for (int j = 0; j < 4; j++) {
            int px = bl + 16*(jb*4 + j);
            float f0 = rbf[j], f1 = rbf[4+j];
            __nv_bfloat16 h0 = __float2bfloat16(f0);
            __nv_bfloat16 h1 = __float2bfloat16(f1);
            __nv_bfloat16 l0 = __float2bfloat16(f0 - __bfloat162float(h0));
            __nv_bfloat16 l1 = __float2bfloat16(f1 - __bfloat162float(h1));
            *reinterpret_cast<uint32_t*>(Bh + px*FM_STR + 2*bp) = pkbf(h0, h1);
            *reinterpret_cast<uint32_t*>(Bl + px*FM_STR + 2*bp) = pkbf(l0, l1);
        }
    };

    load_chunk(0); store_stage(0);
    if (NCH > 1) load_chunk(1);
    __syncthreads();

    for (int ch = 0; ch < NCH; ch++) {
        if (ch + 1 < NCH) store_stage((ch + 1) & 1);
        if (ch + 2 < NCH) load_chunk(ch + 2);
        mma_tiles16(sm2 + (ch & 1)*4*FM_TILE, warp_m, warp_n, g, t, acc);
        __syncthreads();
    }

    #pragma unroll
    for (int mt = 0; mt < 2; mt++) {
        #pragma unroll
        for (int r2q = 0; r2q < 2; r2q++) {
            int oc = warp_m*32 + mt*16 + g + r2q*8;
            float s = bns[oc], bb = bnb[oc], bi = bias[oc];
            float* op = out + ((size_t)(b*128 + oc)*HH + h)*WW + w0 + warp_n*32;
            #pragma unroll
            for (int nt = 0; nt < 4; nt++) {
                float z0 = s*lrelu01(acc[mt][nt][r2q*2+0] + bi) + bb;
                float z1 = s*lrelu01(acc[mt][nt][r2q*2+1] + bi) + bb;
                *reinterpret_cast<float2*>(op + nt*8 + t*2) = make_float2(z0, z1);
            }
        }
    }
}

// =====================================================================
// Generic NCHW-input mma.sync bf16x3 GEMM, 512 threads.
// =====================================================================
template<int KTOT, int NSRC, int ACT>
__global__ __launch_bounds__(512)
void mma_nchw_k(const float* __restrict__ r1, const float* __restrict__ r2,
                const float* __restrict__ r3,
                const __nv_bfloat16* __restrict__ wh, const __nv_bfloat16* __restrict__ wl,
                const float* __restrict__ bias, const float* __restrict__ bns,
                const float* __restrict__ bnb, float* __restrict__ out)
{
    constexpr int NCH = KTOT/32;
    extern __shared__ __align__(16) __nv_bfloat16 sm2[];
    const int gp = blockIdx.x * 128;
    const int b  = gp / HWX, pp = gp - b*HWX;
    const int tid = threadIdx.x;
    const int wid = tid >> 5, lane = tid & 31;
    const int g = lane >> 2, t = lane & 3;
    const int warp_m = wid & 3, warp_n = wid >> 2;
    const int arow = tid >> 2, aq = tid & 3;
    const int jb = tid >> 8, bp = (tid >> 4) & 15, bl = tid & 15;

    float acc[2][4][4];
    #pragma unroll
    for (int mt = 0; mt < 2; mt++)
        #pragma unroll
        for (int nt = 0; nt < 4; nt++)
            #pragma unroll
            for (int q = 0; q < 4; q++) acc[mt][nt][q] = 0.f;

    uint4 rah, ral;
    float rbf[8];
    auto load_chunk = [&](int c) {
        int kc = c*32;
        size_t aoff = (size_t)arow*KTOT + kc + aq*8;
        rah = *reinterpret_cast<const uint4*>(wh + aoff);
        ral = *reinterpret_cast<const uint4*>(wl + aoff);
        const float* src; int chb;
        if (NSRC == 3) { src = (c < 4) ? r1 : (c < 8 ? r2 : r3); chb = (c & 3)*32; }
        else           { src = r1; chb = c*32; }
        const float* s0 = src + ((size_t)(b*128 + chb + 2*bp))*HWX + pp + bl + jb*64;
        const float* s1 = s0 + HWX;
        #pragma unroll
        for (int j = 0; j < 4; j++) { rbf[j] = s0[16*j]; rbf[4+j] = s1[16*j]; }
    };
    auto store_stage = [&](int st) {
        __nv_bfloat16* base = sm2 + st*4*FM_TILE;
        int off = arow*FM_STR + aq*8;
        *reinterpret_cast<uint4*>(base + off)           = rah;
        *reinterpret_cast<uint4*>(base + FM_TILE + off) = ral;
        __nv_bfloat16* Bh = base + 2*FM_TILE;
        __nv_bfloat16* Bl = base + 3*FM_TILE;
        #pragma unroll
        for (int j = 0; j < 4; j++) {
            int px = bl + 16*(jb*4 + j);
            float f0 = rbf[j], f1 = rbf[4+j];
            __nv_bfloat16 h0 = __float2bfloat16(f0);
            __nv_bfloat16 h1 = __float2bfloat16(f1);
            __nv_bfloat16 l0 = __float2bfloat16(f0 - __bfloat162float(h0));
            __nv_bfloat16 l1 = __float2bfloat16(f1 - __bfloat162float(h1));
            *reinterpret_cast<uint32_t*>(Bh + px*FM_STR + 2*bp) = pkbf(h0, h1);
            *reinterpret_cast<uint32_t*>(Bl + px*FM_STR + 2*bp) = pkbf(l0, l1);
        }
    };

    load_chunk(0); store_stage(0);
    if (NCH > 1) load_chunk(1);
    __syncthreads();

    for (int ch = 0; ch < NCH; ch++) {
        if (ch + 1 < NCH) store_stage((ch + 1) & 1);
        if (ch + 2 < NCH) load_chunk(ch + 2);
        mma_tiles16(sm2 + (ch & 1)*4*FM_TILE, warp_m, warp_n, g, t, acc);
        __syncthreads();
    }

    #pragma unroll
    for (int mt = 0; mt < 2; mt++) {
        #pragma unroll
        for (int r2q = 0; r2q < 2; r2q++) {
            int oc = warp_m*32 + mt*16 + g + r2q*8;
            float s = bns[oc], bb = bnb[oc], bi = bias[oc];
            float* op = out + ((size_t)(b*128 + oc))*HWX + pp + warp_n*32;
            #pragma unroll
            for (int nt = 0; nt < 4; nt++) {
                float d0 = acc[mt][nt][r2q*2+0], d1 = acc[mt][nt][r2q*2+1];
                float z0, z1;
                if (ACT == 1) { z0 = s*lrelu01(d0 + bi) + bb; z1 = s*lrelu01(d1 + bi) + bb; }
                else {
                    z0 = s*(d0 + bi) + bb; z0 = z0 > 0.f ? z0 : 0.f;
                    z1 = s*(d1 + bi) + bb; z1 = z1 > 0.f ? z1 : 0.f;
                }
                *reinterpret_cast<float2*>(op + nt*8 + t*2) = make_float2(z0, z1);
            }
        }
    }
}

// =====================================================================
// f32x2 GEMM inner (kept for resa_add / TR kernel)
// =====================================================================
__device__ __forceinline__ void gemm_chunk_f2(const float* __restrict__ in_s,
                                              const float* __restrict__ w_s,
                                              int ty, int tx, U64 acc[4][8])
{
    #pragma unroll
    for (int kk = 0; kk < 16; kk++) {
        ulonglong2 wa = *reinterpret_cast<const ulonglong2*>(w_s + kk*ROWS + ty*8);
        ulonglong2 wb = *reinterpret_cast<const ulonglong2*>(w_s + kk*ROWS + ty*8 + 4);
        U64 wp[4] = {wa.x, wa.y, wb.x, wb.y};
        float4 xa = *reinterpret_cast<const float4*>(in_s + kk*ROWS + tx*4);
        float4 xb = *reinterpret_cast<const float4*>(in_s + kk*ROWS + 64 + tx*4);
        float xs[8] = {xa.x, xa.y, xa.z, xa.w, xb.x, xb.y, xb.z, xb.w};
        U64 xp[8];
        #pragma unroll
        for (int p = 0; p < 8; p++) PACK2(xp[p], xs[p]);
        #pragma unroll
        for (int j = 0; j < 4; j++)
            #pragma unroll
            for (int p = 0; p < 8; p++)
                FMA2(acc[j][p], wp[j], xp[p]);
    }
}

// =====================================================================
// MLP layer 3 (TR): f32x2, writes transposed [pix][C]
// =====================================================================
__global__ __launch_bounds__(256, 2)
void gemm128_tr_k(const float* __restrict__ in, const float* __restrict__ wg,
                  const float* __restrict__ bias, const float* __restrict__ bns,
                  const float* __restrict__ bnb, float* __restrict__ out)
{
    __shared__ __align__(16) float sraw[2*STAGE_F];
    const int gp = blockIdx.x * 128;
    const int b = gp / HWX, pp = gp - b*HWX;
    const int tid = threadIdx.x, ty = tid >> 4, tx = tid & 15;
    const int oc1 = tid >> 2, q1 = tid & 3;
    U64 acc[4][8];
    #pragma unroll
    for (int j = 0; j < 4; j++)
        #pragma unroll
        for (int p = 0; p < 8; p++) acc[j][p] = 0ULL;

    float4 ra, rb, rwa, rwb;
    auto load_chunk = [&](int kc) {
        const float* sp = &in[((b*128 + kc*16 + ty)*HWX) + pp + tx*8];
        ra = *reinterpret_cast<const float4*>(sp);
        rb = *reinterpret_cast<const float4*>(sp + 4);
        rwa = *reinterpret_cast<const float4*>(&wg[oc1*128 + kc*16 + q1*4]);
        rwb = *reinterpret_cast<const float4*>(&wg[(oc1 + 64)*128 + kc*16 + q1*4]);
    };
    auto store_stage = [&](int st) {
        float* in_s = sraw + st*STAGE_F;
        float* w_s  = in_s + 16*ROWS;
        *reinterpret_cast<float4*>(&in_s[ty*ROWS + tx*8])     = ra;
        *reinterpret_cast<float4*>(&in_s[ty*ROWS + tx*8 + 4]) = rb;
        w_s[(q1*4+0)*ROWS + oc1] = rwa.x; w_s[(q1*4+1)*ROWS + oc1] = rwa.y;
        w_s[(q1*4+2)*ROWS + oc1] = rwa.z; w_s[(q1*4+3)*ROWS + oc1] = rwa.w;
        w_s[(q1*4+0)*ROWS + oc1+64] = rwb.x; w_s[(q1*4+1)*ROWS + oc1+64] = rwb.y;
        w_s[(q1*4+2)*ROWS + oc1+64] = rwb.z; w_s[(q1*4+3)*ROWS + oc1+64] = rwb.w;
    };

    load_chunk(0); store_stage(0);
    load_chunk(1);
    __syncthreads();
    for (int kc = 0; kc < 8; kc++) {
        if (kc + 1 < 8) store_stage((kc + 1) & 1);
        if (kc + 2 < 8) load_chunk(kc + 2);
        const float* base = sraw + (kc & 1)*STAGE_F;
        gemm_chunk_f2(base, base + 16*ROWS, ty, tx, acc);
        __syncthreads();
    }

    float* stage = sraw;
    for (int gq = 0; gq < 4; gq++) {
        __syncthreads();
        if ((ty >> 2) == gq) {
            #pragma unroll
            for (int j = 0; j < 4; j++) {
                unsigned a, c;
                float lo[8], hi[8];
                #pragma unroll
                for (int p = 0; p < 8; p++) {
                    UNPK2(a, c, acc[j][p]);
                    lo[p] = __uint_as_float(a); hi[p] = __uint_as_float(c);
                }
                int oc = ty*8 + 2*j;
                int ocl = oc - gq*32;
                float bi0 = bias[oc],   s0 = bns[oc],   b0 = bnb[oc];
                float bi1 = bias[oc+1], s1 = bns[oc+1], b1 = bnb[oc+1];
                #pragma unroll
                for (int p = 0; p < 8; p++) {
                    int col = (p < 4) ? (tx*4 + p) : (64 + tx*4 + p - 4);
                    float z0 = s0*(lo[p] + bi0) + b0;
                    float z1 = s1*(hi[p] + bi1) + b1;
                    stage[ocl*129 + col]     = z0 > 0.f ? z0 : 0.f;
                    stage[(ocl+1)*129 + col] = z1 > 0.f ? z1 : 0.f;
                }
            }
        }
        __syncthreads();
        for (int t2 = tid; t2 < 1024; t2 += 256) {
            int pix = t2 >> 3, c4 = t2 & 7;
            float4 v;
            v.x = stage[(c4*4+0)*129 + pix];
            v.y = stage[(c4*4+1)*129 + pix];
            v.z = stage[(c4*4+2)*129 + pix];
            v.w = stage[(c4*4+3)*129 + pix];
            *reinterpret_cast<float4*>(&out[(size_t)(b*HWX + pp + pix)*128 + gq*32 + c4*4]) = v;
        }
    }
}

// =====================================================================
// resA shortcut add: out += lrelu(c1 @ x + c1_b), K=64 (f32x2)
// =====================================================================
__global__ __launch_bounds__(256, 2)
void resa_add_k(const float* __restrict__ x,
                const float* __restrict__ c1w, const float* __restrict__ c1b,
                float* __restrict__ out)
{
    __shared__ __align__(16) float sraw[2*STAGE_F];
    const int gp = blockIdx.x * 128;
    const int b = gp / HWX, pp = gp - b*HWX;
    const int tid = threadIdx.x, ty = tid >> 4, tx = tid & 15;
    const int oc1 = tid >> 2, q1 = tid & 3;
    U64 acc[4][8];
    #pragma unroll
    for (int j = 0; j < 4; j++)
        #pragma unroll
        for (int p = 0; p < 8; p++) acc[j][p] = 0ULL;

    float4 ra, rb, rwa, rwb;
    auto load_c = [&](int kc) {
        const float* sp = &x[((b*64 + kc*16 + ty)*HWX) + pp + tx*8];
        ra = *reinterpret_cast<const float4*>(sp);
        rb = *reinterpret_cast<const float4*>(sp + 4);
        rwa = *reinterpret_cast<const float4*>(&c1w[oc1*64 + kc*16 + q1*4]);
        rwb = *reinterpret_cast<const float4*>(&c1w[(oc1 + 64)*64 + kc*16 + q1*4]);
    };
    auto store_stage = [&](int st) {
        float* in_s = sraw + st*STAGE_F;
        float* w_s  = in_s + 16*ROWS;
        *reinterpret_cast<float4*>(&in_s[ty*ROWS + tx*8])     = ra;
        *reinterpret_cast<float4*>(&in_s[ty*ROWS + tx*8 + 4]) = rb;
        w_s[(q1*4+0)*ROWS + oc1] = rwa.x; w_s[(q1*4+1)*ROWS + oc1] = rwa.y;
        w_s[(q1*4+2)*ROWS + oc1] = rwa.z; w_s[(q1*4+3)*ROWS + oc1] = rwa.w;
        w_s[(q1*4+0)*ROWS + oc1+64] = rwb.x; w_s[(q1*4+1)*ROWS + oc1+64] = rwb.y;
        w_s[(q1*4+2)*ROWS + oc1+64] = rwb.z; w_s[(q1*4+3)*ROWS + oc1+64] = rwb.w;
    };

    load_c(0); store_stage(0);
    load_c(1);
    __syncthreads();
    for (int kc = 0; kc < 4; kc++) {
        if (kc + 1 < 4) store_stage((kc + 1) & 1);
        if (kc + 2 < 4) load_c(kc + 2);
        const float* base = sraw + (kc & 1)*STAGE_F;
        gemm_chunk_f2(base, base + 16*ROWS, ty, tx, acc);
        __syncthreads();
    }

    #pragma unroll
    for (int j = 0; j < 4; j++) {
        float lo[8], hi[8];
        #pragma unroll
        for (int p = 0; p < 8; p++) {
            unsigned a, c; UNPK2(a, c, acc[j][p]);
            lo[p] = __uint_as_float(a); hi[p] = __uint_as_float(c);
        }
        #pragma unroll
        for (int hh2 = 0; hh2 < 2; hh2++) {
            int oc = ty*8 + 2*j + hh2;
            const float* m = hh2 ? hi : lo;
            float b1 = c1b[oc];
            float* op = &out[((b*128 + oc)*HWX) + pp];
            float4 o0 = *reinterpret_cast<const float4*>(op + tx*4);
            float4 o1 = *reinterpret_cast<const float4*>(op + 64 + tx*4);
            o0.x += lrelu01(m[0] + b1); o0.y += lrelu01(m[1] + b1);
            o0.z += lrelu01(m[2] + b1); o0.w += lrelu01(m[3] + b1);
            o1.x += lrelu01(m[4] + b1); o1.y += lrelu01(m[5] + b1);
            o1.z += lrelu01(m[6] + b1); o1.w += lrelu01(m[7] + b1);
            *reinterpret_cast<float4*>(op + tx*4)      = o0;
            *reinterpret_cast<float4*>(op + 64 + tx*4) = o1;
        }
    }
}

// =====================================================================
// WeightNet
// =====================================================================
__global__ __launch_bounds__(256)
void weightnet_k(const float* __restrict__ xyz,
                 const float* __restrict__ w1w, const float* __restrict__ w1b,
                 const float* __restrict__ w2w, const float* __restrict__ w2b,
                 const float* __restrict__ w3w, const float* __restrict__ w3b,
                 const float* __restrict__ s1, const float* __restrict__ b1,
                 const float* __restrict__ s2, const float* __restrict__ b2,
                 const float* __restrict__ s3, const float* __restrict__ b3,
                 float* __restrict__ out)
{
    int g = blockIdx.x*256 + threadIdx.x;
    int pix = g & (NP2 - 1);
    int rest = g >> 14;
    int k = rest % 25, b = rest / 25;
    int h2 = pix >> 9, w2 = pix & 511;
    int hi = 2*h2 - 2 + k/5, wi = 2*w2 - 2 + (k % 5);
    bool inb = ((unsigned)hi < (unsigned)HH) && ((unsigned)wi < (unsigned)WW);
    float gv[3];
    #pragma unroll
    for (int c = 0; c < 3; c++) {
        float ctr = xyz[(b*3 + c)*HWX + (2*h2)*WW + 2*w2];
        float nb  = inb ? xyz[(b*3 + c)*HWX + hi*WW + wi] : 0.f;
        gv[c] = nb - ctr;
    }
    float a1[8];
    #pragma unroll
    for (int j = 0; j < 8; j++) {
        float z = w1b[j];
        #pragma unroll
        for (int c = 0; c < 3; c++) z += w1w[j*3 + c]*gv[c];
        z = s1[j]*z + b1[j];
        a1[j] = z > 0.f ? z : 0.f;
    }
    float a2[8];
    #pragma unroll
    for (int j = 0; j < 8; j++) {
        float z = w2b[j];
        #pragma unroll
        for (int i = 0; i < 8; i++) z += w2w[j*8 + i]*a1[i];
        z = s2[j]*z + b2[j];
        a2[j] = z > 0.f ? z : 0.f;
    }
    float o[16];
    #pragma unroll
    for (int n = 0; n < 16; n++) {
        float z = w3b[n];
        #pragma unroll
        for (int i = 0; i < 8; i++) z += w3w[n*8 + i]*a2[i];
        z = s3[n]*z + b3[n];
        o[n] = z > 0.f ? z : 0.f;
    }
    size_t base = (((size_t)(b*NP2 + pix))*25 + k)*16;
    #pragma unroll
    for (int q = 0; q < 4; q++)
        *reinterpret_cast<float4*>(&out[base + q*4]) =
            make_float4(o[q*4], o[q*4+1], o[q*4+2], o[q*4+3]);
}

// =====================================================================
// Einsum -> writes y directly as bf16 hi/lo (pixel-major [px][2048])
// =====================================================================
__global__ __launch_bounds__(128)
void einsum_k(const float* __restrict__ hT, const float* __restrict__ wn,
              __nv_bfloat16* __restrict__ yh, __nv_bfloat16* __restrict__ yl)
{
    __shared__ __align__(16) float u_s[2][25][128];
    __shared__ float wn_s[2][400];
    const int gpix = blockIdx.x*2;
    const int b = gpix / NP2;
    const int tid = threadIdx.x;

    for (int i = tid; i < 800; i += 128) {
        int pl = i / 400, r = i - pl*400;
        wn_s[pl][r] = wn[(size_t)(gpix + pl)*400 + r];
    }
    for (int idx = 0; idx < 50; idx++) {
        int pl = idx / 25, k = idx - pl*25;
        int pp = (gpix + pl) - b*NP2;
        int h2 = pp >> 9, w2 = pp & 511;
        int hi = 2*h2 - 2 + k/5, wi = 2*w2 - 2 + (k % 5);
        float v = 0.f;
        if ((unsigned)hi < (unsigned)HH && (unsigned)wi < (unsigned)WW)
            v = hT[((size_t)(b*HH + hi)*WW + wi)*128 + tid];
        u_s[pl][k][tid] = v;
    }
    __syncthreads();

    const int s = tid & 63, pl = tid >> 6;
    const int cg = s & 15, ng = s >> 4;
    float acc[8][4];
    #pragma unroll
    for (int i = 0; i < 8; i++)
        #pragma unroll
        for (int n = 0; n < 4; n++) acc[i][n] = 0.f;

    #pragma unroll
    for (int k = 0; k < 25; k++) {
        float4 ua = *reinterpret_cast<const float4*>(&u_s[pl][k][cg*4]);
        float4 ub = *reinterpret_cast<const float4*>(&u_s[pl][k][64 + cg*4]);
        float u[8] = {ua.x, ua.y, ua.z, ua.w, ub.x, ub.y, ub.z, ub.w};
        float4 wv = *reinterpret_cast<const float4*>(&wn_s[pl][k*16 + ng*4]);
        float wvv[4] = {wv.x, wv.y, wv.z, wv.w};
        #pragma unroll
        for (int i = 0; i < 8; i++)
            #pragma unroll
            for (int n = 0; n < 4; n++) acc[i][n] += u[i]*wvv[n];
    }
    size_t base = (size_t)(gpix + pl)*2048;
    #pragma unroll
    for (int i = 0; i < 8; i++) {
        int c = (i < 4) ? (cg*4 + i) : (64 + cg*4 + i - 4);
        __nv_bfloat16 h[4], l[4];
        #pragma unroll
        for (int n = 0; n < 4; n++) {
            h[n] = __float2bfloat16(acc[i][n]);
            l[n] = __float2bfloat16(acc[i][n] - __bfloat162float(h[n]));
        }
        *reinterpret_cast<uint2*>(&yh[base + c*16 + ng*4]) = make_uint2(pkbf(h[0],h[1]), pkbf(h[2],h[3]));
        *reinterpret_cast<uint2*>(&yl[base + c*16 + ng*4]) = make_uint2(pkbf(l[0],l[1]), pkbf(l[2],l[3]));
    }
}

// =====================================================================
// Final GEMM (mma.sync bf16x3) with pure-copy fills, 512 threads
// =====================================================================
__global__ __launch_bounds__(512)
void final_mma_k(const __nv_bfloat16* __restrict__ yh, const __nv_bfloat16* __restrict__ yl,
                 const __nv_bfloat16* __restrict__ lwh, const __nv_bfloat16* __restrict__ lwl,
                 const float* __restrict__ lbias, const float* __restrict__ bns,
                 const float* __restrict__ bnb, float* __restrict__ out)
{
    extern __shared__ __align__(16) __nv_bfloat16 sm2[];
    const int gp = blockIdx.x * 128;
    const int b  = gp / NP2, pp = gp - b*NP2;
    const int tid = threadIdx.x;
    const int wid = tid >> 5, lane = tid & 31;
    const int g = lane >> 2, t = lane & 3;
    const int warp_m = wid & 3, warp_n = wid >> 2;
    const int row = tid >> 2, q = tid & 3;

    float acc[2][4][4];
    #pragma unroll
    for (int mt = 0; mt < 2; mt++)
        #pragma unroll
        for (int nt = 0; nt < 4; nt++)
            #pragma unroll
            for (int qq = 0; qq < 4; qq++) acc[mt][nt][qq] = 0.f;

    uint4 rah, ral, rbh, rbl;
    auto load_chunk = [&](int ch) {
        int kc = ch*32;
        size_t aoff = (size_t)row*2048 + kc + q*8;
        size_t boff = (size_t)(gp + row)*2048 + kc + q*8;
        rah = *reinterpret_cast<const uint4*>(lwh + aoff);
        ral = *reinterpret_cast<const uint4*>(lwl + aoff);
        rbh = *reinterpret_cast<const uint4*>(yh + boff);
        rbl = *reinterpret_cast<const uint4*>(yl + boff);
    };
    auto store_stage = [&](int st) {
        __nv_bfloat16* base = sm2 + st*4*FM_TILE;
        int off = row*FM_STR + q*8;
        *reinterpret_cast<uint4*>(base + off)             = rah;
        *reinterpret_cast<uint4*>(base + FM_TILE + off)   = ral;
        *reinterpret_cast<uint4*>(base + 2*FM_TILE + off) = rbh;
        *reinterpret_cast<uint4*>(base + 3*FM_TILE + off) = rbl;
    };

    load_chunk(0); store_stage(0);
    load_chunk(1);
    __syncthreads();

    for (int ch = 0; ch < 64; ch++) {
        if (ch + 1 < 64) store_stage((ch + 1) & 1);
        if (ch + 2 < 64) load_chunk(ch + 2);
        mma_tiles16(sm2 + (ch & 1)*4*FM_TILE, warp_m, warp_n, g, t, acc);
        __syncthreads();
    }

    #pragma unroll
    for (int mt = 0; mt < 2; mt++) {
        #pragma unroll
        for (int r2 = 0; r2 < 2; r2++) {
            int oc = warp_m*32 + mt*16 + g + r2*8;
            float s = bns[oc], bb = bnb[oc], bi = lbias[oc];
            float* op = out + ((size_t)(b*128 + oc))*NP2 + pp + warp_n*32;
            #pragma unroll
            for (int nt = 0; nt < 4; nt++) {
                float z0 = s*(acc[mt][nt][r2*2+0] + bi) + bb;
                float z1 = s*(acc[mt][nt][r2*2+1] + bi) + bb;
                float2 v;
                v.x = z0 > 0.f ? z0 : 0.f;
                v.y = z1 > 0.f ? z1 : 0.f;
                *reinterpret_cast<float2*>(op + nt*8 + t*2) = v;
            }
        }
    }
}

// =====================================================================
// host launcher
// =====================================================================
extern "C" void kernel_launch(void* const* d_in, const int* in_sizes, int n_in,
                              void* d_out, int out_size)
{
    const float* x      = (const float*)d_in[0];
    const float* xyz    = (const float*)d_in[1];
    const float* c1_w   = (const float*)d_in[2];
    const float* c1_b   = (const float*)d_in[3];
    const float* c2_w   = (const float*)d_in[4];
    const float* c2_b   = (const float*)d_in[5];
    const float* c3_w   = (const float*)d_in[6];
    const float* c3_b   = (const float*)d_in[7];
    const float* c4_w   = (const float*)d_in[8];
    const float* c4_b   = (const float*)d_in[9];
    const float* c5_w   = (const float*)d_in[10];
    const float* c5_b   = (const float*)d_in[11];
    const float* rbn_s  = (const float*)d_in[12];
    const float* rbn_b  = (const float*)d_in[13];
    const float* p_w    = (const float*)d_in[14];
    const float* p_b    = (const float*)d_in[15];
    const float* pbn_s  = (const float*)d_in[16];
    const float* pbn_b  = (const float*)d_in[17];
    const float* lin_w  = (const float*)d_in[18];
    const float* lin_b  = (const float*)d_in[19];
    const float* w1_w   = (const float*)d_in[20];
    const float* w1_b   = (const float*)d_in[21];
    const float* w2_w   = (const float*)d_in[22];
    const float* w2_b   = (const float*)d_in[23];
    const float* w3_w   = (const float*)d_in[24];
    const float* w3_b   = (const float*)d_in[25];
    const float* wbn1_s = (const float*)d_in[26];
    const float* wbn1_b = (const float*)d_in[27];
    const float* wbn2_s = (const float*)d_in[28];
    const float* wbn2_b = (const float*)d_in[29];
    const float* wbn3_s = (const float*)d_in[30];
    const float* wbn3_b = (const float*)d_in[31];

    float* outp = (float*)d_out;
    float* resB = outp;                 // [B,128,H2,W2]
    float* resA = outp + RESB_ELEMS;    // [B,128,H,W]

    float *A1, *A2, *A3, *B1, *B2, *HT, *WN;
    __nv_bfloat16 *YH, *YL, *WHp, *WLp;
    cudaGetSymbolAddress((void**)&A1, g_resA1);
    cudaGetSymbolAddress((void**)&A2, g_resA2);
    cudaGetSymbolAddress((void**)&A3, g_resA3);
    cudaGetSymbolAddress((void**)&B1, g_buf1);
    cudaGetSymbolAddress((void**)&B2, g_buf2);
    cudaGetSymbolAddress((void**)&HT, g_hT);
    cudaGetSymbolAddress((void**)&WN, g_wn);
    cudaGetSymbolAddress((void**)&YH, g_yh);
    cudaGetSymbolAddress((void**)&YL, g_yl);
    cudaGetSymbolAddress((void**)&WHp, g_wh);
    cudaGetSymbolAddress((void**)&WLp, g_wl);

    cudaFuncSetAttribute(final_mma_k, cudaFuncAttributeMaxDynamicSharedMemorySize, FM_SMEM);
    cudaFuncSetAttribute(mma_nchw_k<384,3,1>, cudaFuncAttributeMaxDynamicSharedMemorySize, FM_SMEM);
    cudaFuncSetAttribute(mma_nchw_k<128,1,0>, cudaFuncAttributeMaxDynamicSharedMemorySize, FM_SMEM);
    cudaFuncSetAttribute(mma_conv_k<64,3,1,1>, cudaFuncAttributeMaxDynamicSharedMemorySize, FM_SMEM);
    cudaFuncSetAttribute(mma_conv_k<128,3,2,2>, cudaFuncAttributeMaxDynamicSharedMemorySize, FM_SMEM);
    cudaFuncSetAttribute(mma_conv_k<128,2,2,1>, cudaFuncAttributeMaxDynamicSharedMemorySize, FM_SMEM);

    // weight precompute (bf16 hi/lo)
    prep_w_k<<<(WTOTAL + 255)/256, 256>>>(lin_w, c5_w, p_w, c2_w, c3_w, c4_w, WHp, WLp);

    dim3 cgrid(WW/128, HH, BB);   // (8, 64, 2)
    // ResBlock trunk on HMMA (implicit im2col)
    mma_conv_k<64,3,1,1><<<cgrid, 512, FM_SMEM>>>(x,  WHp + WOFF_C2, WLp + WOFF_C2,
        c2_b, rbn_s,       rbn_b,       A1);
    mma_conv_k<128,3,2,2><<<cgrid, 512, FM_SMEM>>>(A1, WHp + WOFF_C3, WLp + WOFF_C3,
        c3_b, rbn_s + 128, rbn_b + 128, A2);
    mma_conv_k<128,2,2,1><<<cgrid, 512, FM_SMEM>>>(A2, WHp + WOFF_C4, WLp + WOFF_C4,
        c4_b, rbn_s + 256, rbn_b + 256, A3);
    // resA main via mma (K=384, lrelu+bn)
    mma_nchw_k<384,3,1><<<BB*HWX/128, 512, FM_SMEM>>>(A1, A2, A3,
        WHp + WOFF_C5, WLp + WOFF_C5, c5_b, rbn_s + 384, rbn_b + 384, resA);
    resa_add_k<<<BB*HWX/128, 256>>>(x, c1_w, c1_b, resA);
    // MLP layers 1,2 via mma (K=128, relu(bn))
    mma_nchw_k<128,1,0><<<BB*HWX/128, 512, FM_SMEM>>>(resA, resA, resA,
        WHp + WOFF_P, WLp + WOFF_P, p_b, pbn_s, pbn_b, B1);
    mma_nchw_k<128,1,0><<<BB*HWX/128, 512, FM_SMEM>>>(B1, B1, B1,
        WHp + WOFF_P + 16384, WLp + WOFF_P + 16384, p_b + 128, pbn_s + 128, pbn_b + 128, B2);
    // MLP layer 3: f32, transposed output for unfold gather
    gemm128_tr_k<<<BB*HWX/128, 256>>>(B2, p_w + 32768, p_b + 256, pbn_s + 256, pbn_b + 256, HT);
    // WeightNet
    weightnet_k<<<(BB*25*NP2)/256, 256>>>(xyz, w1_w, w1_b, w2_w, w2_b, w3_w, w3_b,
                                          wbn1_s, wbn1_b, wbn2_s, wbn2_b, wbn3_s, wbn3_b, WN);
    // einsum -> y (bf16 hi/lo, pixel-major)
    einsum_k<<<BB*NP2/2, 128>>>(HT, WN, YH, YL);
    // final GEMM (copy-fill mma)
    final_mma_k<<<BB*NP2/128, 512, FM_SMEM>>>(YH, YL, WHp, WLp,
                                              lin_b, pbn_s + 384, pbn_b + 384, resB);
}